// round 1
// baseline (speedup 1.0000x reference)
#include <cuda_runtime.h>
#include <math.h>

// Problem dims (fixed by reference)
#define B_   32
#define S_   512
#define H_   256
#define NH   8
#define HD   32
#define M_   (B_ * S_)     // 16384 rows
#define TOT  (M_ * H_)     // 4,194,304 elements

#define QK_SCALE   0.17677669529663689f   // 1/sqrt(32)
#define RSQRT2     0.70710678118654752f
#define LN_EPS     1e-5f

// ---------------- scratch (device globals; no allocation allowed) ----------------
__device__ float g_normed[TOT];
__device__ float g_Q[TOT];     // [b, h, s, d], pre-transformed (q*q+1e-6)*scale
__device__ float g_K[TOT];     // [b, h, s, d], pre-shifted by log(radial_mask)
__device__ float g_V[TOT];     // [b, h, s, d]
__device__ float g_attn[TOT];  // [b, s, h*32+d]  (row-major [M, H] for out-proj)
__device__ float g_lr[M_];     // log(radial_mask) per (b,s) row

// ---------------- LayerNorm: one warp per row ----------------
__global__ __launch_bounds__(256) void ln_kernel(
    const float* __restrict__ x, const float* __restrict__ gamma,
    const float* __restrict__ beta, const float* __restrict__ rmask)
{
    int warp = threadIdx.x >> 5;
    int lane = threadIdx.x & 31;
    int row  = blockIdx.x * 8 + warp;
    const float* xr = x + row * H_;

    float v[8];
    float sum = 0.f, sq = 0.f;
#pragma unroll
    for (int k = 0; k < 8; k++) {
        float t = xr[lane + 32 * k];
        v[k] = t; sum += t; sq += t * t;
    }
#pragma unroll
    for (int o = 16; o > 0; o >>= 1) {
        sum += __shfl_xor_sync(0xffffffffu, sum, o);
        sq  += __shfl_xor_sync(0xffffffffu, sq,  o);
    }
    float mu   = sum * (1.f / H_);
    float var  = sq * (1.f / H_) - mu * mu;
    float rstd = rsqrtf(var + LN_EPS);

    float* nr = g_normed + row * H_;
#pragma unroll
    for (int k = 0; k < 8; k++) {
        int idx = lane + 32 * k;
        nr[idx] = (v[k] - mu) * rstd * gamma[idx] + beta[idx];
    }
    if (lane == 0) g_lr[row] = logf(rmask[row]);
}

// ---------------- Tiled SGEMM (NT): C[m,n] = sum_k A[m,k] * Bmat[n,k] ----------------
// MODE 1: A = g_normed, epilogue scatters q/k/v (with transforms) to g_Q/g_K/g_V
// MODE 2: A = g_attn,   epilogue adds residual (extra = inputs), * 1/sqrt(2) -> C
#define BM 128
#define BN 128
#define BK 8
#define TM 8
#define TN 8

template <int MODE>
__global__ __launch_bounds__(256, 2) void sgemm_nt(
    const float* __restrict__ Bmat, const float* __restrict__ extra,
    float* __restrict__ C)
{
    const int K = 256;
    __shared__ float As[BK][BM];
    __shared__ float Bs[BK][BN];

    const float* A = (MODE == 1) ? g_normed : g_attn;

    int tid  = threadIdx.x;
    int brow = blockIdx.y, bcol = blockIdx.x;
    int trow = tid >> 4;        // 0..15
    int tcol = tid & 15;        // 0..15
    int lrow = tid >> 1;        // 0..127
    int lcol = (tid & 1) * 4;   // 0 or 4

    const float* Ag = A    + (brow * BM + lrow) * K + lcol;
    const float* Bg = Bmat + (bcol * BN + lrow) * K + lcol;

    float acc[TM][TN];
#pragma unroll
    for (int i = 0; i < TM; i++)
#pragma unroll
        for (int j = 0; j < TN; j++) acc[i][j] = 0.f;

    for (int k0 = 0; k0 < K; k0 += BK) {
        float4 a4 = *(const float4*)(Ag + k0);
        float4 b4 = *(const float4*)(Bg + k0);
        As[lcol + 0][lrow] = a4.x; As[lcol + 1][lrow] = a4.y;
        As[lcol + 2][lrow] = a4.z; As[lcol + 3][lrow] = a4.w;
        Bs[lcol + 0][lrow] = b4.x; Bs[lcol + 1][lrow] = b4.y;
        Bs[lcol + 2][lrow] = b4.z; Bs[lcol + 3][lrow] = b4.w;
        __syncthreads();
#pragma unroll
        for (int kk = 0; kk < BK; kk++) {
            float4 a0 = *(const float4*)(&As[kk][trow * TM]);
            float4 a1 = *(const float4*)(&As[kk][trow * TM + 4]);
            float4 b0 = *(const float4*)(&Bs[kk][tcol * TN]);
            float4 b1 = *(const float4*)(&Bs[kk][tcol * TN + 4]);
            float ar[8] = {a0.x, a0.y, a0.z, a0.w, a1.x, a1.y, a1.z, a1.w};
            float br[8] = {b0.x, b0.y, b0.z, b0.w, b1.x, b1.y, b1.z, b1.w};
#pragma unroll
            for (int i = 0; i < TM; i++)
#pragma unroll
                for (int j = 0; j < TN; j++)
                    acc[i][j] = fmaf(ar[i], br[j], acc[i][j]);
        }
        __syncthreads();
    }

    int n_base = bcol * BN + tcol * TN;
    if (MODE == 1) {
        int region = n_base >> 8;     // 0=q, 1=k, 2=v (tile never crosses regions)
        int nn     = n_base & 255;
        int h      = nn >> 5;
        int dbase  = nn & 31;
        float* dst = (region == 0) ? g_Q : (region == 1) ? g_K : g_V;
#pragma unroll
        for (int i = 0; i < TM; i++) {
            int m = brow * BM + trow * TM + i;
            int b = m >> 9, s = m & 511;
            float add = (region == 1) ? g_lr[m] : 0.f;
            float* o = dst + (((b << 3) + h) * S_ + s) * HD + dbase;
#pragma unroll
            for (int j = 0; j < TN; j++) {
                float v_ = acc[i][j];
                if (region == 0) v_ = (v_ * v_ + 1e-6f) * QK_SCALE;
                else             v_ += add;
                o[j] = v_;
            }
        }
    } else {
#pragma unroll
        for (int i = 0; i < TM; i++) {
            int m = brow * BM + trow * TM + i;
            const float* inr = extra + m * H_ + n_base;
            float*       o   = C     + m * H_ + n_base;
#pragma unroll
            for (int j = 0; j < TN; j++)
                o[j] = (acc[i][j] + inr[j]) * RSQRT2;
        }
    }
}

// ---------------- Attention: one CTA per (b,h); full K,V in smem ----------------
__global__ __launch_bounds__(256, 1) void attn_kernel()
{
    extern __shared__ float sm[];
    float* Ks = sm;              // 512*32 floats
    float* Vs = sm + S_ * HD;    // 512*32 floats

    int bh  = blockIdx.x;
    int tid = threadIdx.x;
    int b = bh >> 3, h = bh & 7;

    const float4* Kg = (const float4*)(g_K + bh * S_ * HD);
    const float4* Vg = (const float4*)(g_V + bh * S_ * HD);
    float4* Ks4 = (float4*)Ks;
    float4* Vs4 = (float4*)Vs;
    for (int i = tid; i < S_ * HD / 4; i += 256) {
        Ks4[i] = Kg[i];
        Vs4[i] = Vg[i];
    }
    __syncthreads();

    for (int r = tid; r < S_; r += 256) {
        float4 q[8];
        const float4* qg = (const float4*)(g_Q + (bh * S_ + r) * HD);
#pragma unroll
        for (int i = 0; i < 8; i++) q[i] = qg[i];   // already scaled & transformed

        float mi = -1e30f, l = 0.f;
        float oacc[HD];
#pragma unroll
        for (int d = 0; d < HD; d++) oacc[d] = 0.f;

        for (int jt = 0; jt < S_; jt += 16) {
            float s[16];
#pragma unroll
            for (int jj = 0; jj < 16; jj++) {
                const float4* kr = (const float4*)(Ks + (jt + jj) * HD);
                float a0 = 0.f, a1 = 0.f, a2 = 0.f, a3 = 0.f;
#pragma unroll
                for (int d4 = 0; d4 < 8; d4++) {
                    float4 kv = kr[d4];
                    float4 qv = q[d4];
                    a0 = fmaf(qv.x, kv.x, a0);
                    a1 = fmaf(qv.y, kv.y, a1);
                    a2 = fmaf(qv.z, kv.z, a2);
                    a3 = fmaf(qv.w, kv.w, a3);
                }
                s[jj] = (a0 + a1) + (a2 + a3);
            }
            float mt = s[0];
#pragma unroll
            for (int jj = 1; jj < 16; jj++) mt = fmaxf(mt, s[jj]);
            float mn   = fmaxf(mi, mt);
            float corr = __expf(mi - mn);
            l *= corr;
#pragma unroll
            for (int d = 0; d < HD; d++) oacc[d] *= corr;
#pragma unroll
            for (int jj = 0; jj < 16; jj++) {
                float p = __expf(s[jj] - mn);
                l += p;
                const float4* vr = (const float4*)(Vs + (jt + jj) * HD);
#pragma unroll
                for (int d4 = 0; d4 < 8; d4++) {
                    float4 vv = vr[d4];
                    oacc[d4 * 4 + 0] = fmaf(p, vv.x, oacc[d4 * 4 + 0]);
                    oacc[d4 * 4 + 1] = fmaf(p, vv.y, oacc[d4 * 4 + 1]);
                    oacc[d4 * 4 + 2] = fmaf(p, vv.z, oacc[d4 * 4 + 2]);
                    oacc[d4 * 4 + 3] = fmaf(p, vv.w, oacc[d4 * 4 + 3]);
                }
            }
            mi = mn;
        }

        float inv = 1.f / l;
        float* o = g_attn + (b * S_ + r) * H_ + h * HD;
#pragma unroll
        for (int d = 0; d < HD; d += 4) {
            float4 ov = make_float4(oacc[d] * inv, oacc[d + 1] * inv,
                                    oacc[d + 2] * inv, oacc[d + 3] * inv);
            *(float4*)(o + d) = ov;
        }
    }
}

// ---------------- launch ----------------
extern "C" void kernel_launch(void* const* d_in, const int* in_sizes, int n_in,
                              void* d_out, int out_size)
{
    const float* inputs = (const float*)d_in[0];
    const float* rmask  = (const float*)d_in[1];
    const float* w_in   = (const float*)d_in[2];   // [768, 256]
    const float* w_out  = (const float*)d_in[3];   // [256, 256]
    const float* gamma  = (const float*)d_in[4];
    const float* beta   = (const float*)d_in[5];
    float* out = (float*)d_out;

    // 1) LayerNorm + log(radial_mask)
    ln_kernel<<<M_ / 8, 256>>>(inputs, gamma, beta, rmask);

    // 2) QKV projection with fused q/k transforms and [b,h,s,d] scatter
    sgemm_nt<1><<<dim3(768 / BN, M_ / BM), 256>>>(w_in, nullptr, nullptr);

    // 3) Attention (128 KB dynamic smem for full K,V per head)
    cudaFuncSetAttribute(attn_kernel,
                         cudaFuncAttributeMaxDynamicSharedMemorySize,
                         2 * S_ * HD * (int)sizeof(float));
    attn_kernel<<<B_ * NH, 256, 2 * S_ * HD * sizeof(float)>>>();

    // 4) Output projection + residual + 1/sqrt(2)
    sgemm_nt<2><<<dim3(H_ / BN, M_ / BM), 256>>>(w_out, inputs, out);
}

// round 2
// speedup vs baseline: 3.3704x; 3.3704x over previous
#include <cuda_runtime.h>
#include <math.h>

// Problem dims (fixed)
#define B_   32
#define S_   512
#define H_   256
#define NH   8
#define HD   32
#define M_   (B_ * S_)     // 16384
#define TOT  (M_ * H_)

#define QK_SCALE   0.17677669529663689f   // 1/sqrt(32)
#define RSQRT2     0.70710678118654752f
#define LN_EPS     1e-5f

// ---------------- scratch ----------------
__device__ float g_normed[TOT];
__device__ float g_Q[TOT];     // [b,h,s,d], (q*q+1e-6)*scale
__device__ float g_K[TOT];     // [b,h,s,d], + log(radial_mask)
__device__ float g_V[TOT];     // [b,h,s,d]
__device__ float g_attn[TOT];  // [b,s,H]
__device__ float g_lr[M_];

// ---------------- helpers ----------------
__device__ __forceinline__ unsigned f2tf(float f) {
    unsigned u;
    asm("cvt.rna.tf32.f32 %0, %1;" : "=r"(u) : "f"(f));
    return u;
}

__device__ __forceinline__ void mma_tf32(float* d, const unsigned* a, const unsigned* b) {
    asm("mma.sync.aligned.m16n8k8.row.col.f32.tf32.tf32.f32 "
        "{%0,%1,%2,%3},{%4,%5,%6,%7},{%8,%9},{%0,%1,%2,%3};"
        : "+f"(d[0]), "+f"(d[1]), "+f"(d[2]), "+f"(d[3])
        : "r"(a[0]), "r"(a[1]), "r"(a[2]), "r"(a[3]), "r"(b[0]), "r"(b[1]));
}

__device__ __forceinline__ unsigned su(float f) { return __float_as_uint(f); }
__device__ __forceinline__ float uf(unsigned u) { return __uint_as_float(u); }

// ---------------- LayerNorm ----------------
__global__ __launch_bounds__(256) void ln_kernel(
    const float* __restrict__ x, const float* __restrict__ gamma,
    const float* __restrict__ beta, const float* __restrict__ rmask)
{
    int warp = threadIdx.x >> 5, lane = threadIdx.x & 31;
    int row  = blockIdx.x * 8 + warp;
    const float* xr = x + row * H_;

    float v[8], sum = 0.f, sq = 0.f;
#pragma unroll
    for (int k = 0; k < 8; k++) {
        float t = xr[lane + 32 * k];
        v[k] = t; sum += t; sq += t * t;
    }
#pragma unroll
    for (int o = 16; o > 0; o >>= 1) {
        sum += __shfl_xor_sync(0xffffffffu, sum, o);
        sq  += __shfl_xor_sync(0xffffffffu, sq,  o);
    }
    float mu = sum * (1.f / H_);
    float var = sq * (1.f / H_) - mu * mu;
    float rstd = rsqrtf(var + LN_EPS);

    float* nr = g_normed + row * H_;
#pragma unroll
    for (int k = 0; k < 8; k++) {
        int idx = lane + 32 * k;
        nr[idx] = (v[k] - mu) * rstd * gamma[idx] + beta[idx];
    }
    if (lane == 0) g_lr[row] = logf(rmask[row]);
}

// ---------------- tf32 MMA GEMM (NT): C[m,n] = sum_k A[m,k]*Bmat[n,k] ----------------
// 128x128x32 CTA tile, 8 warps of 64x32. K fixed at 256.
// MODE 1: A=g_normed, scatter q/k/v with transforms.  MODE 2: A=g_attn, residual epilogue.
#define SSTR 36

template <int MODE>
__global__ __launch_bounds__(256) void gemm_mma(
    const float* __restrict__ Bmat, const float* __restrict__ extra,
    float* __restrict__ C)
{
    __shared__ float As[128 * SSTR];
    __shared__ float Bs[128 * SSTR];

    const float* A = (MODE == 1) ? g_normed : g_attn;
    const int K = 256;

    int tid = threadIdx.x;
    int wid = tid >> 5, lane = tid & 31;
    int g = lane >> 2, t = lane & 3;
    int wm = wid >> 2, wn = wid & 3;        // 2 x 4 warps
    int brow = blockIdx.y, bcol = blockIdx.x;

    int arow0 = tid >> 3;                    // + 32*i
    int acol  = (tid & 7) << 2;

    const float* Ag = A    + (size_t)(brow * 128 + arow0) * K + acol;
    const float* Bg = Bmat + (size_t)(bcol * 128 + arow0) * K + acol;

    float dacc[4][4][4];
#pragma unroll
    for (int i = 0; i < 4; i++)
#pragma unroll
        for (int j = 0; j < 4; j++)
#pragma unroll
            for (int c = 0; c < 4; c++) dacc[i][j][c] = 0.f;

    float4 pa[4], pb[4];
#pragma unroll
    for (int i = 0; i < 4; i++) {
        pa[i] = *(const float4*)(Ag + (size_t)(32 * i) * K);
        pb[i] = *(const float4*)(Bg + (size_t)(32 * i) * K);
    }
    // store tile 0
#pragma unroll
    for (int i = 0; i < 4; i++) {
        int r = arow0 + 32 * i;
        *(float4*)&As[r * SSTR + acol] = make_float4(
            uf(f2tf(pa[i].x)), uf(f2tf(pa[i].y)), uf(f2tf(pa[i].z)), uf(f2tf(pa[i].w)));
        *(float4*)&Bs[r * SSTR + acol] = make_float4(
            uf(f2tf(pb[i].x)), uf(f2tf(pb[i].y)), uf(f2tf(pb[i].z)), uf(f2tf(pb[i].w)));
    }
    __syncthreads();

    for (int k0 = 0; k0 < K; k0 += 32) {
        if (k0 + 32 < K) {
#pragma unroll
            for (int i = 0; i < 4; i++) {
                pa[i] = *(const float4*)(Ag + (size_t)(32 * i) * K + k0 + 32);
                pb[i] = *(const float4*)(Bg + (size_t)(32 * i) * K + k0 + 32);
            }
        }
#pragma unroll
        for (int ks = 0; ks < 4; ks++) {
            unsigned af[4][4], bf[4][2];
#pragma unroll
            for (int mi = 0; mi < 4; mi++) {
                int r = wm * 64 + mi * 16 + g;
                af[mi][0] = su(As[r * SSTR + ks * 8 + t]);
                af[mi][1] = su(As[(r + 8) * SSTR + ks * 8 + t]);
                af[mi][2] = su(As[r * SSTR + ks * 8 + t + 4]);
                af[mi][3] = su(As[(r + 8) * SSTR + ks * 8 + t + 4]);
            }
#pragma unroll
            for (int ni = 0; ni < 4; ni++) {
                int n = wn * 32 + ni * 8 + g;
                bf[ni][0] = su(Bs[n * SSTR + ks * 8 + t]);
                bf[ni][1] = su(Bs[n * SSTR + ks * 8 + t + 4]);
            }
#pragma unroll
            for (int mi = 0; mi < 4; mi++)
#pragma unroll
                for (int ni = 0; ni < 4; ni++)
                    mma_tf32(dacc[mi][ni], af[mi], bf[ni]);
        }
        __syncthreads();
        if (k0 + 32 < K) {
#pragma unroll
            for (int i = 0; i < 4; i++) {
                int r = arow0 + 32 * i;
                *(float4*)&As[r * SSTR + acol] = make_float4(
                    uf(f2tf(pa[i].x)), uf(f2tf(pa[i].y)), uf(f2tf(pa[i].z)), uf(f2tf(pa[i].w)));
                *(float4*)&Bs[r * SSTR + acol] = make_float4(
                    uf(f2tf(pb[i].x)), uf(f2tf(pb[i].y)), uf(f2tf(pb[i].z)), uf(f2tf(pb[i].w)));
            }
            __syncthreads();
        }
    }

    // epilogue
    if (MODE == 1) {
        int region = (bcol * 128) >> 8;     // 0=q 1=k 2=v (uniform per CTA)
        int hh = ((bcol * 128 + wn * 32) & 255) >> 5;
        float* dst = (region == 0) ? g_Q : (region == 1) ? g_K : g_V;
#pragma unroll
        for (int mi = 0; mi < 4; mi++) {
            int r0 = brow * 128 + wm * 64 + mi * 16 + g;
            int r1 = r0 + 8;
            float lr0 = (region == 1) ? g_lr[r0] : 0.f;
            float lr1 = (region == 1) ? g_lr[r1] : 0.f;
            float* p0 = dst + (((size_t)((r0 >> 9) * 8 + hh) * S_ + (r0 & 511)) * HD);
            float* p1 = dst + (((size_t)((r1 >> 9) * 8 + hh) * S_ + (r1 & 511)) * HD);
#pragma unroll
            for (int ni = 0; ni < 4; ni++) {
                int dcol = ni * 8 + 2 * t;
                float v0 = dacc[mi][ni][0], v1 = dacc[mi][ni][1];
                float v2 = dacc[mi][ni][2], v3 = dacc[mi][ni][3];
                if (region == 0) {
                    v0 = (v0 * v0 + 1e-6f) * QK_SCALE;
                    v1 = (v1 * v1 + 1e-6f) * QK_SCALE;
                    v2 = (v2 * v2 + 1e-6f) * QK_SCALE;
                    v3 = (v3 * v3 + 1e-6f) * QK_SCALE;
                } else if (region == 1) {
                    v0 += lr0; v1 += lr0; v2 += lr1; v3 += lr1;
                }
                *(float2*)(p0 + dcol) = make_float2(v0, v1);
                *(float2*)(p1 + dcol) = make_float2(v2, v3);
            }
        }
    } else {
#pragma unroll
        for (int mi = 0; mi < 4; mi++) {
            int r0 = brow * 128 + wm * 64 + mi * 16 + g;
            int r1 = r0 + 8;
            int cbase = bcol * 128 + wn * 32;
            const float* in0 = extra + (size_t)r0 * H_ + cbase;
            const float* in1 = extra + (size_t)r1 * H_ + cbase;
            float* o0 = C + (size_t)r0 * H_ + cbase;
            float* o1 = C + (size_t)r1 * H_ + cbase;
#pragma unroll
            for (int ni = 0; ni < 4; ni++) {
                int dcol = ni * 8 + 2 * t;
                float2 i0 = *(const float2*)(in0 + dcol);
                float2 i1 = *(const float2*)(in1 + dcol);
                *(float2*)(o0 + dcol) = make_float2(
                    (dacc[mi][ni][0] + i0.x) * RSQRT2, (dacc[mi][ni][1] + i0.y) * RSQRT2);
                *(float2*)(o1 + dcol) = make_float2(
                    (dacc[mi][ni][2] + i1.x) * RSQRT2, (dacc[mi][ni][3] + i1.y) * RSQRT2);
            }
        }
    }
}

// ---------------- attention: tf32 mma flash-style ----------------
// grid = 512: blockIdx.x = (bh<<1)|qhalf. 8 warps x 32 q-rows = 256 q rows/CTA.
// K tiles [32 s][d] and V^T tiles [d][32 s] double-buffered in smem.
__global__ __launch_bounds__(256) void attn_mma_kernel()
{
    __shared__ float Ks[2][32 * SSTR];
    __shared__ float Vt[2][32 * SSTR];

    int tid = threadIdx.x;
    int wid = tid >> 5, lane = tid & 31;
    int g = lane >> 2, t = lane & 3;
    int qhalf = blockIdx.x & 1, bh = blockIdx.x >> 1;
    int b = bh >> 3, h = bh & 7;
    int qbase = qhalf * 256 + wid * 32;

    // Q fragments (resident): [mi][kstep][4]
    const float* Qg = g_Q + ((size_t)bh * S_ + qbase) * HD;
    unsigned qf[2][4][4];
#pragma unroll
    for (int mi = 0; mi < 2; mi++) {
        int r = mi * 16 + g;
#pragma unroll
        for (int ks = 0; ks < 4; ks++) {
            qf[mi][ks][0] = f2tf(Qg[r * HD + ks * 8 + t]);
            qf[mi][ks][1] = f2tf(Qg[(r + 8) * HD + ks * 8 + t]);
            qf[mi][ks][2] = f2tf(Qg[r * HD + ks * 8 + t + 4]);
            qf[mi][ks][3] = f2tf(Qg[(r + 8) * HD + ks * 8 + t + 4]);
        }
    }

    float oacc[2][4][4];
#pragma unroll
    for (int mi = 0; mi < 2; mi++)
#pragma unroll
        for (int nd = 0; nd < 4; nd++)
#pragma unroll
            for (int c = 0; c < 4; c++) oacc[mi][nd][c] = 0.f;
    float mrow[4] = {-1e30f, -1e30f, -1e30f, -1e30f};
    float lrow[4] = {0.f, 0.f, 0.f, 0.f};

    // tile loaders: 256 threads, each 1 float4 of K and V
    int sl = tid >> 3;            // 0..31 seq-in-tile
    int d4 = (tid & 7) << 2;      // 0..28
    const float* Kg = g_K + (size_t)bh * S_ * HD;
    const float* Vg = g_V + (size_t)bh * S_ * HD;

    float4 pk = *(const float4*)(Kg + (size_t)sl * HD + d4);
    float4 pv = *(const float4*)(Vg + (size_t)sl * HD + d4);
    // store tile 0
    *(float4*)&Ks[0][sl * SSTR + d4] = make_float4(
        uf(f2tf(pk.x)), uf(f2tf(pk.y)), uf(f2tf(pk.z)), uf(f2tf(pk.w)));
    Vt[0][(d4 + 0) * SSTR + sl] = uf(f2tf(pv.x));
    Vt[0][(d4 + 1) * SSTR + sl] = uf(f2tf(pv.y));
    Vt[0][(d4 + 2) * SSTR + sl] = uf(f2tf(pv.z));
    Vt[0][(d4 + 3) * SSTR + sl] = uf(f2tf(pv.w));
    __syncthreads();

    for (int kt = 0; kt < 16; kt++) {
        int buf = kt & 1;
        if (kt + 1 < 16) {
            pk = *(const float4*)(Kg + (size_t)((kt + 1) * 32 + sl) * HD + d4);
            pv = *(const float4*)(Vg + (size_t)((kt + 1) * 32 + sl) * HD + d4);
            int nb = buf ^ 1;
            *(float4*)&Ks[nb][sl * SSTR + d4] = make_float4(
                uf(f2tf(pk.x)), uf(f2tf(pk.y)), uf(f2tf(pk.z)), uf(f2tf(pk.w)));
            Vt[nb][(d4 + 0) * SSTR + sl] = uf(f2tf(pv.x));
            Vt[nb][(d4 + 1) * SSTR + sl] = uf(f2tf(pv.y));
            Vt[nb][(d4 + 2) * SSTR + sl] = uf(f2tf(pv.z));
            Vt[nb][(d4 + 3) * SSTR + sl] = uf(f2tf(pv.w));
        }

        // ---- QK^T: S[32 q][32 k] ----
        float sacc[2][4][4];
#pragma unroll
        for (int mi = 0; mi < 2; mi++)
#pragma unroll
            for (int ni = 0; ni < 4; ni++)
#pragma unroll
                for (int c = 0; c < 4; c++) sacc[mi][ni][c] = 0.f;

#pragma unroll
        for (int ks = 0; ks < 4; ks++) {
            unsigned kb[4][2];
#pragma unroll
            for (int ni = 0; ni < 4; ni++) {
                kb[ni][0] = su(Ks[buf][(ni * 8 + g) * SSTR + ks * 8 + t]);
                kb[ni][1] = su(Ks[buf][(ni * 8 + g) * SSTR + ks * 8 + t + 4]);
            }
#pragma unroll
            for (int mi = 0; mi < 2; mi++)
#pragma unroll
                for (int ni = 0; ni < 4; ni++)
                    mma_tf32(sacc[mi][ni], qf[mi][ks], kb[ni]);
        }

        // ---- online softmax (per row-slot) ----
#pragma unroll
        for (int r = 0; r < 4; r++) {
            int mi = r >> 1, cb = (r & 1) * 2;
            float tm = -1e30f;
#pragma unroll
            for (int ni = 0; ni < 4; ni++) {
                tm = fmaxf(tm, sacc[mi][ni][cb]);
                tm = fmaxf(tm, sacc[mi][ni][cb + 1]);
            }
            tm = fmaxf(tm, __shfl_xor_sync(0xffffffffu, tm, 1));
            tm = fmaxf(tm, __shfl_xor_sync(0xffffffffu, tm, 2));
            float mn = fmaxf(mrow[r], tm);
            float corr = __expf(mrow[r] - mn);
            float l = lrow[r] * corr;
#pragma unroll
            for (int ni = 0; ni < 4; ni++) {
                float p0 = __expf(sacc[mi][ni][cb] - mn);
                float p1 = __expf(sacc[mi][ni][cb + 1] - mn);
                l += p0 + p1;
                sacc[mi][ni][cb] = p0;
                sacc[mi][ni][cb + 1] = p1;
            }
#pragma unroll
            for (int nd = 0; nd < 4; nd++) {
                oacc[mi][nd][cb] *= corr;
                oacc[mi][nd][cb + 1] *= corr;
            }
            mrow[r] = mn;
            lrow[r] = l;
        }

        // ---- PV: out += P @ V ----
#pragma unroll
        for (int ks = 0; ks < 4; ks++) {
            unsigned vb[4][2];
#pragma unroll
            for (int nd = 0; nd < 4; nd++) {
                vb[nd][0] = su(Vt[buf][(nd * 8 + g) * SSTR + ks * 8 + t]);
                vb[nd][1] = su(Vt[buf][(nd * 8 + g) * SSTR + ks * 8 + t + 4]);
            }
            int src0 = (lane & ~3) | (t >> 1);
            int src1 = src0 + 2;
#pragma unroll
            for (int mi = 0; mi < 2; mi++) {
                unsigned c0 = f2tf(sacc[mi][ks][0]);
                unsigned c1 = f2tf(sacc[mi][ks][1]);
                unsigned c2 = f2tf(sacc[mi][ks][2]);
                unsigned c3 = f2tf(sacc[mi][ks][3]);
                unsigned pa_[4];
                unsigned x, y;
                x = __shfl_sync(0xffffffffu, c0, src0);
                y = __shfl_sync(0xffffffffu, c1, src0);
                pa_[0] = (t & 1) ? y : x;
                x = __shfl_sync(0xffffffffu, c2, src0);
                y = __shfl_sync(0xffffffffu, c3, src0);
                pa_[1] = (t & 1) ? y : x;
                x = __shfl_sync(0xffffffffu, c0, src1);
                y = __shfl_sync(0xffffffffu, c1, src1);
                pa_[2] = (t & 1) ? y : x;
                x = __shfl_sync(0xffffffffu, c2, src1);
                y = __shfl_sync(0xffffffffu, c3, src1);
                pa_[3] = (t & 1) ? y : x;
#pragma unroll
                for (int nd = 0; nd < 4; nd++)
                    mma_tf32(oacc[mi][nd], pa_, vb[nd]);
            }
        }
        __syncthreads();
    }

    // finalize + write [b,s,H]
#pragma unroll
    for (int r = 0; r < 4; r++) {
        int mi = r >> 1, cb = (r & 1) * 2;
        float lt = lrow[r];
        lt += __shfl_xor_sync(0xffffffffu, lt, 1);
        lt += __shfl_xor_sync(0xffffffffu, lt, 2);
        float inv = 1.f / lt;
        int row = qbase + (r >> 1) * 16 + (r & 1) * 8 + g;
        float* op = g_attn + ((size_t)b * S_ + row) * H_ + h * HD;
#pragma unroll
        for (int nd = 0; nd < 4; nd++) {
            *(float2*)(op + nd * 8 + 2 * t) = make_float2(
                oacc[mi][nd][cb] * inv, oacc[mi][nd][cb + 1] * inv);
        }
    }
}

// ---------------- launch ----------------
extern "C" void kernel_launch(void* const* d_in, const int* in_sizes, int n_in,
                              void* d_out, int out_size)
{
    const float* inputs = (const float*)d_in[0];
    const float* rmask  = (const float*)d_in[1];
    const float* w_in   = (const float*)d_in[2];   // [768,256]
    const float* w_out  = (const float*)d_in[3];   // [256,256]
    const float* gamma  = (const float*)d_in[4];
    const float* beta   = (const float*)d_in[5];
    float* out = (float*)d_out;

    ln_kernel<<<M_ / 8, 256>>>(inputs, gamma, beta, rmask);
    gemm_mma<1><<<dim3(6, M_ / 128), 256>>>(w_in, nullptr, nullptr);
    attn_mma_kernel<<<512, 256>>>();
    gemm_mma<2><<<dim3(2, M_ / 128), 256>>>(w_out, inputs, out);
}

// round 3
// speedup vs baseline: 3.5827x; 1.0630x over previous
#include <cuda_runtime.h>
#include <math.h>

// Problem dims (fixed)
#define B_   32
#define S_   512
#define H_   256
#define NH   8
#define HD   32
#define M_   (B_ * S_)     // 16384
#define TOT  (M_ * H_)

#define QK_SCALE   0.17677669529663689f   // 1/sqrt(32)
#define RSQRT2     0.70710678118654752f
#define LN_EPS     1e-5f

// ---------------- scratch ----------------
__device__ float g_normed[TOT];
__device__ float g_Q[TOT];     // [b,h,s,d], (q*q+1e-6)*scale
__device__ float g_K[TOT];     // [b,h,s,d], + log(radial_mask)
__device__ float g_V[TOT];     // [b,h,s,d]
__device__ float g_attn[TOT];  // [b,s,H]
__device__ float g_lr[M_];

// ---------------- helpers ----------------
__device__ __forceinline__ void mma_tf32(float* d, const unsigned* a, const unsigned* b) {
    asm("mma.sync.aligned.m16n8k8.row.col.f32.tf32.tf32.f32 "
        "{%0,%1,%2,%3},{%4,%5,%6,%7},{%8,%9},{%0,%1,%2,%3};"
        : "+f"(d[0]), "+f"(d[1]), "+f"(d[2]), "+f"(d[3])
        : "r"(a[0]), "r"(a[1]), "r"(a[2]), "r"(a[3]), "r"(b[0]), "r"(b[1]));
}
__device__ __forceinline__ unsigned su(float f) { return __float_as_uint(f); }

__device__ __forceinline__ void cp16(float* smem_ptr, const float* gptr) {
    unsigned s = (unsigned)__cvta_generic_to_shared(smem_ptr);
    asm volatile("cp.async.cg.shared.global [%0], [%1], 16;" :: "r"(s), "l"(gptr));
}
#define CP_COMMIT() asm volatile("cp.async.commit_group;")
#define CP_WAIT1()  asm volatile("cp.async.wait_group 1;")

// ---------------- LayerNorm ----------------
__global__ __launch_bounds__(256) void ln_kernel(
    const float* __restrict__ x, const float* __restrict__ gamma,
    const float* __restrict__ beta, const float* __restrict__ rmask)
{
    int warp = threadIdx.x >> 5, lane = threadIdx.x & 31;
    int row  = blockIdx.x * 8 + warp;
    const float* xr = x + row * H_;

    float v[8], sum = 0.f, sq = 0.f;
#pragma unroll
    for (int k = 0; k < 8; k++) {
        float t = xr[lane + 32 * k];
        v[k] = t; sum += t; sq += t * t;
    }
#pragma unroll
    for (int o = 16; o > 0; o >>= 1) {
        sum += __shfl_xor_sync(0xffffffffu, sum, o);
        sq  += __shfl_xor_sync(0xffffffffu, sq,  o);
    }
    float mu = sum * (1.f / H_);
    float var = sq * (1.f / H_) - mu * mu;
    float rstd = rsqrtf(var + LN_EPS);

    float* nr = g_normed + row * H_;
#pragma unroll
    for (int k = 0; k < 8; k++) {
        int idx = lane + 32 * k;
        nr[idx] = (v[k] - mu) * rstd * gamma[idx] + beta[idx];
    }
    if (lane == 0) g_lr[row] = logf(rmask[row]);
}

// ---------------- tf32 MMA GEMM (NT), cp.async 3-stage ----------------
// C[m,n] = sum_k A[m,k]*Bmat[n,k]; 128x128x32 CTA tile, 8 warps of 64x32, K=256.
#define SSTR 36
#define TILE_F (128 * SSTR)

template <int MODE>
__global__ __launch_bounds__(256) void gemm_mma(
    const float* __restrict__ Bmat, const float* __restrict__ extra,
    float* __restrict__ C)
{
    extern __shared__ float smg[];
    float* As = smg;                 // [3][128*SSTR]
    float* Bs = smg + 3 * TILE_F;    // [3][128*SSTR]

    const float* A = (MODE == 1) ? g_normed : g_attn;
    const int K = 256;

    int tid = threadIdx.x;
    int wid = tid >> 5, lane = tid & 31;
    int g = lane >> 2, t = lane & 3;
    int wm = wid >> 2, wn = wid & 3;
    int brow = blockIdx.y, bcol = blockIdx.x;

    int arow0 = tid >> 3;
    int acol  = (tid & 7) << 2;

    const float* Ag = A    + (size_t)(brow * 128 + arow0) * K + acol;
    const float* Bg = Bmat + (size_t)(bcol * 128 + arow0) * K + acol;

    float dacc[4][4][4];
#pragma unroll
    for (int i = 0; i < 4; i++)
#pragma unroll
        for (int j = 0; j < 4; j++)
#pragma unroll
            for (int c = 0; c < 4; c++) dacc[i][j][c] = 0.f;

    // prologue: tiles 0,1
#pragma unroll
    for (int p = 0; p < 2; p++) {
        float* as = As + p * TILE_F;
        float* bs = Bs + p * TILE_F;
#pragma unroll
        for (int i = 0; i < 4; i++) {
            cp16(&as[(arow0 + 32 * i) * SSTR + acol], Ag + (size_t)(32 * i) * K + p * 32);
            cp16(&bs[(arow0 + 32 * i) * SSTR + acol], Bg + (size_t)(32 * i) * K + p * 32);
        }
        CP_COMMIT();
    }

    for (int kt = 0; kt < 8; kt++) {
        int buf = kt % 3;
        CP_WAIT1();
        __syncthreads();
        if (kt + 2 < 8) {
            int nb = (kt + 2) % 3;
            float* as = As + nb * TILE_F;
            float* bs = Bs + nb * TILE_F;
#pragma unroll
            for (int i = 0; i < 4; i++) {
                cp16(&as[(arow0 + 32 * i) * SSTR + acol], Ag + (size_t)(32 * i) * K + (kt + 2) * 32);
                cp16(&bs[(arow0 + 32 * i) * SSTR + acol], Bg + (size_t)(32 * i) * K + (kt + 2) * 32);
            }
        }
        CP_COMMIT();

        const float* as = As + buf * TILE_F;
        const float* bs = Bs + buf * TILE_F;
#pragma unroll
        for (int ks = 0; ks < 4; ks++) {
            unsigned af[4][4], bf[4][2];
#pragma unroll
            for (int mi = 0; mi < 4; mi++) {
                int r = wm * 64 + mi * 16 + g;
                af[mi][0] = su(as[r * SSTR + ks * 8 + t]);
                af[mi][1] = su(as[(r + 8) * SSTR + ks * 8 + t]);
                af[mi][2] = su(as[r * SSTR + ks * 8 + t + 4]);
                af[mi][3] = su(as[(r + 8) * SSTR + ks * 8 + t + 4]);
            }
#pragma unroll
            for (int ni = 0; ni < 4; ni++) {
                int n = wn * 32 + ni * 8 + g;
                bf[ni][0] = su(bs[n * SSTR + ks * 8 + t]);
                bf[ni][1] = su(bs[n * SSTR + ks * 8 + t + 4]);
            }
#pragma unroll
            for (int mi = 0; mi < 4; mi++)
#pragma unroll
                for (int ni = 0; ni < 4; ni++)
                    mma_tf32(dacc[mi][ni], af[mi], bf[ni]);
        }
    }

    // epilogue
    if (MODE == 1) {
        int region = (bcol * 128) >> 8;     // 0=q 1=k 2=v
        int hh = ((bcol * 128 + wn * 32) & 255) >> 5;
        float* dst = (region == 0) ? g_Q : (region == 1) ? g_K : g_V;
#pragma unroll
        for (int mi = 0; mi < 4; mi++) {
            int r0 = brow * 128 + wm * 64 + mi * 16 + g;
            int r1 = r0 + 8;
            float lr0 = (region == 1) ? g_lr[r0] : 0.f;
            float lr1 = (region == 1) ? g_lr[r1] : 0.f;
            float* p0 = dst + (((size_t)((r0 >> 9) * 8 + hh) * S_ + (r0 & 511)) * HD);
            float* p1 = dst + (((size_t)((r1 >> 9) * 8 + hh) * S_ + (r1 & 511)) * HD);
#pragma unroll
            for (int ni = 0; ni < 4; ni++) {
                int dcol = ni * 8 + 2 * t;
                float v0 = dacc[mi][ni][0], v1 = dacc[mi][ni][1];
                float v2 = dacc[mi][ni][2], v3 = dacc[mi][ni][3];
                if (region == 0) {
                    v0 = (v0 * v0 + 1e-6f) * QK_SCALE;
                    v1 = (v1 * v1 + 1e-6f) * QK_SCALE;
                    v2 = (v2 * v2 + 1e-6f) * QK_SCALE;
                    v3 = (v3 * v3 + 1e-6f) * QK_SCALE;
                } else if (region == 1) {
                    v0 += lr0; v1 += lr0; v2 += lr1; v3 += lr1;
                }
                *(float2*)(p0 + dcol) = make_float2(v0, v1);
                *(float2*)(p1 + dcol) = make_float2(v2, v3);
            }
        }
    } else {
#pragma unroll
        for (int mi = 0; mi < 4; mi++) {
            int r0 = brow * 128 + wm * 64 + mi * 16 + g;
            int r1 = r0 + 8;
            int cbase = bcol * 128 + wn * 32;
            const float* in0 = extra + (size_t)r0 * H_ + cbase;
            const float* in1 = extra + (size_t)r1 * H_ + cbase;
            float* o0 = C + (size_t)r0 * H_ + cbase;
            float* o1 = C + (size_t)r1 * H_ + cbase;
#pragma unroll
            for (int ni = 0; ni < 4; ni++) {
                int dcol = ni * 8 + 2 * t;
                float2 i0 = *(const float2*)(in0 + dcol);
                float2 i1 = *(const float2*)(in1 + dcol);
                *(float2*)(o0 + dcol) = make_float2(
                    (dacc[mi][ni][0] + i0.x) * RSQRT2, (dacc[mi][ni][1] + i0.y) * RSQRT2);
                *(float2*)(o1 + dcol) = make_float2(
                    (dacc[mi][ni][2] + i1.x) * RSQRT2, (dacc[mi][ni][3] + i1.y) * RSQRT2);
            }
        }
    }
}

// ---------------- attention: tf32 mma flash-style, cp.async 3-stage ----------------
// grid = 512: blockIdx.x = (bh<<1)|qhalf. 8 warps x 32 q-rows.
// K tiles [32 s][d] pad 36; V tiles [32 s][d] pad 40 (read directly as PV B-frags).
#define KSTR 36
#define VSTR 40

__global__ __launch_bounds__(256) void attn_mma_kernel()
{
    __shared__ float Ks[3][32 * KSTR];
    __shared__ float Vs[3][32 * VSTR];

    int tid = threadIdx.x;
    int wid = tid >> 5, lane = tid & 31;
    int g = lane >> 2, t = lane & 3;
    int qhalf = blockIdx.x & 1, bh = blockIdx.x >> 1;
    int b = bh >> 3, h = bh & 7;
    int qbase = qhalf * 256 + wid * 32;

    // Q fragments resident (raw fp32 bits; HW truncates to tf32)
    const float* Qg = g_Q + ((size_t)bh * S_ + qbase) * HD;
    unsigned qf[2][4][4];
#pragma unroll
    for (int mi = 0; mi < 2; mi++) {
        int r = mi * 16 + g;
#pragma unroll
        for (int ks = 0; ks < 4; ks++) {
            qf[mi][ks][0] = su(Qg[r * HD + ks * 8 + t]);
            qf[mi][ks][1] = su(Qg[(r + 8) * HD + ks * 8 + t]);
            qf[mi][ks][2] = su(Qg[r * HD + ks * 8 + t + 4]);
            qf[mi][ks][3] = su(Qg[(r + 8) * HD + ks * 8 + t + 4]);
        }
    }

    float oacc[2][4][4];
#pragma unroll
    for (int mi = 0; mi < 2; mi++)
#pragma unroll
        for (int nd = 0; nd < 4; nd++)
#pragma unroll
            for (int c = 0; c < 4; c++) oacc[mi][nd][c] = 0.f;
    float mrow[4] = {-1e30f, -1e30f, -1e30f, -1e30f};
    float lrow[4] = {0.f, 0.f, 0.f, 0.f};

    int sl = tid >> 3;            // 0..31
    int d4 = (tid & 7) << 2;      // 0..28
    const float* Kg = g_K + (size_t)bh * S_ * HD;
    const float* Vg = g_V + (size_t)bh * S_ * HD;

    // prologue: tiles 0,1
#pragma unroll
    for (int p = 0; p < 2; p++) {
        cp16(&Ks[p][sl * KSTR + d4], Kg + (size_t)(p * 32 + sl) * HD + d4);
        cp16(&Vs[p][sl * VSTR + d4], Vg + (size_t)(p * 32 + sl) * HD + d4);
        CP_COMMIT();
    }

    for (int kt = 0; kt < 16; kt++) {
        int buf = kt % 3;
        CP_WAIT1();
        __syncthreads();
        if (kt + 2 < 16) {
            int nb = (kt + 2) % 3;
            cp16(&Ks[nb][sl * KSTR + d4], Kg + (size_t)((kt + 2) * 32 + sl) * HD + d4);
            cp16(&Vs[nb][sl * VSTR + d4], Vg + (size_t)((kt + 2) * 32 + sl) * HD + d4);
        }
        CP_COMMIT();

        // ---- QK^T ----
        float sacc[2][4][4];
#pragma unroll
        for (int mi = 0; mi < 2; mi++)
#pragma unroll
            for (int ni = 0; ni < 4; ni++)
#pragma unroll
                for (int c = 0; c < 4; c++) sacc[mi][ni][c] = 0.f;

#pragma unroll
        for (int ks = 0; ks < 4; ks++) {
            unsigned kb[4][2];
#pragma unroll
            for (int ni = 0; ni < 4; ni++) {
                kb[ni][0] = su(Ks[buf][(ni * 8 + g) * KSTR + ks * 8 + t]);
                kb[ni][1] = su(Ks[buf][(ni * 8 + g) * KSTR + ks * 8 + t + 4]);
            }
#pragma unroll
            for (int mi = 0; mi < 2; mi++)
#pragma unroll
                for (int ni = 0; ni < 4; ni++)
                    mma_tf32(sacc[mi][ni], qf[mi][ks], kb[ni]);
        }

        // ---- online softmax ----
#pragma unroll
        for (int r = 0; r < 4; r++) {
            int mi = r >> 1, cb = (r & 1) * 2;
            float tm = -1e30f;
#pragma unroll
            for (int ni = 0; ni < 4; ni++) {
                tm = fmaxf(tm, sacc[mi][ni][cb]);
                tm = fmaxf(tm, sacc[mi][ni][cb + 1]);
            }
            tm = fmaxf(tm, __shfl_xor_sync(0xffffffffu, tm, 1));
            tm = fmaxf(tm, __shfl_xor_sync(0xffffffffu, tm, 2));
            float mn = fmaxf(mrow[r], tm);
            float corr = __expf(mrow[r] - mn);
            float l = lrow[r] * corr;
#pragma unroll
            for (int ni = 0; ni < 4; ni++) {
                float p0 = __expf(sacc[mi][ni][cb] - mn);
                float p1 = __expf(sacc[mi][ni][cb + 1] - mn);
                l += p0 + p1;
                sacc[mi][ni][cb] = p0;
                sacc[mi][ni][cb + 1] = p1;
            }
#pragma unroll
            for (int nd = 0; nd < 4; nd++) {
                oacc[mi][nd][cb] *= corr;
                oacc[mi][nd][cb + 1] *= corr;
            }
            mrow[r] = mn;
            lrow[r] = l;
        }

        // ---- PV: out += P @ V ----
#pragma unroll
        for (int ks = 0; ks < 4; ks++) {
            unsigned vb[4][2];
#pragma unroll
            for (int nd = 0; nd < 4; nd++) {
                vb[nd][0] = su(Vs[buf][(ks * 8 + t) * VSTR + nd * 8 + g]);
                vb[nd][1] = su(Vs[buf][(ks * 8 + t + 4) * VSTR + nd * 8 + g]);
            }
            int src0 = (lane & ~3) | (t >> 1);
            int src1 = src0 + 2;
#pragma unroll
            for (int mi = 0; mi < 2; mi++) {
                unsigned c0 = su(sacc[mi][ks][0]);
                unsigned c1 = su(sacc[mi][ks][1]);
                unsigned c2 = su(sacc[mi][ks][2]);
                unsigned c3 = su(sacc[mi][ks][3]);
                unsigned pa_[4];
                unsigned x, y;
                x = __shfl_sync(0xffffffffu, c0, src0);
                y = __shfl_sync(0xffffffffu, c1, src0);
                pa_[0] = (t & 1) ? y : x;
                x = __shfl_sync(0xffffffffu, c2, src0);
                y = __shfl_sync(0xffffffffu, c3, src0);
                pa_[1] = (t & 1) ? y : x;
                x = __shfl_sync(0xffffffffu, c0, src1);
                y = __shfl_sync(0xffffffffu, c1, src1);
                pa_[2] = (t & 1) ? y : x;
                x = __shfl_sync(0xffffffffu, c2, src1);
                y = __shfl_sync(0xffffffffu, c3, src1);
                pa_[3] = (t & 1) ? y : x;
#pragma unroll
                for (int nd = 0; nd < 4; nd++)
                    mma_tf32(oacc[mi][nd], pa_, vb[nd]);
            }
        }
    }

    // finalize + write [b,s,H]
#pragma unroll
    for (int r = 0; r < 4; r++) {
        int mi = r >> 1, cb = (r & 1) * 2;
        float lt = lrow[r];
        lt += __shfl_xor_sync(0xffffffffu, lt, 1);
        lt += __shfl_xor_sync(0xffffffffu, lt, 2);
        float inv = 1.f / lt;
        int row = qbase + (r >> 1) * 16 + (r & 1) * 8 + g;
        float* op = g_attn + ((size_t)b * S_ + row) * H_ + h * HD;
#pragma unroll
        for (int nd = 0; nd < 4; nd++) {
            *(float2*)(op + nd * 8 + 2 * t) = make_float2(
                oacc[mi][nd][cb] * inv, oacc[mi][nd][cb + 1] * inv);
        }
    }
}

// ---------------- launch ----------------
extern "C" void kernel_launch(void* const* d_in, const int* in_sizes, int n_in,
                              void* d_out, int out_size)
{
    const float* inputs = (const float*)d_in[0];
    const float* rmask  = (const float*)d_in[1];
    const float* w_in   = (const float*)d_in[2];   // [768,256]
    const float* w_out  = (const float*)d_in[3];   // [256,256]
    const float* gamma  = (const float*)d_in[4];
    const float* beta   = (const float*)d_in[5];
    float* out = (float*)d_out;

    const int gemm_smem = 6 * TILE_F * (int)sizeof(float);   // 110592 B
    cudaFuncSetAttribute(gemm_mma<1>, cudaFuncAttributeMaxDynamicSharedMemorySize, gemm_smem);
    cudaFuncSetAttribute(gemm_mma<2>, cudaFuncAttributeMaxDynamicSharedMemorySize, gemm_smem);

    ln_kernel<<<M_ / 8, 256>>>(inputs, gamma, beta, rmask);
    gemm_mma<1><<<dim3(6, M_ / 128), 256, gemm_smem>>>(w_in, nullptr, nullptr);
    attn_mma_kernel<<<512, 256>>>();
    gemm_mma<2><<<dim3(2, M_ / 128), 256, gemm_smem>>>(w_out, inputs, out);
}

// round 4
// speedup vs baseline: 3.6061x; 1.0065x over previous
#include <cuda_runtime.h>
#include <math.h>

// Problem dims (fixed)
#define B_   32
#define S_   512
#define H_   256
#define NH   8
#define HD   32
#define M_   (B_ * S_)     // 16384
#define TOT  (M_ * H_)

#define QK_SCALE   0.17677669529663689f   // 1/sqrt(32)
#define RSQRT2     0.70710678118654752f
#define LN_EPS     1e-5f

// ---------------- scratch ----------------
__device__ float g_normed[TOT];
__device__ float g_Q[TOT];     // [b,h,s,d], (q*q+1e-6)*scale
__device__ float g_K[TOT];     // [b,h,s,d], + log(radial_mask)
__device__ float g_V[TOT];     // [b,h,s,d]
__device__ float g_attn[TOT];  // [b,s,H]
__device__ float g_lr[M_];

// ---------------- helpers ----------------
__device__ __forceinline__ void mma_tf32(float* d, const unsigned* a, const unsigned* b) {
    asm("mma.sync.aligned.m16n8k8.row.col.f32.tf32.tf32.f32 "
        "{%0,%1,%2,%3},{%4,%5,%6,%7},{%8,%9},{%0,%1,%2,%3};"
        : "+f"(d[0]), "+f"(d[1]), "+f"(d[2]), "+f"(d[3])
        : "r"(a[0]), "r"(a[1]), "r"(a[2]), "r"(a[3]), "r"(b[0]), "r"(b[1]));
}
__device__ __forceinline__ unsigned su(float f) { return __float_as_uint(f); }

__device__ __forceinline__ void cp16(float* smem_ptr, const float* gptr) {
    unsigned s = (unsigned)__cvta_generic_to_shared(smem_ptr);
    asm volatile("cp.async.cg.shared.global [%0], [%1], 16;" :: "r"(s), "l"(gptr));
}
#define CP_COMMIT() asm volatile("cp.async.commit_group;")
#define CP_WAIT1()  asm volatile("cp.async.wait_group 1;")

// ---------------- LayerNorm ----------------
__global__ __launch_bounds__(256) void ln_kernel(
    const float* __restrict__ x, const float* __restrict__ gamma,
    const float* __restrict__ beta, const float* __restrict__ rmask)
{
    int warp = threadIdx.x >> 5, lane = threadIdx.x & 31;
    int row  = blockIdx.x * 8 + warp;
    const float* xr = x + row * H_;

    float v[8], sum = 0.f, sq = 0.f;
#pragma unroll
    for (int k = 0; k < 8; k++) {
        float t = xr[lane + 32 * k];
        v[k] = t; sum += t; sq += t * t;
    }
#pragma unroll
    for (int o = 16; o > 0; o >>= 1) {
        sum += __shfl_xor_sync(0xffffffffu, sum, o);
        sq  += __shfl_xor_sync(0xffffffffu, sq,  o);
    }
    float mu = sum * (1.f / H_);
    float var = sq * (1.f / H_) - mu * mu;
    float rstd = rsqrtf(var + LN_EPS);

    float* nr = g_normed + row * H_;
#pragma unroll
    for (int k = 0; k < 8; k++) {
        int idx = lane + 32 * k;
        nr[idx] = (v[k] - mu) * rstd * gamma[idx] + beta[idx];
    }
    if (lane == 0) g_lr[row] = logf(rmask[row]);
}

// ---------------- tf32 MMA GEMM (NT), cp.async 2-stage, 2 CTAs/SM ----------------
// C[m,n] = sum_k A[m,k]*Bmat[n,k]; 128x128x32 CTA tile, 8 warps of 64x32, K=256.
#define SSTR 36
#define TILE_F (128 * SSTR)

template <int MODE>
__global__ __launch_bounds__(256, 2) void gemm_mma(
    const float* __restrict__ Bmat, const float* __restrict__ extra,
    float* __restrict__ C)
{
    extern __shared__ float smg[];
    float* As = smg;                 // [2][128*SSTR]
    float* Bs = smg + 2 * TILE_F;    // [2][128*SSTR]

    const float* A = (MODE == 1) ? g_normed : g_attn;
    const int K = 256;

    int tid = threadIdx.x;
    int wid = tid >> 5, lane = tid & 31;
    int g = lane >> 2, t = lane & 3;
    int wm = wid >> 2, wn = wid & 3;
    int brow = blockIdx.y, bcol = blockIdx.x;

    int arow0 = tid >> 3;
    int acol  = (tid & 7) << 2;

    const float* Ag = A    + (size_t)(brow * 128 + arow0) * K + acol;
    const float* Bg = Bmat + (size_t)(bcol * 128 + arow0) * K + acol;

    float dacc[4][4][4];
#pragma unroll
    for (int i = 0; i < 4; i++)
#pragma unroll
        for (int j = 0; j < 4; j++)
#pragma unroll
            for (int c = 0; c < 4; c++) dacc[i][j][c] = 0.f;

    // prologue: tiles 0,1
#pragma unroll
    for (int p = 0; p < 2; p++) {
        float* as = As + p * TILE_F;
        float* bs = Bs + p * TILE_F;
#pragma unroll
        for (int i = 0; i < 4; i++) {
            cp16(&as[(arow0 + 32 * i) * SSTR + acol], Ag + (size_t)(32 * i) * K + p * 32);
            cp16(&bs[(arow0 + 32 * i) * SSTR + acol], Bg + (size_t)(32 * i) * K + p * 32);
        }
        CP_COMMIT();
    }

    for (int kt = 0; kt < 8; kt++) {
        int buf = kt & 1;
        CP_WAIT1();
        __syncthreads();

        const float* as = As + buf * TILE_F;
        const float* bs = Bs + buf * TILE_F;
#pragma unroll
        for (int ks = 0; ks < 4; ks++) {
            unsigned af[4][4], bf[4][2];
#pragma unroll
            for (int mi = 0; mi < 4; mi++) {
                int r = wm * 64 + mi * 16 + g;
                af[mi][0] = su(as[r * SSTR + ks * 8 + t]);
                af[mi][1] = su(as[(r + 8) * SSTR + ks * 8 + t]);
                af[mi][2] = su(as[r * SSTR + ks * 8 + t + 4]);
                af[mi][3] = su(as[(r + 8) * SSTR + ks * 8 + t + 4]);
            }
#pragma unroll
            for (int ni = 0; ni < 4; ni++) {
                int n = wn * 32 + ni * 8 + g;
                bf[ni][0] = su(bs[n * SSTR + ks * 8 + t]);
                bf[ni][1] = su(bs[n * SSTR + ks * 8 + t + 4]);
            }
#pragma unroll
            for (int mi = 0; mi < 4; mi++)
#pragma unroll
                for (int ni = 0; ni < 4; ni++)
                    mma_tf32(dacc[mi][ni], af[mi], bf[ni]);
        }
        __syncthreads();

        if (kt + 2 < 8) {
            float* asw = As + buf * TILE_F;
            float* bsw = Bs + buf * TILE_F;
#pragma unroll
            for (int i = 0; i < 4; i++) {
                cp16(&asw[(arow0 + 32 * i) * SSTR + acol], Ag + (size_t)(32 * i) * K + (kt + 2) * 32);
                cp16(&bsw[(arow0 + 32 * i) * SSTR + acol], Bg + (size_t)(32 * i) * K + (kt + 2) * 32);
            }
        }
        CP_COMMIT();
    }

    // epilogue
    if (MODE == 1) {
        int region = (bcol * 128) >> 8;     // 0=q 1=k 2=v
        int hh = ((bcol * 128 + wn * 32) & 255) >> 5;
        float* dst = (region == 0) ? g_Q : (region == 1) ? g_K : g_V;
#pragma unroll
        for (int mi = 0; mi < 4; mi++) {
            int r0 = brow * 128 + wm * 64 + mi * 16 + g;
            int r1 = r0 + 8;
            float lr0 = (region == 1) ? g_lr[r0] : 0.f;
            float lr1 = (region == 1) ? g_lr[r1] : 0.f;
            float* p0 = dst + (((size_t)((r0 >> 9) * 8 + hh) * S_ + (r0 & 511)) * HD);
            float* p1 = dst + (((size_t)((r1 >> 9) * 8 + hh) * S_ + (r1 & 511)) * HD);
#pragma unroll
            for (int ni = 0; ni < 4; ni++) {
                int dcol = ni * 8 + 2 * t;
                float v0 = dacc[mi][ni][0], v1 = dacc[mi][ni][1];
                float v2 = dacc[mi][ni][2], v3 = dacc[mi][ni][3];
                if (region == 0) {
                    v0 = (v0 * v0 + 1e-6f) * QK_SCALE;
                    v1 = (v1 * v1 + 1e-6f) * QK_SCALE;
                    v2 = (v2 * v2 + 1e-6f) * QK_SCALE;
                    v3 = (v3 * v3 + 1e-6f) * QK_SCALE;
                } else if (region == 1) {
                    v0 += lr0; v1 += lr0; v2 += lr1; v3 += lr1;
                }
                *(float2*)(p0 + dcol) = make_float2(v0, v1);
                *(float2*)(p1 + dcol) = make_float2(v2, v3);
            }
        }
    } else {
#pragma unroll
        for (int mi = 0; mi < 4; mi++) {
            int r0 = brow * 128 + wm * 64 + mi * 16 + g;
            int r1 = r0 + 8;
            int cbase = bcol * 128 + wn * 32;
            const float* in0 = extra + (size_t)r0 * H_ + cbase;
            const float* in1 = extra + (size_t)r1 * H_ + cbase;
            float* o0 = C + (size_t)r0 * H_ + cbase;
            float* o1 = C + (size_t)r1 * H_ + cbase;
#pragma unroll
            for (int ni = 0; ni < 4; ni++) {
                int dcol = ni * 8 + 2 * t;
                float2 i0 = *(const float2*)(in0 + dcol);
                float2 i1 = *(const float2*)(in1 + dcol);
                *(float2*)(o0 + dcol) = make_float2(
                    (dacc[mi][ni][0] + i0.x) * RSQRT2, (dacc[mi][ni][1] + i0.y) * RSQRT2);
                *(float2*)(o1 + dcol) = make_float2(
                    (dacc[mi][ni][2] + i1.x) * RSQRT2, (dacc[mi][ni][3] + i1.y) * RSQRT2);
            }
        }
    }
}

// ---------------- attention: tf32 mma flash-style, cp.async 3-stage ----------------
#define KSTR 36
#define VSTR 40

__global__ __launch_bounds__(256, 2) void attn_mma_kernel()
{
    __shared__ float Ks[3][32 * KSTR];
    __shared__ float Vs[3][32 * VSTR];

    int tid = threadIdx.x;
    int wid = tid >> 5, lane = tid & 31;
    int g = lane >> 2, t = lane & 3;
    int qhalf = blockIdx.x & 1, bh = blockIdx.x >> 1;
    int b = bh >> 3, h = bh & 7;
    int qbase = qhalf * 256 + wid * 32;

    // Q fragments resident (raw fp32 bits; HW truncates to tf32)
    const float* Qg = g_Q + ((size_t)bh * S_ + qbase) * HD;
    unsigned qf[2][4][4];
#pragma unroll
    for (int mi = 0; mi < 2; mi++) {
        int r = mi * 16 + g;
#pragma unroll
        for (int ks = 0; ks < 4; ks++) {
            qf[mi][ks][0] = su(Qg[r * HD + ks * 8 + t]);
            qf[mi][ks][1] = su(Qg[(r + 8) * HD + ks * 8 + t]);
            qf[mi][ks][2] = su(Qg[r * HD + ks * 8 + t + 4]);
            qf[mi][ks][3] = su(Qg[(r + 8) * HD + ks * 8 + t + 4]);
        }
    }

    float oacc[2][4][4];
#pragma unroll
    for (int mi = 0; mi < 2; mi++)
#pragma unroll
        for (int nd = 0; nd < 4; nd++)
#pragma unroll
            for (int c = 0; c < 4; c++) oacc[mi][nd][c] = 0.f;
    float mrow[4] = {-1e30f, -1e30f, -1e30f, -1e30f};
    float lrow[4] = {0.f, 0.f, 0.f, 0.f};

    int sl = tid >> 3;            // 0..31
    int d4 = (tid & 7) << 2;      // 0..28
    const float* Kg = g_K + (size_t)bh * S_ * HD;
    const float* Vg = g_V + (size_t)bh * S_ * HD;

    // prologue: tiles 0,1
#pragma unroll
    for (int p = 0; p < 2; p++) {
        cp16(&Ks[p][sl * KSTR + d4], Kg + (size_t)(p * 32 + sl) * HD + d4);
        cp16(&Vs[p][sl * VSTR + d4], Vg + (size_t)(p * 32 + sl) * HD + d4);
        CP_COMMIT();
    }

    for (int kt = 0; kt < 16; kt++) {
        int buf = kt % 3;
        CP_WAIT1();
        __syncthreads();
        if (kt + 2 < 16) {
            int nb = (kt + 2) % 3;
            cp16(&Ks[nb][sl * KSTR + d4], Kg + (size_t)((kt + 2) * 32 + sl) * HD + d4);
            cp16(&Vs[nb][sl * VSTR + d4], Vg + (size_t)((kt + 2) * 32 + sl) * HD + d4);
        }
        CP_COMMIT();

        // ---- QK^T ----
        float sacc[2][4][4];
#pragma unroll
        for (int mi = 0; mi < 2; mi++)
#pragma unroll
            for (int ni = 0; ni < 4; ni++)
#pragma unroll
                for (int c = 0; c < 4; c++) sacc[mi][ni][c] = 0.f;

#pragma unroll
        for (int ks = 0; ks < 4; ks++) {
            unsigned kb[4][2];
#pragma unroll
            for (int ni = 0; ni < 4; ni++) {
                kb[ni][0] = su(Ks[buf][(ni * 8 + g) * KSTR + ks * 8 + t]);
                kb[ni][1] = su(Ks[buf][(ni * 8 + g) * KSTR + ks * 8 + t + 4]);
            }
#pragma unroll
            for (int mi = 0; mi < 2; mi++)
#pragma unroll
                for (int ni = 0; ni < 4; ni++)
                    mma_tf32(sacc[mi][ni], qf[mi][ks], kb[ni]);
        }

        // ---- online softmax ----
#pragma unroll
        for (int r = 0; r < 4; r++) {
            int mi = r >> 1, cb = (r & 1) * 2;
            float tm = -1e30f;
#pragma unroll
            for (int ni = 0; ni < 4; ni++) {
                tm = fmaxf(tm, sacc[mi][ni][cb]);
                tm = fmaxf(tm, sacc[mi][ni][cb + 1]);
            }
            tm = fmaxf(tm, __shfl_xor_sync(0xffffffffu, tm, 1));
            tm = fmaxf(tm, __shfl_xor_sync(0xffffffffu, tm, 2));
            float mn = fmaxf(mrow[r], tm);
            float corr = __expf(mrow[r] - mn);
            float l = lrow[r] * corr;
#pragma unroll
            for (int ni = 0; ni < 4; ni++) {
                float p0 = __expf(sacc[mi][ni][cb] - mn);
                float p1 = __expf(sacc[mi][ni][cb + 1] - mn);
                l += p0 + p1;
                sacc[mi][ni][cb] = p0;
                sacc[mi][ni][cb + 1] = p1;
            }
#pragma unroll
            for (int nd = 0; nd < 4; nd++) {
                oacc[mi][nd][cb] *= corr;
                oacc[mi][nd][cb + 1] *= corr;
            }
            mrow[r] = mn;
            lrow[r] = l;
        }

        // ---- PV: out += P @ V ----
#pragma unroll
        for (int ks = 0; ks < 4; ks++) {
            unsigned vb[4][2];
#pragma unroll
            for (int nd = 0; nd < 4; nd++) {
                vb[nd][0] = su(Vs[buf][(ks * 8 + t) * VSTR + nd * 8 + g]);
                vb[nd][1] = su(Vs[buf][(ks * 8 + t + 4) * VSTR + nd * 8 + g]);
            }
            int src0 = (lane & ~3) | (t >> 1);
            int src1 = src0 + 2;
#pragma unroll
            for (int mi = 0; mi < 2; mi++) {
                unsigned c0 = su(sacc[mi][ks][0]);
                unsigned c1 = su(sacc[mi][ks][1]);
                unsigned c2 = su(sacc[mi][ks][2]);
                unsigned c3 = su(sacc[mi][ks][3]);
                unsigned pa_[4];
                unsigned x, y;
                x = __shfl_sync(0xffffffffu, c0, src0);
                y = __shfl_sync(0xffffffffu, c1, src0);
                pa_[0] = (t & 1) ? y : x;
                x = __shfl_sync(0xffffffffu, c2, src0);
                y = __shfl_sync(0xffffffffu, c3, src0);
                pa_[1] = (t & 1) ? y : x;
                x = __shfl_sync(0xffffffffu, c0, src1);
                y = __shfl_sync(0xffffffffu, c1, src1);
                pa_[2] = (t & 1) ? y : x;
                x = __shfl_sync(0xffffffffu, c2, src1);
                y = __shfl_sync(0xffffffffu, c3, src1);
                pa_[3] = (t & 1) ? y : x;
#pragma unroll
                for (int nd = 0; nd < 4; nd++)
                    mma_tf32(oacc[mi][nd], pa_, vb[nd]);
            }
        }
    }

    // finalize + write [b,s,H]
#pragma unroll
    for (int r = 0; r < 4; r++) {
        int mi = r >> 1, cb = (r & 1) * 2;
        float lt = lrow[r];
        lt += __shfl_xor_sync(0xffffffffu, lt, 1);
        lt += __shfl_xor_sync(0xffffffffu, lt, 2);
        float inv = 1.f / lt;
        int row = qbase + (r >> 1) * 16 + (r & 1) * 8 + g;
        float* op = g_attn + ((size_t)b * S_ + row) * H_ + h * HD;
#pragma unroll
        for (int nd = 0; nd < 4; nd++) {
            *(float2*)(op + nd * 8 + 2 * t) = make_float2(
                oacc[mi][nd][cb] * inv, oacc[mi][nd][cb + 1] * inv);
        }
    }
}

// ---------------- launch ----------------
extern "C" void kernel_launch(void* const* d_in, const int* in_sizes, int n_in,
                              void* d_out, int out_size)
{
    const float* inputs = (const float*)d_in[0];
    const float* rmask  = (const float*)d_in[1];
    const float* w_in   = (const float*)d_in[2];   // [768,256]
    const float* w_out  = (const float*)d_in[3];   // [256,256]
    const float* gamma  = (const float*)d_in[4];
    const float* beta   = (const float*)d_in[5];
    float* out = (float*)d_out;

    const int gemm_smem = 4 * TILE_F * (int)sizeof(float);   // 73728 B -> 2 CTAs/SM
    cudaFuncSetAttribute(gemm_mma<1>, cudaFuncAttributeMaxDynamicSharedMemorySize, gemm_smem);
    cudaFuncSetAttribute(gemm_mma<2>, cudaFuncAttributeMaxDynamicSharedMemorySize, gemm_smem);

    ln_kernel<<<M_ / 8, 256>>>(inputs, gamma, beta, rmask);
    gemm_mma<1><<<dim3(6, M_ / 128), 256, gemm_smem>>>(w_in, nullptr, nullptr);
    attn_mma_kernel<<<512, 256>>>();
    gemm_mma<2><<<dim3(2, M_ / 128), 256, gemm_smem>>>(w_out, inputs, out);
}

// round 6
// speedup vs baseline: 5.6312x; 1.5616x over previous
#include <cuda_runtime.h>
#include <cuda_fp16.h>
#include <math.h>
#include <stdint.h>

// Problem dims (fixed)
#define B_   32
#define S_   512
#define H_   256
#define NH   8
#define HD   32
#define M_   (B_ * S_)     // 16384
#define TOT  (M_ * H_)

#define QK_SCALE   0.17677669529663689f   // 1/sqrt(32)
#define RSQRT2     0.70710678118654752f
#define LN_EPS     1e-5f

// ---------------- scratch ----------------
__device__ __half g_normed[TOT];
__device__ __half g_wih[768 * 256];
__device__ __half g_woh[256 * 256];
__device__ __half g_Q[TOT];     // [b,h,s,d], (q*q+1e-6)*scale
__device__ __half g_K[TOT];     // [b,h,s,d], + log(radial_mask)
__device__ __half g_Vt[TOT];    // [b,h,d,s]  (transposed for PV B-frags)
__device__ __half g_attn[TOT];  // [b,s,H]
__device__ float  g_lr[M_];

// ---------------- helpers ----------------
__device__ __forceinline__ void mma_f16(float* d, const unsigned* a, const unsigned* b) {
    asm("mma.sync.aligned.m16n8k16.row.col.f32.f16.f16.f32 "
        "{%0,%1,%2,%3},{%4,%5,%6,%7},{%8,%9},{%0,%1,%2,%3};"
        : "+f"(d[0]), "+f"(d[1]), "+f"(d[2]), "+f"(d[3])
        : "r"(a[0]), "r"(a[1]), "r"(a[2]), "r"(a[3]), "r"(b[0]), "r"(b[1]));
}
__device__ __forceinline__ unsigned packh2(float lo, float hi) {
    __half2 h = __floats2half2_rn(lo, hi);
    return *(unsigned*)&h;
}
__device__ __forceinline__ unsigned ldu32(const __half* p) {
    return *(const unsigned*)p;
}
__device__ __forceinline__ void cp16s(uint32_t saddr, const void* gptr) {
    asm volatile("cp.async.cg.shared.global [%0], [%1], 16;" :: "r"(saddr), "l"(gptr));
}
#define CP_COMMIT() asm volatile("cp.async.commit_group;")
#define CP_WAIT1()  asm volatile("cp.async.wait_group 1;")

// ---------------- weight conversion (fp32 -> fp16) ----------------
__global__ __launch_bounds__(256) void conv_w(
    const float* __restrict__ wi, const float* __restrict__ wo)
{
    int i = blockIdx.x * 256 + threadIdx.x;
    const int N1 = 768 * 256 / 2;   // 98304 half2
    const int N2 = 256 * 256 / 2;   // 32768 half2
    if (i < N1) {
        float2 v = ((const float2*)wi)[i];
        ((__half2*)g_wih)[i] = __floats2half2_rn(v.x, v.y);
    } else if (i < N1 + N2) {
        int j = i - N1;
        float2 v = ((const float2*)wo)[j];
        ((__half2*)g_woh)[j] = __floats2half2_rn(v.x, v.y);
    }
}

// ---------------- LayerNorm (fp32 in -> fp16 out) ----------------
__global__ __launch_bounds__(256) void ln_kernel(
    const float* __restrict__ x, const float* __restrict__ gamma,
    const float* __restrict__ beta, const float* __restrict__ rmask)
{
    int warp = threadIdx.x >> 5, lane = threadIdx.x & 31;
    int row  = blockIdx.x * 8 + warp;
    const float2* xr = (const float2*)(x + row * H_);
    const float2* g2 = (const float2*)gamma;
    const float2* b2 = (const float2*)beta;

    float2 v[4];
    float sum = 0.f, sq = 0.f;
#pragma unroll
    for (int k = 0; k < 4; k++) {
        float2 t = xr[lane + 32 * k];
        v[k] = t;
        sum += t.x + t.y;
        sq  += t.x * t.x + t.y * t.y;
    }
#pragma unroll
    for (int o = 16; o > 0; o >>= 1) {
        sum += __shfl_xor_sync(0xffffffffu, sum, o);
        sq  += __shfl_xor_sync(0xffffffffu, sq,  o);
    }
    float mu = sum * (1.f / H_);
    float var = sq * (1.f / H_) - mu * mu;
    float rstd = rsqrtf(var + LN_EPS);

    __half2* nr = (__half2*)(g_normed + row * H_);
#pragma unroll
    for (int k = 0; k < 4; k++) {
        int idx = lane + 32 * k;
        float2 gv = g2[idx], bv = b2[idx];
        nr[idx] = __floats2half2_rn(
            (v[k].x - mu) * rstd * gv.x + bv.x,
            (v[k].y - mu) * rstd * gv.y + bv.y);
    }
    if (lane == 0) g_lr[row] = logf(rmask[row]);
}

// ---------------- fp16 MMA GEMM (NT), cp.async 2-stage ----------------
// C[m,n] = sum_k A[m,k]*Bmat[n,k]; 128x128 CTA tile, k-tile 64 halves, 8 warps of 64x32.
// MODE 1: A=g_normed, B=g_wih, fused q/k/v transforms + scatter (Vt transposed).
// MODE 2: A=g_attn,   B=g_woh, residual epilogue -> fp32 out.
#define SSTRH 72    // halves per smem row (64 + 8 pad); 144 bytes
#define TILEH (128 * SSTRH)

template <int MODE>
__global__ __launch_bounds__(256) void gemm_f16(
    const float* __restrict__ extra, float* __restrict__ C)
{
    extern __shared__ __half smh[];
    __half* As = smh;                 // [2][128*SSTRH]
    __half* Bs = smh + 2 * TILEH;

    const __half* A    = (MODE == 1) ? g_normed : g_attn;
    const __half* Bmat = (MODE == 1) ? g_wih : g_woh;
    const int K = 256;

    int tid = threadIdx.x;
    int wid = tid >> 5, lane = tid & 31;
    int g = lane >> 2, t = lane & 3;
    int wm = wid >> 2, wn = wid & 3;
    int brow = blockIdx.y, bcol = blockIdx.x;

    int c8  = tid & 7;        // 16B chunk within 128B row
    int rwg = tid >> 3;       // 0..31

    const __half* Agb = A    + (size_t)(brow * 128) * K;
    const __half* Bgb = Bmat + (size_t)(bcol * 128) * K;
    uint32_t asBase = (uint32_t)__cvta_generic_to_shared(As);
    uint32_t bsBase = (uint32_t)__cvta_generic_to_shared(Bs);

    float dacc[4][4][4];
#pragma unroll
    for (int i = 0; i < 4; i++)
#pragma unroll
        for (int j = 0; j < 4; j++)
#pragma unroll
            for (int c = 0; c < 4; c++) dacc[i][j][c] = 0.f;

#define STAGE(kt_) do { \
    int _kb = (kt_) * 64; \
    uint32_t _ab = asBase + ((kt_) & 1) * (TILEH * 2); \
    uint32_t _bb = bsBase + ((kt_) & 1) * (TILEH * 2); \
    _Pragma("unroll") \
    for (int _i = 0; _i < 4; _i++) { \
        int _row = rwg + _i * 32; \
        uint32_t _off = (uint32_t)_row * (SSTRH * 2) + (uint32_t)c8 * 16; \
        cp16s(_ab + _off, Agb + (size_t)_row * K + _kb + c8 * 8); \
        cp16s(_bb + _off, Bgb + (size_t)_row * K + _kb + c8 * 8); \
    } \
} while (0)

    STAGE(0); CP_COMMIT();
    STAGE(1); CP_COMMIT();

    for (int kt = 0; kt < 4; kt++) {
        CP_WAIT1();
        __syncthreads();

        const __half* as = As + (kt & 1) * TILEH;
        const __half* bs = Bs + (kt & 1) * TILEH;
#pragma unroll
        for (int ks = 0; ks < 4; ks++) {
            unsigned af[4][4], bf[4][2];
#pragma unroll
            for (int mi = 0; mi < 4; mi++) {
                int r = wm * 64 + mi * 16 + g;
                af[mi][0] = ldu32(&as[r * SSTRH + ks * 16 + 2 * t]);
                af[mi][1] = ldu32(&as[(r + 8) * SSTRH + ks * 16 + 2 * t]);
                af[mi][2] = ldu32(&as[r * SSTRH + ks * 16 + 2 * t + 8]);
                af[mi][3] = ldu32(&as[(r + 8) * SSTRH + ks * 16 + 2 * t + 8]);
            }
#pragma unroll
            for (int ni = 0; ni < 4; ni++) {
                int n = wn * 32 + ni * 8 + g;
                bf[ni][0] = ldu32(&bs[n * SSTRH + ks * 16 + 2 * t]);
                bf[ni][1] = ldu32(&bs[n * SSTRH + ks * 16 + 2 * t + 8]);
            }
#pragma unroll
            for (int mi = 0; mi < 4; mi++)
#pragma unroll
                for (int ni = 0; ni < 4; ni++)
                    mma_f16(dacc[mi][ni], af[mi], bf[ni]);
        }
        __syncthreads();

        if (kt + 2 < 4) STAGE(kt + 2);
        CP_COMMIT();
    }
#undef STAGE

    // epilogue
    if (MODE == 1) {
        int region = (bcol * 128) >> 8;            // 0=q 1=k 2=v (uniform per CTA)
        int hh = ((bcol & 1) << 2) + wn;           // head index
#pragma unroll
        for (int mi = 0; mi < 4; mi++) {
            int r0 = brow * 128 + wm * 64 + mi * 16 + g;
            int r1 = r0 + 8;
            int b = r0 >> 9, s0 = r0 & 511, s1 = r1 & 511;
            if (region == 2) {
                __half* vt = g_Vt + (size_t)(b * 8 + hh) * HD * S_;
#pragma unroll
                for (int ni = 0; ni < 4; ni++) {
                    int d0 = ni * 8 + 2 * t, d1 = d0 + 1;
                    vt[d0 * S_ + s0] = __float2half_rn(dacc[mi][ni][0]);
                    vt[d1 * S_ + s0] = __float2half_rn(dacc[mi][ni][1]);
                    vt[d0 * S_ + s1] = __float2half_rn(dacc[mi][ni][2]);
                    vt[d1 * S_ + s1] = __float2half_rn(dacc[mi][ni][3]);
                }
            } else {
                __half* dst = (region == 0) ? g_Q : g_K;
                float lr0 = (region == 1) ? g_lr[r0] : 0.f;
                float lr1 = (region == 1) ? g_lr[r1] : 0.f;
                __half* p0 = dst + ((size_t)(b * 8 + hh) * S_ + s0) * HD;
                __half* p1 = dst + ((size_t)(b * 8 + hh) * S_ + s1) * HD;
#pragma unroll
                for (int ni = 0; ni < 4; ni++) {
                    int dcol = ni * 8 + 2 * t;
                    float v0 = dacc[mi][ni][0], v1 = dacc[mi][ni][1];
                    float v2 = dacc[mi][ni][2], v3 = dacc[mi][ni][3];
                    if (region == 0) {
                        v0 = (v0 * v0 + 1e-6f) * QK_SCALE;
                        v1 = (v1 * v1 + 1e-6f) * QK_SCALE;
                        v2 = (v2 * v2 + 1e-6f) * QK_SCALE;
                        v3 = (v3 * v3 + 1e-6f) * QK_SCALE;
                    } else {
                        v0 += lr0; v1 += lr0; v2 += lr1; v3 += lr1;
                    }
                    *(__half2*)(p0 + dcol) = __floats2half2_rn(v0, v1);
                    *(__half2*)(p1 + dcol) = __floats2half2_rn(v2, v3);
                }
            }
        }
    } else {
#pragma unroll
        for (int mi = 0; mi < 4; mi++) {
            int r0 = brow * 128 + wm * 64 + mi * 16 + g;
            int r1 = r0 + 8;
            int cbase = bcol * 128 + wn * 32;
            const float* in0 = extra + (size_t)r0 * H_ + cbase;
            const float* in1 = extra + (size_t)r1 * H_ + cbase;
            float* o0 = C + (size_t)r0 * H_ + cbase;
            float* o1 = C + (size_t)r1 * H_ + cbase;
#pragma unroll
            for (int ni = 0; ni < 4; ni++) {
                int dcol = ni * 8 + 2 * t;
                float2 i0 = *(const float2*)(in0 + dcol);
                float2 i1 = *(const float2*)(in1 + dcol);
                *(float2*)(o0 + dcol) = make_float2(
                    (dacc[mi][ni][0] + i0.x) * RSQRT2, (dacc[mi][ni][1] + i0.y) * RSQRT2);
                *(float2*)(o1 + dcol) = make_float2(
                    (dacc[mi][ni][2] + i1.x) * RSQRT2, (dacc[mi][ni][3] + i1.y) * RSQRT2);
            }
        }
    }
}

// ---------------- attention: fp16 mma flash-style, cp.async 3-stage ----------------
// grid = 512: blockIdx.x = (bh<<1)|qhalf. 8 warps x 32 q-rows.
// K tiles [32 s][HD] (pad 40); V tiles [32 d][32 s] (pad 40) from pre-transposed g_Vt.
#define ASTR 40

__global__ __launch_bounds__(256) void attn_f16_kernel()
{
    __shared__ __half Ks[3][32 * ASTR];
    __shared__ __half Vs[3][32 * ASTR];

    int tid = threadIdx.x;
    int wid = tid >> 5, lane = tid & 31;
    int g = lane >> 2, t = lane & 3;
    int qhalf = blockIdx.x & 1, bh = blockIdx.x >> 1;
    int b = bh >> 3, h = bh & 7;
    int qbase = qhalf * 256 + wid * 32;

    // Q fragments resident: m16n8k16 A-frags, [mi 2][ks 2][4]
    const __half* Qg = g_Q + ((size_t)bh * S_ + qbase) * HD;
    unsigned qf[2][2][4];
#pragma unroll
    for (int mi = 0; mi < 2; mi++) {
        int r = mi * 16 + g;
#pragma unroll
        for (int ks = 0; ks < 2; ks++) {
            qf[mi][ks][0] = ldu32(&Qg[r * HD + ks * 16 + 2 * t]);
            qf[mi][ks][1] = ldu32(&Qg[(r + 8) * HD + ks * 16 + 2 * t]);
            qf[mi][ks][2] = ldu32(&Qg[r * HD + ks * 16 + 2 * t + 8]);
            qf[mi][ks][3] = ldu32(&Qg[(r + 8) * HD + ks * 16 + 2 * t + 8]);
        }
    }

    float oacc[2][4][4];
#pragma unroll
    for (int mi = 0; mi < 2; mi++)
#pragma unroll
        for (int nd = 0; nd < 4; nd++)
#pragma unroll
            for (int c = 0; c < 4; c++) oacc[mi][nd][c] = 0.f;
    float mrow[4] = {-1e30f, -1e30f, -1e30f, -1e30f};
    float lrow[4] = {0.f, 0.f, 0.f, 0.f};

    // loaders: 256 threads = 2 matrices x 32 rows x 4 chunks(16B)
    int mat = tid >> 7;           // 0 = K, 1 = V
    int lrw = (tid >> 2) & 31;    // row in tile
    int c4  = tid & 3;            // 16B chunk (8 halves)
    const __half* Kg  = g_K  + (size_t)bh * S_ * HD;
    const __half* Vtg = g_Vt + (size_t)bh * HD * S_;
    uint32_t ksb = (uint32_t)__cvta_generic_to_shared(&Ks[0][0]);
    uint32_t vsb = (uint32_t)__cvta_generic_to_shared(&Vs[0][0]);

#define ASTAGE(kt_) do { \
    int _st = (kt_) % 3; \
    uint32_t _soff = (uint32_t)_st * (32 * ASTR * 2) + (uint32_t)lrw * (ASTR * 2) + (uint32_t)c4 * 16; \
    if (mat == 0) \
        cp16s(ksb + _soff, Kg + (size_t)((kt_) * 32 + lrw) * HD + c4 * 8); \
    else \
        cp16s(vsb + _soff, Vtg + (size_t)lrw * S_ + (kt_) * 32 + c4 * 8); \
} while (0)

    ASTAGE(0); CP_COMMIT();
    ASTAGE(1); CP_COMMIT();

    for (int kt = 0; kt < 16; kt++) {
        int buf = kt % 3;
        CP_WAIT1();
        __syncthreads();
        if (kt + 2 < 16) ASTAGE(kt + 2);
        CP_COMMIT();

        // ---- QK^T: S[32 q][32 k] ----
        float sacc[2][4][4];
#pragma unroll
        for (int mi = 0; mi < 2; mi++)
#pragma unroll
            for (int ni = 0; ni < 4; ni++)
#pragma unroll
                for (int c = 0; c < 4; c++) sacc[mi][ni][c] = 0.f;

#pragma unroll
        for (int ks = 0; ks < 2; ks++) {
            unsigned kb[4][2];
#pragma unroll
            for (int ni = 0; ni < 4; ni++) {
                kb[ni][0] = ldu32(&Ks[buf][(ni * 8 + g) * ASTR + ks * 16 + 2 * t]);
                kb[ni][1] = ldu32(&Ks[buf][(ni * 8 + g) * ASTR + ks * 16 + 2 * t + 8]);
            }
#pragma unroll
            for (int mi = 0; mi < 2; mi++)
#pragma unroll
                for (int ni = 0; ni < 4; ni++)
                    mma_f16(sacc[mi][ni], qf[mi][ks], kb[ni]);
        }

        // ---- online softmax ----
#pragma unroll
        for (int r = 0; r < 4; r++) {
            int mi = r >> 1, cb = (r & 1) * 2;
            float tm = -1e30f;
#pragma unroll
            for (int ni = 0; ni < 4; ni++) {
                tm = fmaxf(tm, sacc[mi][ni][cb]);
                tm = fmaxf(tm, sacc[mi][ni][cb + 1]);
            }
            tm = fmaxf(tm, __shfl_xor_sync(0xffffffffu, tm, 1));
            tm = fmaxf(tm, __shfl_xor_sync(0xffffffffu, tm, 2));
            float mn = fmaxf(mrow[r], tm);
            float corr = __expf(mrow[r] - mn);
            float l = lrow[r] * corr;
#pragma unroll
            for (int ni = 0; ni < 4; ni++) {
                float p0 = __expf(sacc[mi][ni][cb] - mn);
                float p1 = __expf(sacc[mi][ni][cb + 1] - mn);
                l += p0 + p1;
                sacc[mi][ni][cb] = p0;
                sacc[mi][ni][cb + 1] = p1;
            }
#pragma unroll
            for (int nd = 0; nd < 4; nd++) {
                oacc[mi][nd][cb] *= corr;
                oacc[mi][nd][cb + 1] *= corr;
            }
            mrow[r] = mn;
            lrow[r] = l;
        }

        // ---- PV: out += P @ V  (A-frags packed locally, NO shuffles) ----
#pragma unroll
        for (int ks = 0; ks < 2; ks++) {
            unsigned vb[4][2];
#pragma unroll
            for (int nd = 0; nd < 4; nd++) {
                vb[nd][0] = ldu32(&Vs[buf][(nd * 8 + g) * ASTR + ks * 16 + 2 * t]);
                vb[nd][1] = ldu32(&Vs[buf][(nd * 8 + g) * ASTR + ks * 16 + 2 * t + 8]);
            }
#pragma unroll
            for (int mi = 0; mi < 2; mi++) {
                unsigned pa_[4];
                pa_[0] = packh2(sacc[mi][2 * ks][0],     sacc[mi][2 * ks][1]);
                pa_[1] = packh2(sacc[mi][2 * ks][2],     sacc[mi][2 * ks][3]);
                pa_[2] = packh2(sacc[mi][2 * ks + 1][0], sacc[mi][2 * ks + 1][1]);
                pa_[3] = packh2(sacc[mi][2 * ks + 1][2], sacc[mi][2 * ks + 1][3]);
#pragma unroll
                for (int nd = 0; nd < 4; nd++)
                    mma_f16(oacc[mi][nd], pa_, vb[nd]);
            }
        }
    }
#undef ASTAGE

    // finalize + write [b,s,H] as half
#pragma unroll
    for (int r = 0; r < 4; r++) {
        int mi = r >> 1, cb = (r & 1) * 2;
        float lt = lrow[r];
        lt += __shfl_xor_sync(0xffffffffu, lt, 1);
        lt += __shfl_xor_sync(0xffffffffu, lt, 2);
        float inv = 1.f / lt;
        int row = qbase + (r >> 1) * 16 + (r & 1) * 8 + g;
        __half* op = g_attn + ((size_t)b * S_ + row) * H_ + h * HD;
#pragma unroll
        for (int nd = 0; nd < 4; nd++) {
            *(__half2*)(op + nd * 8 + 2 * t) = __floats2half2_rn(
                oacc[mi][nd][cb] * inv, oacc[mi][nd][cb + 1] * inv);
        }
    }
}

// ---------------- launch ----------------
extern "C" void kernel_launch(void* const* d_in, const int* in_sizes, int n_in,
                              void* d_out, int out_size)
{
    const float* inputs = (const float*)d_in[0];
    const float* rmask  = (const float*)d_in[1];
    const float* w_in   = (const float*)d_in[2];   // [768,256]
    const float* w_out  = (const float*)d_in[3];   // [256,256]
    const float* gamma  = (const float*)d_in[4];
    const float* beta   = (const float*)d_in[5];
    float* out = (float*)d_out;

    const int gemm_smem = 4 * TILEH * (int)sizeof(__half);   // 73728 B
    cudaFuncSetAttribute(gemm_f16<1>, cudaFuncAttributeMaxDynamicSharedMemorySize, gemm_smem);
    cudaFuncSetAttribute(gemm_f16<2>, cudaFuncAttributeMaxDynamicSharedMemorySize, gemm_smem);

    conv_w<<<512, 256>>>(w_in, w_out);
    ln_kernel<<<M_ / 8, 256>>>(inputs, gamma, beta, rmask);
    gemm_f16<1><<<dim3(6, M_ / 128), 256, gemm_smem>>>(nullptr, nullptr);
    attn_f16_kernel<<<512, 256>>>();
    gemm_f16<2><<<dim3(2, M_ / 128), 256, gemm_smem>>>(inputs, out);
}

// round 7
// speedup vs baseline: 5.9633x; 1.0590x over previous
#include <cuda_runtime.h>
#include <cuda_fp16.h>
#include <math.h>
#include <stdint.h>

// Problem dims (fixed)
#define B_   32
#define S_   512
#define H_   256
#define NH   8
#define HD   32
#define M_   (B_ * S_)     // 16384
#define TOT  (M_ * H_)

#define QK_SCALE_L2E 0.25505654440f     // (1/sqrt(32)) * log2(e)
#define RSQRT2       0.70710678118654752f
#define LN_EPS       1e-5f

// ---------------- scratch ----------------
__device__ __half g_normed[TOT];
__device__ __half g_wih[768 * 256];
__device__ __half g_woh[256 * 256];
__device__ __half g_Q[TOT];     // [b,h,s,d], (q*q+1e-6)*scale*log2e  (>= 0)
__device__ __half g_K[TOT];     // [b,h,s,d], + log(radial_mask)
__device__ __half g_Vt[TOT];    // [b,h,d,s]
__device__ __half g_attn[TOT];  // [b,s,H]
__device__ float  g_lr[M_];
__device__ float  g_maxkd[B_ * NH * HD];   // per-(b,h) per-dim max of K

// ---------------- helpers ----------------
__device__ __forceinline__ void mma_f16(float* d, const unsigned* a, const unsigned* b) {
    asm("mma.sync.aligned.m16n8k16.row.col.f32.f16.f16.f32 "
        "{%0,%1,%2,%3},{%4,%5,%6,%7},{%8,%9},{%0,%1,%2,%3};"
        : "+f"(d[0]), "+f"(d[1]), "+f"(d[2]), "+f"(d[3])
        : "r"(a[0]), "r"(a[1]), "r"(a[2]), "r"(a[3]), "r"(b[0]), "r"(b[1]));
}
__device__ __forceinline__ unsigned packh2(float lo, float hi) {
    __half2 h = __floats2half2_rn(lo, hi);
    return *(unsigned*)&h;
}
__device__ __forceinline__ unsigned ldu32(const __half* p) {
    return *(const unsigned*)p;
}
__device__ __forceinline__ float ex2(float x) {
    float y;
    asm("ex2.approx.f32 %0, %1;" : "=f"(y) : "f"(x));
    return y;
}
__device__ __forceinline__ void cp16s(uint32_t saddr, const void* gptr) {
    asm volatile("cp.async.cg.shared.global [%0], [%1], 16;" :: "r"(saddr), "l"(gptr));
}
#define CP_COMMIT() asm volatile("cp.async.commit_group;")
#define CP_WAIT1()  asm volatile("cp.async.wait_group 1;")

// ---------------- weight conversion (fp32 -> fp16) ----------------
__global__ __launch_bounds__(256) void conv_w(
    const float* __restrict__ wi, const float* __restrict__ wo)
{
    int i = blockIdx.x * 256 + threadIdx.x;
    const int N1 = 768 * 256 / 2;
    const int N2 = 256 * 256 / 2;
    if (i < N1) {
        float2 v = ((const float2*)wi)[i];
        ((__half2*)g_wih)[i] = __floats2half2_rn(v.x, v.y);
    } else if (i < N1 + N2) {
        int j = i - N1;
        float2 v = ((const float2*)wo)[j];
        ((__half2*)g_woh)[j] = __floats2half2_rn(v.x, v.y);
    }
}

// ---------------- LayerNorm (fp32 in -> fp16 out) ----------------
__global__ __launch_bounds__(256) void ln_kernel(
    const float* __restrict__ x, const float* __restrict__ gamma,
    const float* __restrict__ beta, const float* __restrict__ rmask)
{
    int warp = threadIdx.x >> 5, lane = threadIdx.x & 31;
    int row  = blockIdx.x * 8 + warp;
    const float2* xr = (const float2*)(x + row * H_);
    const float2* g2 = (const float2*)gamma;
    const float2* b2 = (const float2*)beta;

    float2 v[4];
    float sum = 0.f, sq = 0.f;
#pragma unroll
    for (int k = 0; k < 4; k++) {
        float2 t = xr[lane + 32 * k];
        v[k] = t;
        sum += t.x + t.y;
        sq  += t.x * t.x + t.y * t.y;
    }
#pragma unroll
    for (int o = 16; o > 0; o >>= 1) {
        sum += __shfl_xor_sync(0xffffffffu, sum, o);
        sq  += __shfl_xor_sync(0xffffffffu, sq,  o);
    }
    float mu = sum * (1.f / H_);
    float var = sq * (1.f / H_) - mu * mu;
    float rstd = rsqrtf(var + LN_EPS);

    __half2* nr = (__half2*)(g_normed + row * H_);
#pragma unroll
    for (int k = 0; k < 4; k++) {
        int idx = lane + 32 * k;
        float2 gv = g2[idx], bv = b2[idx];
        nr[idx] = __floats2half2_rn(
            (v[k].x - mu) * rstd * gv.x + bv.x,
            (v[k].y - mu) * rstd * gv.y + bv.y);
    }
    if (lane == 0) g_lr[row] = logf(rmask[row]);
}

// ---------------- per-(b,h) per-dim max of K ----------------
__global__ __launch_bounds__(256) void maxk_kernel()
{
    int bh = blockIdx.x;
    int tid = threadIdx.x;
    int d2 = tid & 15;        // half2 column
    int sg = tid >> 4;        // 16 s-groups
    const __half2* Kg = (const __half2*)(g_K + (size_t)bh * S_ * HD);
    float mx = -1e30f, my = -1e30f;
    for (int s = sg; s < S_; s += 16) {
        float2 v = __half22float2(Kg[s * 16 + d2]);
        mx = fmaxf(mx, v.x);
        my = fmaxf(my, v.y);
    }
    __shared__ float red[16][32];
    red[sg][2 * d2]     = mx;
    red[sg][2 * d2 + 1] = my;
    __syncthreads();
    if (tid < 32) {
        float m = red[0][tid];
#pragma unroll
        for (int r = 1; r < 16; r++) m = fmaxf(m, red[r][tid]);
        g_maxkd[bh * 32 + tid] = m;
    }
}

// ---------------- fp16 MMA GEMM (NT), cp.async 2-stage ----------------
#define SSTRH 72
#define TILEH (128 * SSTRH)

template <int MODE>
__global__ __launch_bounds__(256) void gemm_f16(
    const float* __restrict__ extra, float* __restrict__ C)
{
    extern __shared__ __half smh[];
    __half* As = smh;
    __half* Bs = smh + 2 * TILEH;

    const __half* A    = (MODE == 1) ? g_normed : g_attn;
    const __half* Bmat = (MODE == 1) ? g_wih : g_woh;
    const int K = 256;

    int tid = threadIdx.x;
    int wid = tid >> 5, lane = tid & 31;
    int g = lane >> 2, t = lane & 3;
    int wm = wid >> 2, wn = wid & 3;
    int brow = blockIdx.y, bcol = blockIdx.x;

    int c8  = tid & 7;
    int rwg = tid >> 3;

    const __half* Agb = A    + (size_t)(brow * 128) * K;
    const __half* Bgb = Bmat + (size_t)(bcol * 128) * K;
    uint32_t asBase = (uint32_t)__cvta_generic_to_shared(As);
    uint32_t bsBase = (uint32_t)__cvta_generic_to_shared(Bs);

    float dacc[4][4][4];
#pragma unroll
    for (int i = 0; i < 4; i++)
#pragma unroll
        for (int j = 0; j < 4; j++)
#pragma unroll
            for (int c = 0; c < 4; c++) dacc[i][j][c] = 0.f;

#define STAGE(kt_) do { \
    int _kb = (kt_) * 64; \
    uint32_t _ab = asBase + ((kt_) & 1) * (TILEH * 2); \
    uint32_t _bb = bsBase + ((kt_) & 1) * (TILEH * 2); \
    _Pragma("unroll") \
    for (int _i = 0; _i < 4; _i++) { \
        int _row = rwg + _i * 32; \
        uint32_t _off = (uint32_t)_row * (SSTRH * 2) + (uint32_t)c8 * 16; \
        cp16s(_ab + _off, Agb + (size_t)_row * K + _kb + c8 * 8); \
        cp16s(_bb + _off, Bgb + (size_t)_row * K + _kb + c8 * 8); \
    } \
} while (0)

    STAGE(0); CP_COMMIT();
    STAGE(1); CP_COMMIT();

    for (int kt = 0; kt < 4; kt++) {
        CP_WAIT1();
        __syncthreads();

        const __half* as = As + (kt & 1) * TILEH;
        const __half* bs = Bs + (kt & 1) * TILEH;
#pragma unroll
        for (int ks = 0; ks < 4; ks++) {
            unsigned af[4][4], bf[4][2];
#pragma unroll
            for (int mi = 0; mi < 4; mi++) {
                int r = wm * 64 + mi * 16 + g;
                af[mi][0] = ldu32(&as[r * SSTRH + ks * 16 + 2 * t]);
                af[mi][1] = ldu32(&as[(r + 8) * SSTRH + ks * 16 + 2 * t]);
                af[mi][2] = ldu32(&as[r * SSTRH + ks * 16 + 2 * t + 8]);
                af[mi][3] = ldu32(&as[(r + 8) * SSTRH + ks * 16 + 2 * t + 8]);
            }
#pragma unroll
            for (int ni = 0; ni < 4; ni++) {
                int n = wn * 32 + ni * 8 + g;
                bf[ni][0] = ldu32(&bs[n * SSTRH + ks * 16 + 2 * t]);
                bf[ni][1] = ldu32(&bs[n * SSTRH + ks * 16 + 2 * t + 8]);
            }
#pragma unroll
            for (int mi = 0; mi < 4; mi++)
#pragma unroll
                for (int ni = 0; ni < 4; ni++)
                    mma_f16(dacc[mi][ni], af[mi], bf[ni]);
        }
        __syncthreads();

        if (kt + 2 < 4) STAGE(kt + 2);
        CP_COMMIT();
    }
#undef STAGE

    if (MODE == 1) {
        int region = (bcol * 128) >> 8;
        int hh = ((bcol & 1) << 2) + wn;
#pragma unroll
        for (int mi = 0; mi < 4; mi++) {
            int r0 = brow * 128 + wm * 64 + mi * 16 + g;
            int r1 = r0 + 8;
            int b = r0 >> 9, s0 = r0 & 511, s1 = r1 & 511;
            if (region == 2) {
                __half* vt = g_Vt + (size_t)(b * 8 + hh) * HD * S_;
#pragma unroll
                for (int ni = 0; ni < 4; ni++) {
                    int d0 = ni * 8 + 2 * t, d1 = d0 + 1;
                    vt[d0 * S_ + s0] = __float2half_rn(dacc[mi][ni][0]);
                    vt[d1 * S_ + s0] = __float2half_rn(dacc[mi][ni][1]);
                    vt[d0 * S_ + s1] = __float2half_rn(dacc[mi][ni][2]);
                    vt[d1 * S_ + s1] = __float2half_rn(dacc[mi][ni][3]);
                }
            } else {
                __half* dst = (region == 0) ? g_Q : g_K;
                float lr0 = (region == 1) ? g_lr[r0] : 0.f;
                float lr1 = (region == 1) ? g_lr[r1] : 0.f;
                __half* p0 = dst + ((size_t)(b * 8 + hh) * S_ + s0) * HD;
                __half* p1 = dst + ((size_t)(b * 8 + hh) * S_ + s1) * HD;
#pragma unroll
                for (int ni = 0; ni < 4; ni++) {
                    int dcol = ni * 8 + 2 * t;
                    float v0 = dacc[mi][ni][0], v1 = dacc[mi][ni][1];
                    float v2 = dacc[mi][ni][2], v3 = dacc[mi][ni][3];
                    if (region == 0) {
                        v0 = (v0 * v0 + 1e-6f) * QK_SCALE_L2E;
                        v1 = (v1 * v1 + 1e-6f) * QK_SCALE_L2E;
                        v2 = (v2 * v2 + 1e-6f) * QK_SCALE_L2E;
                        v3 = (v3 * v3 + 1e-6f) * QK_SCALE_L2E;
                    } else {
                        v0 += lr0; v1 += lr0; v2 += lr1; v3 += lr1;
                    }
                    *(__half2*)(p0 + dcol) = __floats2half2_rn(v0, v1);
                    *(__half2*)(p1 + dcol) = __floats2half2_rn(v2, v3);
                }
            }
        }
    } else {
#pragma unroll
        for (int mi = 0; mi < 4; mi++) {
            int r0 = brow * 128 + wm * 64 + mi * 16 + g;
            int r1 = r0 + 8;
            int cbase = bcol * 128 + wn * 32;
            const float* in0 = extra + (size_t)r0 * H_ + cbase;
            const float* in1 = extra + (size_t)r1 * H_ + cbase;
            float* o0 = C + (size_t)r0 * H_ + cbase;
            float* o1 = C + (size_t)r1 * H_ + cbase;
#pragma unroll
            for (int ni = 0; ni < 4; ni++) {
                int dcol = ni * 8 + 2 * t;
                float2 i0 = *(const float2*)(in0 + dcol);
                float2 i1 = *(const float2*)(in1 + dcol);
                *(float2*)(o0 + dcol) = make_float2(
                    (dacc[mi][ni][0] + i0.x) * RSQRT2, (dacc[mi][ni][1] + i0.y) * RSQRT2);
                *(float2*)(o1 + dcol) = make_float2(
                    (dacc[mi][ni][2] + i1.x) * RSQRT2, (dacc[mi][ni][3] + i1.y) * RSQRT2);
            }
        }
    }
}

// ---------------- attention: fp16 mma, STATIC softmax bound (no online rescale) ----------------
#define ASTR 40

__global__ __launch_bounds__(256) void attn_f16_kernel()
{
    __shared__ __half Ks[3][32 * ASTR];
    __shared__ __half Vs[3][32 * ASTR];

    int tid = threadIdx.x;
    int wid = tid >> 5, lane = tid & 31;
    int g = lane >> 2, t = lane & 3;
    int qhalf = blockIdx.x & 1, bh = blockIdx.x >> 1;
    int b = bh >> 3, h = bh & 7;
    int qbase = qhalf * 256 + wid * 32;

    // Q fragments resident
    const __half* Qg = g_Q + ((size_t)bh * S_ + qbase) * HD;
    unsigned qf[2][2][4];
#pragma unroll
    for (int mi = 0; mi < 2; mi++) {
        int r = mi * 16 + g;
#pragma unroll
        for (int ks = 0; ks < 2; ks++) {
            qf[mi][ks][0] = ldu32(&Qg[r * HD + ks * 16 + 2 * t]);
            qf[mi][ks][1] = ldu32(&Qg[(r + 8) * HD + ks * 16 + 2 * t]);
            qf[mi][ks][2] = ldu32(&Qg[r * HD + ks * 16 + 2 * t + 8]);
            qf[mi][ks][3] = ldu32(&Qg[(r + 8) * HD + ks * 16 + 2 * t + 8]);
        }
    }

    // static row-max bound: m_row = sum_d q'_d * maxK_d  (q' >= 0 => valid upper bound)
    float mrow[4];
    {
        const float* mk = g_maxkd + bh * 32;
        float m0[2] = {0.f, 0.f}, m1[2] = {0.f, 0.f};
#pragma unroll
        for (int ks = 0; ks < 2; ks++) {
            float2 mkA = *(const float2*)(mk + ks * 16 + 2 * t);
            float2 mkB = *(const float2*)(mk + ks * 16 + 2 * t + 8);
#pragma unroll
            for (int mi = 0; mi < 2; mi++) {
                float2 qa = __half22float2(*(__half2*)&qf[mi][ks][0]);
                float2 qb = __half22float2(*(__half2*)&qf[mi][ks][2]);
                float2 qc = __half22float2(*(__half2*)&qf[mi][ks][1]);
                float2 qd = __half22float2(*(__half2*)&qf[mi][ks][3]);
                m0[mi] += qa.x * mkA.x + qa.y * mkA.y + qb.x * mkB.x + qb.y * mkB.y;
                m1[mi] += qc.x * mkA.x + qc.y * mkA.y + qd.x * mkB.x + qd.y * mkB.y;
            }
        }
#pragma unroll
        for (int o = 1; o <= 2; o <<= 1) {
#pragma unroll
            for (int mi = 0; mi < 2; mi++) {
                m0[mi] += __shfl_xor_sync(0xffffffffu, m0[mi], o);
                m1[mi] += __shfl_xor_sync(0xffffffffu, m1[mi], o);
            }
        }
        mrow[0] = m0[0]; mrow[1] = m1[0]; mrow[2] = m0[1]; mrow[3] = m1[1];
    }

    float oacc[2][4][4];
#pragma unroll
    for (int mi = 0; mi < 2; mi++)
#pragma unroll
        for (int nd = 0; nd < 4; nd++)
#pragma unroll
            for (int c = 0; c < 4; c++) oacc[mi][nd][c] = 0.f;
    float lrow[4] = {0.f, 0.f, 0.f, 0.f};

    int mat = tid >> 7;
    int lrw = (tid >> 2) & 31;
    int c4  = tid & 3;
    const __half* Kg  = g_K  + (size_t)bh * S_ * HD;
    const __half* Vtg = g_Vt + (size_t)bh * HD * S_;
    uint32_t ksb = (uint32_t)__cvta_generic_to_shared(&Ks[0][0]);
    uint32_t vsb = (uint32_t)__cvta_generic_to_shared(&Vs[0][0]);

#define ASTAGE(kt_) do { \
    int _st = (kt_) % 3; \
    uint32_t _soff = (uint32_t)_st * (32 * ASTR * 2) + (uint32_t)lrw * (ASTR * 2) + (uint32_t)c4 * 16; \
    if (mat == 0) \
        cp16s(ksb + _soff, Kg + (size_t)((kt_) * 32 + lrw) * HD + c4 * 8); \
    else \
        cp16s(vsb + _soff, Vtg + (size_t)lrw * S_ + (kt_) * 32 + c4 * 8); \
} while (0)

    ASTAGE(0); CP_COMMIT();
    ASTAGE(1); CP_COMMIT();

    for (int kt = 0; kt < 16; kt++) {
        int buf = kt % 3;
        CP_WAIT1();
        __syncthreads();
        if (kt + 2 < 16) ASTAGE(kt + 2);
        CP_COMMIT();

        // ---- QK^T ----
        float sacc[2][4][4];
#pragma unroll
        for (int mi = 0; mi < 2; mi++)
#pragma unroll
            for (int ni = 0; ni < 4; ni++)
#pragma unroll
                for (int c = 0; c < 4; c++) sacc[mi][ni][c] = 0.f;

#pragma unroll
        for (int ks = 0; ks < 2; ks++) {
            unsigned kb[4][2];
#pragma unroll
            for (int ni = 0; ni < 4; ni++) {
                kb[ni][0] = ldu32(&Ks[buf][(ni * 8 + g) * ASTR + ks * 16 + 2 * t]);
                kb[ni][1] = ldu32(&Ks[buf][(ni * 8 + g) * ASTR + ks * 16 + 2 * t + 8]);
            }
#pragma unroll
            for (int mi = 0; mi < 2; mi++)
#pragma unroll
                for (int ni = 0; ni < 4; ni++)
                    mma_f16(sacc[mi][ni], qf[mi][ks], kb[ni]);
        }

        // ---- exp2 against static bound; accumulate l ----
#pragma unroll
        for (int r = 0; r < 4; r++) {
            int mi = r >> 1, cb = (r & 1) * 2;
            float m = mrow[r];
            float l = lrow[r];
#pragma unroll
            for (int ni = 0; ni < 4; ni++) {
                float p0 = ex2(sacc[mi][ni][cb] - m);
                float p1 = ex2(sacc[mi][ni][cb + 1] - m);
                l += p0 + p1;
                sacc[mi][ni][cb] = p0;
                sacc[mi][ni][cb + 1] = p1;
            }
            lrow[r] = l;
        }

        // ---- PV ----
#pragma unroll
        for (int ks = 0; ks < 2; ks++) {
            unsigned vb[4][2];
#pragma unroll
            for (int nd = 0; nd < 4; nd++) {
                vb[nd][0] = ldu32(&Vs[buf][(nd * 8 + g) * ASTR + ks * 16 + 2 * t]);
                vb[nd][1] = ldu32(&Vs[buf][(nd * 8 + g) * ASTR + ks * 16 + 2 * t + 8]);
            }
#pragma unroll
            for (int mi = 0; mi < 2; mi++) {
                unsigned pa_[4];
                pa_[0] = packh2(sacc[mi][2 * ks][0],     sacc[mi][2 * ks][1]);
                pa_[1] = packh2(sacc[mi][2 * ks][2],     sacc[mi][2 * ks][3]);
                pa_[2] = packh2(sacc[mi][2 * ks + 1][0], sacc[mi][2 * ks + 1][1]);
                pa_[3] = packh2(sacc[mi][2 * ks + 1][2], sacc[mi][2 * ks + 1][3]);
#pragma unroll
                for (int nd = 0; nd < 4; nd++)
                    mma_f16(oacc[mi][nd], pa_, vb[nd]);
            }
        }
    }
#undef ASTAGE

    // finalize
#pragma unroll
    for (int r = 0; r < 4; r++) {
        int mi = r >> 1, cb = (r & 1) * 2;
        float lt = lrow[r];
        lt += __shfl_xor_sync(0xffffffffu, lt, 1);
        lt += __shfl_xor_sync(0xffffffffu, lt, 2);
        float inv = 1.f / lt;
        int row = qbase + (r >> 1) * 16 + (r & 1) * 8 + g;
        __half* op = g_attn + ((size_t)b * S_ + row) * H_ + h * HD;
#pragma unroll
        for (int nd = 0; nd < 4; nd++) {
            *(__half2*)(op + nd * 8 + 2 * t) = __floats2half2_rn(
                oacc[mi][nd][cb] * inv, oacc[mi][nd][cb + 1] * inv);
        }
    }
}

// ---------------- launch ----------------
extern "C" void kernel_launch(void* const* d_in, const int* in_sizes, int n_in,
                              void* d_out, int out_size)
{
    const float* inputs = (const float*)d_in[0];
    const float* rmask  = (const float*)d_in[1];
    const float* w_in   = (const float*)d_in[2];
    const float* w_out  = (const float*)d_in[3];
    const float* gamma  = (const float*)d_in[4];
    const float* beta   = (const float*)d_in[5];
    float* out = (float*)d_out;

    const int gemm_smem = 4 * TILEH * (int)sizeof(__half);   // 73728 B
    cudaFuncSetAttribute(gemm_f16<1>, cudaFuncAttributeMaxDynamicSharedMemorySize, gemm_smem);
    cudaFuncSetAttribute(gemm_f16<2>, cudaFuncAttributeMaxDynamicSharedMemorySize, gemm_smem);

    conv_w<<<512, 256>>>(w_in, w_out);
    ln_kernel<<<M_ / 8, 256>>>(inputs, gamma, beta, rmask);
    gemm_f16<1><<<dim3(6, M_ / 128), 256, gemm_smem>>>(nullptr, nullptr);
    maxk_kernel<<<B_ * NH, 256>>>();
    attn_f16_kernel<<<512, 256>>>();
    gemm_f16<2><<<dim3(2, M_ / 128), 256, gemm_smem>>>(inputs, out);
}

// round 8
// speedup vs baseline: 6.3194x; 1.0597x over previous
#include <cuda_runtime.h>
#include <cuda_fp16.h>
#include <math.h>
#include <stdint.h>

// Problem dims (fixed)
#define B_   32
#define S_   512
#define H_   256
#define NH   8
#define HD   32
#define M_   (B_ * S_)     // 16384
#define TOT  (M_ * H_)

#define QK_SCALE_L2E 0.25505654440f     // (1/sqrt(32)) * log2(e)
#define RSQRT2       0.70710678118654752f
#define LN_EPS       1e-5f

// ---------------- scratch ----------------
__device__ __half g_normed[TOT];
__device__ __half g_wih[768 * 256];
__device__ __half g_woh[256 * 256];
__device__ __half g_Q[TOT];     // [b,h,s,d], (q*q+1e-6)*scale*log2e  (>= 0)
__device__ __half g_K[TOT];     // [b,h,s,d], + log(radial_mask)
__device__ __half g_Vt[TOT];    // [b,h,d,s]
__device__ __half g_attn[TOT];  // [b,s,H]
__device__ float    g_lr[M_];
__device__ unsigned g_maxkd[B_ * NH * HD];   // order-preserving float keys

// ---------------- helpers ----------------
__device__ __forceinline__ void mma_f16(float* d, const unsigned* a, const unsigned* b) {
    asm("mma.sync.aligned.m16n8k16.row.col.f32.f16.f16.f32 "
        "{%0,%1,%2,%3},{%4,%5,%6,%7},{%8,%9},{%0,%1,%2,%3};"
        : "+f"(d[0]), "+f"(d[1]), "+f"(d[2]), "+f"(d[3])
        : "r"(a[0]), "r"(a[1]), "r"(a[2]), "r"(a[3]), "r"(b[0]), "r"(b[1]));
}
__device__ __forceinline__ void ldsm4(unsigned* r, uint32_t addr) {
    asm volatile("ldmatrix.sync.aligned.m8n8.x4.shared.b16 {%0,%1,%2,%3}, [%4];"
        : "=r"(r[0]), "=r"(r[1]), "=r"(r[2]), "=r"(r[3]) : "r"(addr));
}
__device__ __forceinline__ unsigned packh2(float lo, float hi) {
    __half2 h = __floats2half2_rn(lo, hi);
    return *(unsigned*)&h;
}
__device__ __forceinline__ unsigned ldu32(const __half* p) {
    return *(const unsigned*)p;
}
__device__ __forceinline__ float ex2(float x) {
    float y;
    asm("ex2.approx.f32 %0, %1;" : "=f"(y) : "f"(x));
    return y;
}
__device__ __forceinline__ void cp16s(uint32_t saddr, const void* gptr) {
    asm volatile("cp.async.cg.shared.global [%0], [%1], 16;" :: "r"(saddr), "l"(gptr));
}
#define CP_COMMIT() asm volatile("cp.async.commit_group;")
#define CP_WAIT1()  asm volatile("cp.async.wait_group 1;")

// order-preserving float<->uint key (unsigned compare == float compare)
__device__ __forceinline__ unsigned fkey(float f) {
    unsigned b = __float_as_uint(f);
    return (b & 0x80000000u) ? ~b : (b | 0x80000000u);
}
__device__ __forceinline__ float funkey(unsigned k) {
    unsigned b = (k & 0x80000000u) ? (k & 0x7fffffffu) : ~k;
    return __uint_as_float(b);
}

// ---------------- weight conversion + maxk key init ----------------
__global__ __launch_bounds__(256) void conv_w(
    const float* __restrict__ wi, const float* __restrict__ wo)
{
    int i = blockIdx.x * 256 + threadIdx.x;
    if (i < B_ * NH * HD) g_maxkd[i] = 0u;
    const int N1 = 768 * 256 / 2;
    const int N2 = 256 * 256 / 2;
    if (i < N1) {
        float2 v = ((const float2*)wi)[i];
        ((__half2*)g_wih)[i] = __floats2half2_rn(v.x, v.y);
    } else if (i < N1 + N2) {
        int j = i - N1;
        float2 v = ((const float2*)wo)[j];
        ((__half2*)g_woh)[j] = __floats2half2_rn(v.x, v.y);
    }
}

// ---------------- LayerNorm (fp32 in -> fp16 out) ----------------
__global__ __launch_bounds__(256) void ln_kernel(
    const float* __restrict__ x, const float* __restrict__ gamma,
    const float* __restrict__ beta, const float* __restrict__ rmask)
{
    int warp = threadIdx.x >> 5, lane = threadIdx.x & 31;
    int row  = blockIdx.x * 8 + warp;
    const float2* xr = (const float2*)(x + row * H_);
    const float2* g2 = (const float2*)gamma;
    const float2* b2 = (const float2*)beta;

    float2 v[4];
    float sum = 0.f, sq = 0.f;
#pragma unroll
    for (int k = 0; k < 4; k++) {
        float2 t = xr[lane + 32 * k];
        v[k] = t;
        sum += t.x + t.y;
        sq  += t.x * t.x + t.y * t.y;
    }
#pragma unroll
    for (int o = 16; o > 0; o >>= 1) {
        sum += __shfl_xor_sync(0xffffffffu, sum, o);
        sq  += __shfl_xor_sync(0xffffffffu, sq,  o);
    }
    float mu = sum * (1.f / H_);
    float var = sq * (1.f / H_) - mu * mu;
    float rstd = rsqrtf(var + LN_EPS);

    __half2* nr = (__half2*)(g_normed + row * H_);
#pragma unroll
    for (int k = 0; k < 4; k++) {
        int idx = lane + 32 * k;
        float2 gv = g2[idx], bv = b2[idx];
        nr[idx] = __floats2half2_rn(
            (v[k].x - mu) * rstd * gv.x + bv.x,
            (v[k].y - mu) * rstd * gv.y + bv.y);
    }
    if (lane == 0) g_lr[row] = logf(rmask[row]);
}

// ---------------- fp16 MMA GEMM (NT), cp.async 2-stage, ldmatrix frags ----------------
#define SSTRH 72
#define TILEH (128 * SSTRH)

template <int MODE>
__global__ __launch_bounds__(256) void gemm_f16(
    const float* __restrict__ extra, float* __restrict__ C)
{
    extern __shared__ __half smh[];
    __half* As = smh;
    __half* Bs = smh + 2 * TILEH;

    const __half* A    = (MODE == 1) ? g_normed : g_attn;
    const __half* Bmat = (MODE == 1) ? g_wih : g_woh;
    const int K = 256;

    int tid = threadIdx.x;
    int wid = tid >> 5, lane = tid & 31;
    int g = lane >> 2, t = lane & 3;
    int wm = wid >> 2, wn = wid & 3;
    int brow = blockIdx.y, bcol = blockIdx.x;

    int c8  = tid & 7;
    int rwg = tid >> 3;

    // ldmatrix per-lane offsets
    int arow_lm = (lane & 7) + ((lane >> 3) & 1) * 8;   // A: m0/m1 rows, m2/m3 cols+8
    int acol_lm = (lane >> 4) * 8;
    int brow_lm = (lane & 7) + (lane >> 4) * 8;         // B: m0/m1 cols, m2/m3 rows+8
    int bcol_lm = ((lane >> 3) & 1) * 8;

    const __half* Agb = A    + (size_t)(brow * 128) * K;
    const __half* Bgb = Bmat + (size_t)(bcol * 128) * K;
    uint32_t asBase = (uint32_t)__cvta_generic_to_shared(As);
    uint32_t bsBase = (uint32_t)__cvta_generic_to_shared(Bs);

    float dacc[4][4][4];
#pragma unroll
    for (int i = 0; i < 4; i++)
#pragma unroll
        for (int j = 0; j < 4; j++)
#pragma unroll
            for (int c = 0; c < 4; c++) dacc[i][j][c] = 0.f;

#define STAGE(kt_) do { \
    int _kb = (kt_) * 64; \
    uint32_t _ab = asBase + ((kt_) & 1) * (TILEH * 2); \
    uint32_t _bb = bsBase + ((kt_) & 1) * (TILEH * 2); \
    _Pragma("unroll") \
    for (int _i = 0; _i < 4; _i++) { \
        int _row = rwg + _i * 32; \
        uint32_t _off = (uint32_t)_row * (SSTRH * 2) + (uint32_t)c8 * 16; \
        cp16s(_ab + _off, Agb + (size_t)_row * K + _kb + c8 * 8); \
        cp16s(_bb + _off, Bgb + (size_t)_row * K + _kb + c8 * 8); \
    } \
} while (0)

    STAGE(0); CP_COMMIT();
    STAGE(1); CP_COMMIT();

    for (int kt = 0; kt < 4; kt++) {
        CP_WAIT1();
        __syncthreads();

        uint32_t abuf = asBase + (kt & 1) * (TILEH * 2);
        uint32_t bbuf = bsBase + (kt & 1) * (TILEH * 2);
#pragma unroll
        for (int ks = 0; ks < 4; ks++) {
            unsigned af[4][4], bf[4][2];
#pragma unroll
            for (int mi = 0; mi < 4; mi++)
                ldsm4(af[mi], abuf + (uint32_t)((wm * 64 + mi * 16 + arow_lm) * SSTRH
                                               + ks * 16 + acol_lm) * 2);
#pragma unroll
            for (int nig = 0; nig < 2; nig++) {
                unsigned r[4];
                ldsm4(r, bbuf + (uint32_t)((wn * 32 + nig * 16 + brow_lm) * SSTRH
                                           + ks * 16 + bcol_lm) * 2);
                bf[nig * 2][0] = r[0]; bf[nig * 2][1] = r[1];
                bf[nig * 2 + 1][0] = r[2]; bf[nig * 2 + 1][1] = r[3];
            }
#pragma unroll
            for (int mi = 0; mi < 4; mi++)
#pragma unroll
                for (int ni = 0; ni < 4; ni++)
                    mma_f16(dacc[mi][ni], af[mi], bf[ni]);
        }
        __syncthreads();

        if (kt + 2 < 4) STAGE(kt + 2);
        CP_COMMIT();
    }
#undef STAGE

    if (MODE == 1) {
        int region = (bcol * 128) >> 8;
        int hh = ((bcol & 1) << 2) + wn;
        float cmax[4][2];
#pragma unroll
        for (int ni = 0; ni < 4; ni++) { cmax[ni][0] = -1e30f; cmax[ni][1] = -1e30f; }

#pragma unroll
        for (int mi = 0; mi < 4; mi++) {
            int r0 = brow * 128 + wm * 64 + mi * 16 + g;
            int r1 = r0 + 8;
            int b = r0 >> 9, s0 = r0 & 511, s1 = r1 & 511;
            if (region == 2) {
                __half* vt = g_Vt + (size_t)(b * 8 + hh) * HD * S_;
#pragma unroll
                for (int ni = 0; ni < 4; ni++) {
                    int d0 = ni * 8 + 2 * t, d1 = d0 + 1;
                    vt[d0 * S_ + s0] = __float2half_rn(dacc[mi][ni][0]);
                    vt[d1 * S_ + s0] = __float2half_rn(dacc[mi][ni][1]);
                    vt[d0 * S_ + s1] = __float2half_rn(dacc[mi][ni][2]);
                    vt[d1 * S_ + s1] = __float2half_rn(dacc[mi][ni][3]);
                }
            } else {
                __half* dst = (region == 0) ? g_Q : g_K;
                float lr0 = (region == 1) ? g_lr[r0] : 0.f;
                float lr1 = (region == 1) ? g_lr[r1] : 0.f;
                __half* p0 = dst + ((size_t)(b * 8 + hh) * S_ + s0) * HD;
                __half* p1 = dst + ((size_t)(b * 8 + hh) * S_ + s1) * HD;
#pragma unroll
                for (int ni = 0; ni < 4; ni++) {
                    int dcol = ni * 8 + 2 * t;
                    float v0 = dacc[mi][ni][0], v1 = dacc[mi][ni][1];
                    float v2 = dacc[mi][ni][2], v3 = dacc[mi][ni][3];
                    if (region == 0) {
                        v0 = (v0 * v0 + 1e-6f) * QK_SCALE_L2E;
                        v1 = (v1 * v1 + 1e-6f) * QK_SCALE_L2E;
                        v2 = (v2 * v2 + 1e-6f) * QK_SCALE_L2E;
                        v3 = (v3 * v3 + 1e-6f) * QK_SCALE_L2E;
                    } else {
                        v0 += lr0; v1 += lr0; v2 += lr1; v3 += lr1;
                        cmax[ni][0] = fmaxf(cmax[ni][0], fmaxf(v0, v2));
                        cmax[ni][1] = fmaxf(cmax[ni][1], fmaxf(v1, v3));
                    }
                    *(__half2*)(p0 + dcol) = __floats2half2_rn(v0, v1);
                    *(__half2*)(p1 + dcol) = __floats2half2_rn(v2, v3);
                }
            }
        }

        if (region == 1) {
            // reduce over the 8 row-groups (g), then atomic-max per (b,h,d)
#pragma unroll
            for (int ni = 0; ni < 4; ni++) {
#pragma unroll
                for (int o = 4; o <= 16; o <<= 1) {
                    cmax[ni][0] = fmaxf(cmax[ni][0], __shfl_xor_sync(0xffffffffu, cmax[ni][0], o));
                    cmax[ni][1] = fmaxf(cmax[ni][1], __shfl_xor_sync(0xffffffffu, cmax[ni][1], o));
                }
            }
            if (g == 0) {
                int b = brow >> 2;
                unsigned* mk = g_maxkd + (size_t)(b * 8 + hh) * HD;
#pragma unroll
                for (int ni = 0; ni < 4; ni++) {
                    atomicMax(&mk[ni * 8 + 2 * t],     fkey(cmax[ni][0]));
                    atomicMax(&mk[ni * 8 + 2 * t + 1], fkey(cmax[ni][1]));
                }
            }
        }
    } else {
#pragma unroll
        for (int mi = 0; mi < 4; mi++) {
            int r0 = brow * 128 + wm * 64 + mi * 16 + g;
            int r1 = r0 + 8;
            int cbase = bcol * 128 + wn * 32;
            const float* in0 = extra + (size_t)r0 * H_ + cbase;
            const float* in1 = extra + (size_t)r1 * H_ + cbase;
            float* o0 = C + (size_t)r0 * H_ + cbase;
            float* o1 = C + (size_t)r1 * H_ + cbase;
#pragma unroll
            for (int ni = 0; ni < 4; ni++) {
                int dcol = ni * 8 + 2 * t;
                float2 i0 = *(const float2*)(in0 + dcol);
                float2 i1 = *(const float2*)(in1 + dcol);
                *(float2*)(o0 + dcol) = make_float2(
                    (dacc[mi][ni][0] + i0.x) * RSQRT2, (dacc[mi][ni][1] + i0.y) * RSQRT2);
                *(float2*)(o1 + dcol) = make_float2(
                    (dacc[mi][ni][2] + i1.x) * RSQRT2, (dacc[mi][ni][3] + i1.y) * RSQRT2);
            }
        }
    }
}

// ---------------- attention: fp16 mma, static bound, ldmatrix frags ----------------
#define ASTR 40

__global__ __launch_bounds__(256) void attn_f16_kernel()
{
    __shared__ __half Ks[3][32 * ASTR];
    __shared__ __half Vs[3][32 * ASTR];

    int tid = threadIdx.x;
    int wid = tid >> 5, lane = tid & 31;
    int g = lane >> 2, t = lane & 3;
    int qhalf = blockIdx.x & 1, bh = blockIdx.x >> 1;
    int b = bh >> 3, h = bh & 7;
    int qbase = qhalf * 256 + wid * 32;

    int brow_lm = (lane & 7) + (lane >> 4) * 8;
    int bcol_lm = ((lane >> 3) & 1) * 8;

    // Q fragments resident
    const __half* Qg = g_Q + ((size_t)bh * S_ + qbase) * HD;
    unsigned qf[2][2][4];
#pragma unroll
    for (int mi = 0; mi < 2; mi++) {
        int r = mi * 16 + g;
#pragma unroll
        for (int ks = 0; ks < 2; ks++) {
            qf[mi][ks][0] = ldu32(&Qg[r * HD + ks * 16 + 2 * t]);
            qf[mi][ks][1] = ldu32(&Qg[(r + 8) * HD + ks * 16 + 2 * t]);
            qf[mi][ks][2] = ldu32(&Qg[r * HD + ks * 16 + 2 * t + 8]);
            qf[mi][ks][3] = ldu32(&Qg[(r + 8) * HD + ks * 16 + 2 * t + 8]);
        }
    }

    // static row-max bound from fused per-dim K maxima
    float mrow[4];
    {
        const unsigned* mku = g_maxkd + bh * HD;
        float m0[2] = {0.f, 0.f}, m1[2] = {0.f, 0.f};
#pragma unroll
        for (int ks = 0; ks < 2; ks++) {
            float mkA0 = funkey(mku[ks * 16 + 2 * t]);
            float mkA1 = funkey(mku[ks * 16 + 2 * t + 1]);
            float mkB0 = funkey(mku[ks * 16 + 2 * t + 8]);
            float mkB1 = funkey(mku[ks * 16 + 2 * t + 9]);
#pragma unroll
            for (int mi = 0; mi < 2; mi++) {
                float2 qa = __half22float2(*(__half2*)&qf[mi][ks][0]);
                float2 qb = __half22float2(*(__half2*)&qf[mi][ks][2]);
                float2 qc = __half22float2(*(__half2*)&qf[mi][ks][1]);
                float2 qd = __half22float2(*(__half2*)&qf[mi][ks][3]);
                m0[mi] += qa.x * mkA0 + qa.y * mkA1 + qb.x * mkB0 + qb.y * mkB1;
                m1[mi] += qc.x * mkA0 + qc.y * mkA1 + qd.x * mkB0 + qd.y * mkB1;
            }
        }
#pragma unroll
        for (int o = 1; o <= 2; o <<= 1) {
#pragma unroll
            for (int mi = 0; mi < 2; mi++) {
                m0[mi] += __shfl_xor_sync(0xffffffffu, m0[mi], o);
                m1[mi] += __shfl_xor_sync(0xffffffffu, m1[mi], o);
            }
        }
        mrow[0] = m0[0]; mrow[1] = m1[0]; mrow[2] = m0[1]; mrow[3] = m1[1];
    }

    float oacc[2][4][4];
#pragma unroll
    for (int mi = 0; mi < 2; mi++)
#pragma unroll
        for (int nd = 0; nd < 4; nd++)
#pragma unroll
            for (int c = 0; c < 4; c++) oacc[mi][nd][c] = 0.f;
    float lrow[4] = {0.f, 0.f, 0.f, 0.f};

    int mat = tid >> 7;
    int lrw = (tid >> 2) & 31;
    int c4  = tid & 3;
    const __half* Kg  = g_K  + (size_t)bh * S_ * HD;
    const __half* Vtg = g_Vt + (size_t)bh * HD * S_;
    uint32_t ksb = (uint32_t)__cvta_generic_to_shared(&Ks[0][0]);
    uint32_t vsb = (uint32_t)__cvta_generic_to_shared(&Vs[0][0]);

#define ASTAGE(kt_) do { \
    int _st = (kt_) % 3; \
    uint32_t _soff = (uint32_t)_st * (32 * ASTR * 2) + (uint32_t)lrw * (ASTR * 2) + (uint32_t)c4 * 16; \
    if (mat == 0) \
        cp16s(ksb + _soff, Kg + (size_t)((kt_) * 32 + lrw) * HD + c4 * 8); \
    else \
        cp16s(vsb + _soff, Vtg + (size_t)lrw * S_ + (kt_) * 32 + c4 * 8); \
} while (0)

    ASTAGE(0); CP_COMMIT();
    ASTAGE(1); CP_COMMIT();

    for (int kt = 0; kt < 16; kt++) {
        int buf = kt % 3;
        CP_WAIT1();
        __syncthreads();
        if (kt + 2 < 16) ASTAGE(kt + 2);
        CP_COMMIT();

        uint32_t kbuf = ksb + (uint32_t)buf * (32 * ASTR * 2);
        uint32_t vbuf = vsb + (uint32_t)buf * (32 * ASTR * 2);

        // ---- QK^T ----
        float sacc[2][4][4];
#pragma unroll
        for (int mi = 0; mi < 2; mi++)
#pragma unroll
            for (int ni = 0; ni < 4; ni++)
#pragma unroll
                for (int c = 0; c < 4; c++) sacc[mi][ni][c] = 0.f;

#pragma unroll
        for (int ks = 0; ks < 2; ks++) {
            unsigned kb[4][2];
#pragma unroll
            for (int nig = 0; nig < 2; nig++) {
                unsigned r[4];
                ldsm4(r, kbuf + (uint32_t)((nig * 16 + brow_lm) * ASTR + ks * 16 + bcol_lm) * 2);
                kb[nig * 2][0] = r[0]; kb[nig * 2][1] = r[1];
                kb[nig * 2 + 1][0] = r[2]; kb[nig * 2 + 1][1] = r[3];
            }
#pragma unroll
            for (int mi = 0; mi < 2; mi++)
#pragma unroll
                for (int ni = 0; ni < 4; ni++)
                    mma_f16(sacc[mi][ni], qf[mi][ks], kb[ni]);
        }

        // ---- exp2 against static bound ----
#pragma unroll
        for (int r = 0; r < 4; r++) {
            int mi = r >> 1, cb = (r & 1) * 2;
            float m = mrow[r];
            float l = lrow[r];
#pragma unroll
            for (int ni = 0; ni < 4; ni++) {
                float p0 = ex2(sacc[mi][ni][cb] - m);
                float p1 = ex2(sacc[mi][ni][cb + 1] - m);
                l += p0 + p1;
                sacc[mi][ni][cb] = p0;
                sacc[mi][ni][cb + 1] = p1;
            }
            lrow[r] = l;
        }

        // ---- PV ----
#pragma unroll
        for (int ks = 0; ks < 2; ks++) {
            unsigned vb[4][2];
#pragma unroll
            for (int nig = 0; nig < 2; nig++) {
                unsigned r[4];
                ldsm4(r, vbuf + (uint32_t)((nig * 16 + brow_lm) * ASTR + ks * 16 + bcol_lm) * 2);
                vb[nig * 2][0] = r[0]; vb[nig * 2][1] = r[1];
                vb[nig * 2 + 1][0] = r[2]; vb[nig * 2 + 1][1] = r[3];
            }
#pragma unroll
            for (int mi = 0; mi < 2; mi++) {
                unsigned pa_[4];
                pa_[0] = packh2(sacc[mi][2 * ks][0],     sacc[mi][2 * ks][1]);
                pa_[1] = packh2(sacc[mi][2 * ks][2],     sacc[mi][2 * ks][3]);
                pa_[2] = packh2(sacc[mi][2 * ks + 1][0], sacc[mi][2 * ks + 1][1]);
                pa_[3] = packh2(sacc[mi][2 * ks + 1][2], sacc[mi][2 * ks + 1][3]);
#pragma unroll
                for (int nd = 0; nd < 4; nd++)
                    mma_f16(oacc[mi][nd], pa_, vb[nd]);
            }
        }
    }
#undef ASTAGE

    // finalize
#pragma unroll
    for (int r = 0; r < 4; r++) {
        int mi = r >> 1, cb = (r & 1) * 2;
        float lt = lrow[r];
        lt += __shfl_xor_sync(0xffffffffu, lt, 1);
        lt += __shfl_xor_sync(0xffffffffu, lt, 2);
        float inv = 1.f / lt;
        int row = qbase + (r >> 1) * 16 + (r & 1) * 8 + g;
        __half* op = g_attn + ((size_t)b * S_ + row) * H_ + h * HD;
#pragma unroll
        for (int nd = 0; nd < 4; nd++) {
            *(__half2*)(op + nd * 8 + 2 * t) = __floats2half2_rn(
                oacc[mi][nd][cb] * inv, oacc[mi][nd][cb + 1] * inv);
        }
    }
}

// ---------------- launch ----------------
extern "C" void kernel_launch(void* const* d_in, const int* in_sizes, int n_in,
                              void* d_out, int out_size)
{
    const float* inputs = (const float*)d_in[0];
    const float* rmask  = (const float*)d_in[1];
    const float* w_in   = (const float*)d_in[2];
    const float* w_out  = (const float*)d_in[3];
    const float* gamma  = (const float*)d_in[4];
    const float* beta   = (const float*)d_in[5];
    float* out = (float*)d_out;

    const int gemm_smem = 4 * TILEH * (int)sizeof(__half);   // 73728 B
    cudaFuncSetAttribute(gemm_f16<1>, cudaFuncAttributeMaxDynamicSharedMemorySize, gemm_smem);
    cudaFuncSetAttribute(gemm_f16<2>, cudaFuncAttributeMaxDynamicSharedMemorySize, gemm_smem);

    conv_w<<<512, 256>>>(w_in, w_out);
    ln_kernel<<<M_ / 8, 256>>>(inputs, gamma, beta, rmask);
    gemm_f16<1><<<dim3(6, M_ / 128), 256, gemm_smem>>>(nullptr, nullptr);
    attn_f16_kernel<<<512, 256>>>();
    gemm_f16<2><<<dim3(2, M_ / 128), 256, gemm_smem>>>(inputs, out);
}

// round 9
// speedup vs baseline: 6.8966x; 1.0913x over previous
#include <cuda_runtime.h>
#include <cuda_fp16.h>
#include <math.h>
#include <stdint.h>

// Problem dims (fixed)
#define B_   32
#define S_   512
#define H_   256
#define NH   8
#define HD   32
#define M_   (B_ * S_)     // 16384
#define TOT  (M_ * H_)

#define QK_SCALE_L2E 0.25505654440f     // (1/sqrt(32)) * log2(e)
#define RSQRT2       0.70710678118654752f
#define LN_EPS       1e-5f

// ---------------- scratch ----------------
__device__ __half g_normed[TOT];
__device__ __half g_wih[768 * 256];
__device__ __half g_woh[256 * 256];
__device__ __half g_Q[TOT];     // [b,h,s,d], (q*q+1e-6)*scale*log2e  (>= 0)
__device__ __half g_K[TOT];     // [b,h,s,d], + log(radial_mask)
__device__ __half g_Vt[TOT];    // [b,h,d,s]
__device__ __half g_attn[TOT];  // [b,s,H]
__device__ float    g_lr[M_];
__device__ unsigned g_maxkd[B_ * NH * HD];   // order-preserving float keys

// ---------------- helpers ----------------
__device__ __forceinline__ void mma_f16(float* d, const unsigned* a, const unsigned* b) {
    asm("mma.sync.aligned.m16n8k16.row.col.f32.f16.f16.f32 "
        "{%0,%1,%2,%3},{%4,%5,%6,%7},{%8,%9},{%0,%1,%2,%3};"
        : "+f"(d[0]), "+f"(d[1]), "+f"(d[2]), "+f"(d[3])
        : "r"(a[0]), "r"(a[1]), "r"(a[2]), "r"(a[3]), "r"(b[0]), "r"(b[1]));
}
__device__ __forceinline__ void ldsm4(unsigned* r, uint32_t addr) {
    asm volatile("ldmatrix.sync.aligned.m8n8.x4.shared.b16 {%0,%1,%2,%3}, [%4];"
        : "=r"(r[0]), "=r"(r[1]), "=r"(r[2]), "=r"(r[3]) : "r"(addr));
}
__device__ __forceinline__ unsigned packh2(float lo, float hi) {
    __half2 h = __floats2half2_rn(lo, hi);
    return *(unsigned*)&h;
}
__device__ __forceinline__ unsigned ex2h2(unsigned x) {
    unsigned y;
    asm("ex2.approx.f16x2 %0, %1;" : "=r"(y) : "r"(x));
    return y;
}
__device__ __forceinline__ unsigned ldu32(const __half* p) {
    return *(const unsigned*)p;
}
__device__ __forceinline__ void cp16s(uint32_t saddr, const void* gptr) {
    asm volatile("cp.async.cg.shared.global [%0], [%1], 16;" :: "r"(saddr), "l"(gptr));
}
#define CP_COMMIT() asm volatile("cp.async.commit_group;")
#define CP_WAIT1()  asm volatile("cp.async.wait_group 1;")

// order-preserving float<->uint key
__device__ __forceinline__ unsigned fkey(float f) {
    unsigned b = __float_as_uint(f);
    return (b & 0x80000000u) ? ~b : (b | 0x80000000u);
}
__device__ __forceinline__ float funkey(unsigned k) {
    unsigned b = (k & 0x80000000u) ? (k & 0x7fffffffu) : ~k;
    return __uint_as_float(b);
}

// ---------------- weight conversion + maxk key init ----------------
__global__ __launch_bounds__(256) void conv_w(
    const float* __restrict__ wi, const float* __restrict__ wo)
{
    int i = blockIdx.x * 256 + threadIdx.x;
    if (i < B_ * NH * HD) g_maxkd[i] = 0u;
    const int N1 = 768 * 256 / 2;
    const int N2 = 256 * 256 / 2;
    if (i < N1) {
        float2 v = ((const float2*)wi)[i];
        ((__half2*)g_wih)[i] = __floats2half2_rn(v.x, v.y);
    } else if (i < N1 + N2) {
        int j = i - N1;
        float2 v = ((const float2*)wo)[j];
        ((__half2*)g_woh)[j] = __floats2half2_rn(v.x, v.y);
    }
}

// ---------------- LayerNorm (fp32 in -> fp16 out) ----------------
__global__ __launch_bounds__(256) void ln_kernel(
    const float* __restrict__ x, const float* __restrict__ gamma,
    const float* __restrict__ beta, const float* __restrict__ rmask)
{
    int warp = threadIdx.x >> 5, lane = threadIdx.x & 31;
    int row  = blockIdx.x * 8 + warp;
    const float2* xr = (const float2*)(x + row * H_);
    const float2* g2 = (const float2*)gamma;
    const float2* b2 = (const float2*)beta;

    float2 v[4];
    float sum = 0.f, sq = 0.f;
#pragma unroll
    for (int k = 0; k < 4; k++) {
        float2 t = xr[lane + 32 * k];
        v[k] = t;
        sum += t.x + t.y;
        sq  += t.x * t.x + t.y * t.y;
    }
#pragma unroll
    for (int o = 16; o > 0; o >>= 1) {
        sum += __shfl_xor_sync(0xffffffffu, sum, o);
        sq  += __shfl_xor_sync(0xffffffffu, sq,  o);
    }
    float mu = sum * (1.f / H_);
    float var = sq * (1.f / H_) - mu * mu;
    float rstd = rsqrtf(var + LN_EPS);

    __half2* nr = (__half2*)(g_normed + row * H_);
#pragma unroll
    for (int k = 0; k < 4; k++) {
        int idx = lane + 32 * k;
        float2 gv = g2[idx], bv = b2[idx];
        nr[idx] = __floats2half2_rn(
            (v[k].x - mu) * rstd * gv.x + bv.x,
            (v[k].y - mu) * rstd * gv.y + bv.y);
    }
    if (lane == 0) g_lr[row] = logf(rmask[row]);
}

// ---------------- fp16 MMA GEMM (NT), cp.async 2-stage, ldmatrix frags ----------------
#define SSTRH 72
#define TILEH (128 * SSTRH)

template <int MODE>
__global__ __launch_bounds__(256) void gemm_f16(
    const float* __restrict__ extra, float* __restrict__ C)
{
    extern __shared__ __half smh[];
    __half* As = smh;
    __half* Bs = smh + 2 * TILEH;

    const __half* A    = (MODE == 1) ? g_normed : g_attn;
    const __half* Bmat = (MODE == 1) ? g_wih : g_woh;
    const int K = 256;

    int tid = threadIdx.x;
    int wid = tid >> 5, lane = tid & 31;
    int g = lane >> 2, t = lane & 3;
    int wm = wid >> 2, wn = wid & 3;
    int brow = blockIdx.y, bcol = blockIdx.x;

    int c8  = tid & 7;
    int rwg = tid >> 3;

    int arow_lm = (lane & 7) + ((lane >> 3) & 1) * 8;
    int acol_lm = (lane >> 4) * 8;
    int brow_lm = (lane & 7) + (lane >> 4) * 8;
    int bcol_lm = ((lane >> 3) & 1) * 8;

    const __half* Agb = A    + (size_t)(brow * 128) * K;
    const __half* Bgb = Bmat + (size_t)(bcol * 128) * K;
    uint32_t asBase = (uint32_t)__cvta_generic_to_shared(As);
    uint32_t bsBase = (uint32_t)__cvta_generic_to_shared(Bs);

    float dacc[4][4][4];
#pragma unroll
    for (int i = 0; i < 4; i++)
#pragma unroll
        for (int j = 0; j < 4; j++)
#pragma unroll
            for (int c = 0; c < 4; c++) dacc[i][j][c] = 0.f;

#define STAGE(kt_) do { \
    int _kb = (kt_) * 64; \
    uint32_t _ab = asBase + ((kt_) & 1) * (TILEH * 2); \
    uint32_t _bb = bsBase + ((kt_) & 1) * (TILEH * 2); \
    _Pragma("unroll") \
    for (int _i = 0; _i < 4; _i++) { \
        int _row = rwg + _i * 32; \
        uint32_t _off = (uint32_t)_row * (SSTRH * 2) + (uint32_t)c8 * 16; \
        cp16s(_ab + _off, Agb + (size_t)_row * K + _kb + c8 * 8); \
        cp16s(_bb + _off, Bgb + (size_t)_row * K + _kb + c8 * 8); \
    } \
} while (0)

    STAGE(0); CP_COMMIT();
    STAGE(1); CP_COMMIT();

    for (int kt = 0; kt < 4; kt++) {
        CP_WAIT1();
        __syncthreads();

        uint32_t abuf = asBase + (kt & 1) * (TILEH * 2);
        uint32_t bbuf = bsBase + (kt & 1) * (TILEH * 2);
#pragma unroll
        for (int ks = 0; ks < 4; ks++) {
            unsigned af[4][4], bf[4][2];
#pragma unroll
            for (int mi = 0; mi < 4; mi++)
                ldsm4(af[mi], abuf + (uint32_t)((wm * 64 + mi * 16 + arow_lm) * SSTRH
                                               + ks * 16 + acol_lm) * 2);
#pragma unroll
            for (int nig = 0; nig < 2; nig++) {
                unsigned r[4];
                ldsm4(r, bbuf + (uint32_t)((wn * 32 + nig * 16 + brow_lm) * SSTRH
                                           + ks * 16 + bcol_lm) * 2);
                bf[nig * 2][0] = r[0]; bf[nig * 2][1] = r[1];
                bf[nig * 2 + 1][0] = r[2]; bf[nig * 2 + 1][1] = r[3];
            }
#pragma unroll
            for (int mi = 0; mi < 4; mi++)
#pragma unroll
                for (int ni = 0; ni < 4; ni++)
                    mma_f16(dacc[mi][ni], af[mi], bf[ni]);
        }
        __syncthreads();

        if (kt + 2 < 4) STAGE(kt + 2);
        CP_COMMIT();
    }
#undef STAGE

    if (MODE == 1) {
        int region = (bcol * 128) >> 8;
        int hh = ((bcol & 1) << 2) + wn;
        float cmax[4][2];
#pragma unroll
        for (int ni = 0; ni < 4; ni++) { cmax[ni][0] = -1e30f; cmax[ni][1] = -1e30f; }

#pragma unroll
        for (int mi = 0; mi < 4; mi++) {
            int r0 = brow * 128 + wm * 64 + mi * 16 + g;
            int r1 = r0 + 8;
            int b = r0 >> 9, s0 = r0 & 511, s1 = r1 & 511;
            if (region == 2) {
                __half* vt = g_Vt + (size_t)(b * 8 + hh) * HD * S_;
#pragma unroll
                for (int ni = 0; ni < 4; ni++) {
                    int d0 = ni * 8 + 2 * t, d1 = d0 + 1;
                    vt[d0 * S_ + s0] = __float2half_rn(dacc[mi][ni][0]);
                    vt[d1 * S_ + s0] = __float2half_rn(dacc[mi][ni][1]);
                    vt[d0 * S_ + s1] = __float2half_rn(dacc[mi][ni][2]);
                    vt[d1 * S_ + s1] = __float2half_rn(dacc[mi][ni][3]);
                }
            } else {
                __half* dst = (region == 0) ? g_Q : g_K;
                float lr0 = (region == 1) ? g_lr[r0] : 0.f;
                float lr1 = (region == 1) ? g_lr[r1] : 0.f;
                __half* p0 = dst + ((size_t)(b * 8 + hh) * S_ + s0) * HD;
                __half* p1 = dst + ((size_t)(b * 8 + hh) * S_ + s1) * HD;
#pragma unroll
                for (int ni = 0; ni < 4; ni++) {
                    int dcol = ni * 8 + 2 * t;
                    float v0 = dacc[mi][ni][0], v1 = dacc[mi][ni][1];
                    float v2 = dacc[mi][ni][2], v3 = dacc[mi][ni][3];
                    if (region == 0) {
                        v0 = (v0 * v0 + 1e-6f) * QK_SCALE_L2E;
                        v1 = (v1 * v1 + 1e-6f) * QK_SCALE_L2E;
                        v2 = (v2 * v2 + 1e-6f) * QK_SCALE_L2E;
                        v3 = (v3 * v3 + 1e-6f) * QK_SCALE_L2E;
                    } else {
                        v0 += lr0; v1 += lr0; v2 += lr1; v3 += lr1;
                        cmax[ni][0] = fmaxf(cmax[ni][0], fmaxf(v0, v2));
                        cmax[ni][1] = fmaxf(cmax[ni][1], fmaxf(v1, v3));
                    }
                    *(__half2*)(p0 + dcol) = __floats2half2_rn(v0, v1);
                    *(__half2*)(p1 + dcol) = __floats2half2_rn(v2, v3);
                }
            }
        }

        if (region == 1) {
#pragma unroll
            for (int ni = 0; ni < 4; ni++) {
#pragma unroll
                for (int o = 4; o <= 16; o <<= 1) {
                    cmax[ni][0] = fmaxf(cmax[ni][0], __shfl_xor_sync(0xffffffffu, cmax[ni][0], o));
                    cmax[ni][1] = fmaxf(cmax[ni][1], __shfl_xor_sync(0xffffffffu, cmax[ni][1], o));
                }
            }
            if (g == 0) {
                int b = brow >> 2;
                unsigned* mk = g_maxkd + (size_t)(b * 8 + hh) * HD;
#pragma unroll
                for (int ni = 0; ni < 4; ni++) {
                    atomicMax(&mk[ni * 8 + 2 * t],     fkey(cmax[ni][0]));
                    atomicMax(&mk[ni * 8 + 2 * t + 1], fkey(cmax[ni][1]));
                }
            }
        }
    } else {
#pragma unroll
        for (int mi = 0; mi < 4; mi++) {
            int r0 = brow * 128 + wm * 64 + mi * 16 + g;
            int r1 = r0 + 8;
            int cbase = bcol * 128 + wn * 32;
            const float* in0 = extra + (size_t)r0 * H_ + cbase;
            const float* in1 = extra + (size_t)r1 * H_ + cbase;
            float* o0 = C + (size_t)r0 * H_ + cbase;
            float* o1 = C + (size_t)r1 * H_ + cbase;
#pragma unroll
            for (int ni = 0; ni < 4; ni++) {
                int dcol = ni * 8 + 2 * t;
                float2 i0 = *(const float2*)(in0 + dcol);
                float2 i1 = *(const float2*)(in1 + dcol);
                *(float2*)(o0 + dcol) = make_float2(
                    (dacc[mi][ni][0] + i0.x) * RSQRT2, (dacc[mi][ni][1] + i0.y) * RSQRT2);
                *(float2*)(o1 + dcol) = make_float2(
                    (dacc[mi][ni][2] + i1.x) * RSQRT2, (dacc[mi][ni][3] + i1.y) * RSQRT2);
            }
        }
    }
}

// ---------------- attention: fp16 mma, static bound folded into acc-init,
// ---------------- f16x2 exp, l via ones-mma ----------------
#define ASTR 40

__global__ __launch_bounds__(256) void attn_f16_kernel()
{
    __shared__ __half Ks[3][32 * ASTR];
    __shared__ __half Vs[3][32 * ASTR];

    int tid = threadIdx.x;
    int wid = tid >> 5, lane = tid & 31;
    int g = lane >> 2, t = lane & 3;
    int qhalf = blockIdx.x & 1, bh = blockIdx.x >> 1;
    int b = bh >> 3, h = bh & 7;
    int qbase = qhalf * 256 + wid * 32;

    int brow_lm = (lane & 7) + (lane >> 4) * 8;
    int bcol_lm = ((lane >> 3) & 1) * 8;

    // Q fragments resident
    const __half* Qg = g_Q + ((size_t)bh * S_ + qbase) * HD;
    unsigned qf[2][2][4];
#pragma unroll
    for (int mi = 0; mi < 2; mi++) {
        int r = mi * 16 + g;
#pragma unroll
        for (int ks = 0; ks < 2; ks++) {
            qf[mi][ks][0] = ldu32(&Qg[r * HD + ks * 16 + 2 * t]);
            qf[mi][ks][1] = ldu32(&Qg[(r + 8) * HD + ks * 16 + 2 * t]);
            qf[mi][ks][2] = ldu32(&Qg[r * HD + ks * 16 + 2 * t + 8]);
            qf[mi][ks][3] = ldu32(&Qg[(r + 8) * HD + ks * 16 + 2 * t + 8]);
        }
    }

    // static row-max bound
    float mrow[4];
    {
        const unsigned* mku = g_maxkd + bh * HD;
        float m0[2] = {0.f, 0.f}, m1[2] = {0.f, 0.f};
#pragma unroll
        for (int ks = 0; ks < 2; ks++) {
            float mkA0 = funkey(mku[ks * 16 + 2 * t]);
            float mkA1 = funkey(mku[ks * 16 + 2 * t + 1]);
            float mkB0 = funkey(mku[ks * 16 + 2 * t + 8]);
            float mkB1 = funkey(mku[ks * 16 + 2 * t + 9]);
#pragma unroll
            for (int mi = 0; mi < 2; mi++) {
                float2 qa = __half22float2(*(__half2*)&qf[mi][ks][0]);
                float2 qb = __half22float2(*(__half2*)&qf[mi][ks][2]);
                float2 qc = __half22float2(*(__half2*)&qf[mi][ks][1]);
                float2 qd = __half22float2(*(__half2*)&qf[mi][ks][3]);
                m0[mi] += qa.x * mkA0 + qa.y * mkA1 + qb.x * mkB0 + qb.y * mkB1;
                m1[mi] += qc.x * mkA0 + qc.y * mkA1 + qd.x * mkB0 + qd.y * mkB1;
            }
        }
#pragma unroll
        for (int o = 1; o <= 2; o <<= 1) {
#pragma unroll
            for (int mi = 0; mi < 2; mi++) {
                m0[mi] += __shfl_xor_sync(0xffffffffu, m0[mi], o);
                m1[mi] += __shfl_xor_sync(0xffffffffu, m1[mi], o);
            }
        }
        mrow[0] = m0[0]; mrow[1] = m1[0]; mrow[2] = m0[1]; mrow[3] = m1[1];
    }

    float oacc[2][4][4];
#pragma unroll
    for (int mi = 0; mi < 2; mi++)
#pragma unroll
        for (int nd = 0; nd < 4; nd++)
#pragma unroll
            for (int c = 0; c < 4; c++) oacc[mi][nd][c] = 0.f;
    float lacc[2][4];
#pragma unroll
    for (int mi = 0; mi < 2; mi++)
#pragma unroll
        for (int c = 0; c < 4; c++) lacc[mi][c] = 0.f;

    const unsigned ONES2[2] = {0x3C003C00u, 0x3C003C00u};   // half2(1,1)

    int mat = tid >> 7;
    int lrw = (tid >> 2) & 31;
    int c4  = tid & 3;
    const __half* Kg  = g_K  + (size_t)bh * S_ * HD;
    const __half* Vtg = g_Vt + (size_t)bh * HD * S_;
    uint32_t ksb = (uint32_t)__cvta_generic_to_shared(&Ks[0][0]);
    uint32_t vsb = (uint32_t)__cvta_generic_to_shared(&Vs[0][0]);

#define ASTAGE(kt_) do { \
    int _st = (kt_) % 3; \
    uint32_t _soff = (uint32_t)_st * (32 * ASTR * 2) + (uint32_t)lrw * (ASTR * 2) + (uint32_t)c4 * 16; \
    if (mat == 0) \
        cp16s(ksb + _soff, Kg + (size_t)((kt_) * 32 + lrw) * HD + c4 * 8); \
    else \
        cp16s(vsb + _soff, Vtg + (size_t)lrw * S_ + (kt_) * 32 + c4 * 8); \
} while (0)

    ASTAGE(0); CP_COMMIT();
    ASTAGE(1); CP_COMMIT();

    for (int kt = 0; kt < 16; kt++) {
        int buf = kt % 3;
        CP_WAIT1();
        __syncthreads();
        if (kt + 2 < 16) ASTAGE(kt + 2);
        CP_COMMIT();

        uint32_t kbuf = ksb + (uint32_t)buf * (32 * ASTR * 2);
        uint32_t vbuf = vsb + (uint32_t)buf * (32 * ASTR * 2);

        // ---- QK^T with -m folded into accumulator init ----
        float sacc[2][4][4];
#pragma unroll
        for (int mi = 0; mi < 2; mi++)
#pragma unroll
            for (int ni = 0; ni < 4; ni++) {
                sacc[mi][ni][0] = -mrow[2 * mi];
                sacc[mi][ni][1] = -mrow[2 * mi];
                sacc[mi][ni][2] = -mrow[2 * mi + 1];
                sacc[mi][ni][3] = -mrow[2 * mi + 1];
            }

#pragma unroll
        for (int ks = 0; ks < 2; ks++) {
            unsigned kb[4][2];
#pragma unroll
            for (int nig = 0; nig < 2; nig++) {
                unsigned r[4];
                ldsm4(r, kbuf + (uint32_t)((nig * 16 + brow_lm) * ASTR + ks * 16 + bcol_lm) * 2);
                kb[nig * 2][0] = r[0]; kb[nig * 2][1] = r[1];
                kb[nig * 2 + 1][0] = r[2]; kb[nig * 2 + 1][1] = r[3];
            }
#pragma unroll
            for (int mi = 0; mi < 2; mi++)
#pragma unroll
                for (int ni = 0; ni < 4; ni++)
                    mma_f16(sacc[mi][ni], qf[mi][ks], kb[ni]);
        }

        // ---- exp: pack to half2, one ex2.f16x2 per pair; result IS the PV A-frag ----
        unsigned p01[2][4], p23[2][4];
#pragma unroll
        for (int mi = 0; mi < 2; mi++)
#pragma unroll
            for (int ni = 0; ni < 4; ni++) {
                p01[mi][ni] = ex2h2(packh2(sacc[mi][ni][0], sacc[mi][ni][1]));
                p23[mi][ni] = ex2h2(packh2(sacc[mi][ni][2], sacc[mi][ni][3]));
            }

        // ---- PV + l-via-ones-mma ----
#pragma unroll
        for (int ks = 0; ks < 2; ks++) {
            unsigned vb[4][2];
#pragma unroll
            for (int nig = 0; nig < 2; nig++) {
                unsigned r[4];
                ldsm4(r, vbuf + (uint32_t)((nig * 16 + brow_lm) * ASTR + ks * 16 + bcol_lm) * 2);
                vb[nig * 2][0] = r[0]; vb[nig * 2][1] = r[1];
                vb[nig * 2 + 1][0] = r[2]; vb[nig * 2 + 1][1] = r[3];
            }
#pragma unroll
            for (int mi = 0; mi < 2; mi++) {
                unsigned pa_[4];
                pa_[0] = p01[mi][2 * ks];
                pa_[1] = p23[mi][2 * ks];
                pa_[2] = p01[mi][2 * ks + 1];
                pa_[3] = p23[mi][2 * ks + 1];
#pragma unroll
                for (int nd = 0; nd < 4; nd++)
                    mma_f16(oacc[mi][nd], pa_, vb[nd]);
                mma_f16(lacc[mi], pa_, ONES2);
            }
        }
    }
#undef ASTAGE

    // finalize: lacc C-frag already holds full row sums (all cols equal)
#pragma unroll
    for (int r = 0; r < 4; r++) {
        int mi = r >> 1, cb = (r & 1) * 2;
        float inv = 1.f / lacc[mi][cb];
        int row = qbase + (r >> 1) * 16 + (r & 1) * 8 + g;
        __half* op = g_attn + ((size_t)b * S_ + row) * H_ + h * HD;
#pragma unroll
        for (int nd = 0; nd < 4; nd++) {
            *(__half2*)(op + nd * 8 + 2 * t) = __floats2half2_rn(
                oacc[mi][nd][cb] * inv, oacc[mi][nd][cb + 1] * inv);
        }
    }
}

// ---------------- launch ----------------
extern "C" void kernel_launch(void* const* d_in, const int* in_sizes, int n_in,
                              void* d_out, int out_size)
{
    const float* inputs = (const float*)d_in[0];
    const float* rmask  = (const float*)d_in[1];
    const float* w_in   = (const float*)d_in[2];
    const float* w_out  = (const float*)d_in[3];
    const float* gamma  = (const float*)d_in[4];
    const float* beta   = (const float*)d_in[5];
    float* out = (float*)d_out;

    const int gemm_smem = 4 * TILEH * (int)sizeof(__half);   // 73728 B
    cudaFuncSetAttribute(gemm_f16<1>, cudaFuncAttributeMaxDynamicSharedMemorySize, gemm_smem);
    cudaFuncSetAttribute(gemm_f16<2>, cudaFuncAttributeMaxDynamicSharedMemorySize, gemm_smem);

    conv_w<<<512, 256>>>(w_in, w_out);
    ln_kernel<<<M_ / 8, 256>>>(inputs, gamma, beta, rmask);
    gemm_f16<1><<<dim3(6, M_ / 128), 256, gemm_smem>>>(nullptr, nullptr);
    attn_f16_kernel<<<512, 256>>>();
    gemm_f16<2><<<dim3(2, M_ / 128), 256, gemm_smem>>>(inputs, out);
}

// round 10
// speedup vs baseline: 7.2481x; 1.0510x over previous
#include <cuda_runtime.h>
#include <cuda_fp16.h>
#include <math.h>
#include <stdint.h>

// Problem dims (fixed)
#define B_   32
#define S_   512
#define H_   256
#define NH   8
#define HD   32
#define M_   (B_ * S_)     // 16384
#define TOT  (M_ * H_)

#define QK_SCALE_L2E 0.25505654440f     // (1/sqrt(32)) * log2(e)
#define RSQRT2       0.70710678118654752f
#define LN_EPS       1e-5f

// ---------------- scratch ----------------
__device__ __half g_normed[TOT];
__device__ __half g_wih[768 * 256];
__device__ __half g_woh[256 * 256];
__device__ __half g_Q[TOT];     // [b,h,s,d], (q*q+1e-6)*scale*log2e  (>= 0)
__device__ __half g_K[TOT];     // [b,h,s,d], + log(radial_mask)
__device__ __half g_V[TOT];     // [b,h,s,d]
__device__ __half g_attn[TOT];  // [b,s,H]
__device__ float    g_lr[M_];
__device__ unsigned g_maxkd[B_ * NH * HD];   // order-preserving float keys

// ---------------- helpers ----------------
__device__ __forceinline__ void mma_f16(float* d, const unsigned* a, const unsigned* b) {
    asm("mma.sync.aligned.m16n8k16.row.col.f32.f16.f16.f32 "
        "{%0,%1,%2,%3},{%4,%5,%6,%7},{%8,%9},{%0,%1,%2,%3};"
        : "+f"(d[0]), "+f"(d[1]), "+f"(d[2]), "+f"(d[3])
        : "r"(a[0]), "r"(a[1]), "r"(a[2]), "r"(a[3]), "r"(b[0]), "r"(b[1]));
}
__device__ __forceinline__ void ldsm4(unsigned* r, uint32_t addr) {
    asm volatile("ldmatrix.sync.aligned.m8n8.x4.shared.b16 {%0,%1,%2,%3}, [%4];"
        : "=r"(r[0]), "=r"(r[1]), "=r"(r[2]), "=r"(r[3]) : "r"(addr));
}
__device__ __forceinline__ void ldsm4t(unsigned* r, uint32_t addr) {
    asm volatile("ldmatrix.sync.aligned.m8n8.x4.trans.shared.b16 {%0,%1,%2,%3}, [%4];"
        : "=r"(r[0]), "=r"(r[1]), "=r"(r[2]), "=r"(r[3]) : "r"(addr));
}
__device__ __forceinline__ unsigned packh2(float lo, float hi) {
    __half2 h = __floats2half2_rn(lo, hi);
    return *(unsigned*)&h;
}
__device__ __forceinline__ unsigned ex2h2(unsigned x) {
    unsigned y;
    asm("ex2.approx.f16x2 %0, %1;" : "=r"(y) : "r"(x));
    return y;
}
__device__ __forceinline__ unsigned ldu32(const __half* p) {
    return *(const unsigned*)p;
}
__device__ __forceinline__ void cp16s(uint32_t saddr, const void* gptr) {
    asm volatile("cp.async.cg.shared.global [%0], [%1], 16;" :: "r"(saddr), "l"(gptr));
}
#define CP_COMMIT() asm volatile("cp.async.commit_group;")
#define CP_WAIT1()  asm volatile("cp.async.wait_group 1;")
#define CP_WAIT2()  asm volatile("cp.async.wait_group 2;")

// order-preserving float<->uint key
__device__ __forceinline__ unsigned fkey(float f) {
    unsigned b = __float_as_uint(f);
    return (b & 0x80000000u) ? ~b : (b | 0x80000000u);
}
__device__ __forceinline__ float funkey(unsigned k) {
    unsigned b = (k & 0x80000000u) ? (k & 0x7fffffffu) : ~k;
    return __uint_as_float(b);
}

// ---------------- LayerNorm + fused weight conversion + maxk init ----------------
__global__ __launch_bounds__(256) void ln_conv_kernel(
    const float* __restrict__ x, const float* __restrict__ gamma,
    const float* __restrict__ beta, const float* __restrict__ rmask,
    const float* __restrict__ wi, const float* __restrict__ wo)
{
    int warp = threadIdx.x >> 5, lane = threadIdx.x & 31;
    int row  = blockIdx.x * 8 + warp;

    // fused conv_w / maxk-init on the first blocks' threads
    int gi = blockIdx.x * 256 + threadIdx.x;
    const int N1 = 768 * 256 / 2;
    const int N2 = 256 * 256 / 2;
    if (gi < B_ * NH * HD) g_maxkd[gi] = 0u;
    if (gi < N1) {
        float2 v = ((const float2*)wi)[gi];
        ((__half2*)g_wih)[gi] = __floats2half2_rn(v.x, v.y);
    } else if (gi < N1 + N2) {
        int j = gi - N1;
        float2 v = ((const float2*)wo)[j];
        ((__half2*)g_woh)[j] = __floats2half2_rn(v.x, v.y);
    }

    const float2* xr = (const float2*)(x + row * H_);
    const float2* g2 = (const float2*)gamma;
    const float2* b2 = (const float2*)beta;

    float2 v[4];
    float sum = 0.f, sq = 0.f;
#pragma unroll
    for (int k = 0; k < 4; k++) {
        float2 t = xr[lane + 32 * k];
        v[k] = t;
        sum += t.x + t.y;
        sq  += t.x * t.x + t.y * t.y;
    }
#pragma unroll
    for (int o = 16; o > 0; o >>= 1) {
        sum += __shfl_xor_sync(0xffffffffu, sum, o);
        sq  += __shfl_xor_sync(0xffffffffu, sq,  o);
    }
    float mu = sum * (1.f / H_);
    float var = sq * (1.f / H_) - mu * mu;
    float rstd = rsqrtf(var + LN_EPS);

    __half2* nr = (__half2*)(g_normed + row * H_);
#pragma unroll
    for (int k = 0; k < 4; k++) {
        int idx = lane + 32 * k;
        float2 gv = g2[idx], bv = b2[idx];
        nr[idx] = __floats2half2_rn(
            (v[k].x - mu) * rstd * gv.x + bv.x,
            (v[k].y - mu) * rstd * gv.y + bv.y);
    }
    if (lane == 0) g_lr[row] = logf(rmask[row]);
}

// ---------------- fp16 MMA GEMM (NT), cp.async 2-stage, ldmatrix frags ----------------
#define SSTRH 72
#define TILEH (128 * SSTRH)

template <int MODE>
__global__ __launch_bounds__(256) void gemm_f16(
    const float* __restrict__ extra, float* __restrict__ C)
{
    extern __shared__ __half smh[];
    __half* As = smh;
    __half* Bs = smh + 2 * TILEH;

    const __half* A    = (MODE == 1) ? g_normed : g_attn;
    const __half* Bmat = (MODE == 1) ? g_wih : g_woh;
    const int K = 256;

    int tid = threadIdx.x;
    int wid = tid >> 5, lane = tid & 31;
    int g = lane >> 2, t = lane & 3;
    int wm = wid >> 2, wn = wid & 3;
    int brow = blockIdx.y, bcol = blockIdx.x;

    int c8  = tid & 7;
    int rwg = tid >> 3;

    int arow_lm = (lane & 7) + ((lane >> 3) & 1) * 8;
    int acol_lm = (lane >> 4) * 8;
    int brow_lm = (lane & 7) + (lane >> 4) * 8;
    int bcol_lm = ((lane >> 3) & 1) * 8;

    const __half* Agb = A    + (size_t)(brow * 128) * K;
    const __half* Bgb = Bmat + (size_t)(bcol * 128) * K;
    uint32_t asBase = (uint32_t)__cvta_generic_to_shared(As);
    uint32_t bsBase = (uint32_t)__cvta_generic_to_shared(Bs);

    float dacc[4][4][4];
#pragma unroll
    for (int i = 0; i < 4; i++)
#pragma unroll
        for (int j = 0; j < 4; j++)
#pragma unroll
            for (int c = 0; c < 4; c++) dacc[i][j][c] = 0.f;

#define STAGE(kt_) do { \
    int _kb = (kt_) * 64; \
    uint32_t _ab = asBase + ((kt_) & 1) * (TILEH * 2); \
    uint32_t _bb = bsBase + ((kt_) & 1) * (TILEH * 2); \
    _Pragma("unroll") \
    for (int _i = 0; _i < 4; _i++) { \
        int _row = rwg + _i * 32; \
        uint32_t _off = (uint32_t)_row * (SSTRH * 2) + (uint32_t)c8 * 16; \
        cp16s(_ab + _off, Agb + (size_t)_row * K + _kb + c8 * 8); \
        cp16s(_bb + _off, Bgb + (size_t)_row * K + _kb + c8 * 8); \
    } \
} while (0)

    STAGE(0); CP_COMMIT();
    STAGE(1); CP_COMMIT();

#pragma unroll
    for (int kt = 0; kt < 4; kt++) {
        CP_WAIT1();
        __syncthreads();

        uint32_t abuf = asBase + (kt & 1) * (TILEH * 2);
        uint32_t bbuf = bsBase + (kt & 1) * (TILEH * 2);
#pragma unroll
        for (int ks = 0; ks < 4; ks++) {
            unsigned af[4][4], bf[4][2];
#pragma unroll
            for (int mi = 0; mi < 4; mi++)
                ldsm4(af[mi], abuf + (uint32_t)((wm * 64 + mi * 16 + arow_lm) * SSTRH
                                               + ks * 16 + acol_lm) * 2);
#pragma unroll
            for (int nig = 0; nig < 2; nig++) {
                unsigned r[4];
                ldsm4(r, bbuf + (uint32_t)((wn * 32 + nig * 16 + brow_lm) * SSTRH
                                           + ks * 16 + bcol_lm) * 2);
                bf[nig * 2][0] = r[0]; bf[nig * 2][1] = r[1];
                bf[nig * 2 + 1][0] = r[2]; bf[nig * 2 + 1][1] = r[3];
            }
#pragma unroll
            for (int mi = 0; mi < 4; mi++)
#pragma unroll
                for (int ni = 0; ni < 4; ni++)
                    mma_f16(dacc[mi][ni], af[mi], bf[ni]);
        }
        __syncthreads();

        if (kt + 2 < 4) STAGE(kt + 2);
        CP_COMMIT();
    }
#undef STAGE

    if (MODE == 1) {
        int region = (bcol * 128) >> 8;   // 0=q 1=k 2=v (uniform per CTA)
        int hh = ((bcol & 1) << 2) + wn;
        float cmax[4][2];
#pragma unroll
        for (int ni = 0; ni < 4; ni++) { cmax[ni][0] = -1e30f; cmax[ni][1] = -1e30f; }

#pragma unroll
        for (int mi = 0; mi < 4; mi++) {
            int r0 = brow * 128 + wm * 64 + mi * 16 + g;
            int r1 = r0 + 8;
            int b = r0 >> 9, s0 = r0 & 511, s1 = r1 & 511;
            __half* dst = (region == 0) ? g_Q : (region == 1) ? g_K : g_V;
            float lr0 = (region == 1) ? g_lr[r0] : 0.f;
            float lr1 = (region == 1) ? g_lr[r1] : 0.f;
            __half* p0 = dst + ((size_t)(b * 8 + hh) * S_ + s0) * HD;
            __half* p1 = dst + ((size_t)(b * 8 + hh) * S_ + s1) * HD;
#pragma unroll
            for (int ni = 0; ni < 4; ni++) {
                int dcol = ni * 8 + 2 * t;
                float v0 = dacc[mi][ni][0], v1 = dacc[mi][ni][1];
                float v2 = dacc[mi][ni][2], v3 = dacc[mi][ni][3];
                if (region == 0) {
                    v0 = (v0 * v0 + 1e-6f) * QK_SCALE_L2E;
                    v1 = (v1 * v1 + 1e-6f) * QK_SCALE_L2E;
                    v2 = (v2 * v2 + 1e-6f) * QK_SCALE_L2E;
                    v3 = (v3 * v3 + 1e-6f) * QK_SCALE_L2E;
                } else if (region == 1) {
                    v0 += lr0; v1 += lr0; v2 += lr1; v3 += lr1;
                    cmax[ni][0] = fmaxf(cmax[ni][0], fmaxf(v0, v2));
                    cmax[ni][1] = fmaxf(cmax[ni][1], fmaxf(v1, v3));
                }
                *(__half2*)(p0 + dcol) = __floats2half2_rn(v0, v1);
                *(__half2*)(p1 + dcol) = __floats2half2_rn(v2, v3);
            }
        }

        if (region == 1) {
#pragma unroll
            for (int ni = 0; ni < 4; ni++) {
#pragma unroll
                for (int o = 4; o <= 16; o <<= 1) {
                    cmax[ni][0] = fmaxf(cmax[ni][0], __shfl_xor_sync(0xffffffffu, cmax[ni][0], o));
                    cmax[ni][1] = fmaxf(cmax[ni][1], __shfl_xor_sync(0xffffffffu, cmax[ni][1], o));
                }
            }
            if (g == 0) {
                int b = brow >> 2;
                unsigned* mk = g_maxkd + (size_t)(b * 8 + hh) * HD;
#pragma unroll
                for (int ni = 0; ni < 4; ni++) {
                    atomicMax(&mk[ni * 8 + 2 * t],     fkey(cmax[ni][0]));
                    atomicMax(&mk[ni * 8 + 2 * t + 1], fkey(cmax[ni][1]));
                }
            }
        }
    } else {
#pragma unroll
        for (int mi = 0; mi < 4; mi++) {
            int r0 = brow * 128 + wm * 64 + mi * 16 + g;
            int r1 = r0 + 8;
            int cbase = bcol * 128 + wn * 32;
            const float* in0 = extra + (size_t)r0 * H_ + cbase;
            const float* in1 = extra + (size_t)r1 * H_ + cbase;
            float* o0 = C + (size_t)r0 * H_ + cbase;
            float* o1 = C + (size_t)r1 * H_ + cbase;
#pragma unroll
            for (int ni = 0; ni < 4; ni++) {
                int dcol = ni * 8 + 2 * t;
                float2 i0 = *(const float2*)(in0 + dcol);
                float2 i1 = *(const float2*)(in1 + dcol);
                *(float2*)(o0 + dcol) = make_float2(
                    (dacc[mi][ni][0] + i0.x) * RSQRT2, (dacc[mi][ni][1] + i0.y) * RSQRT2);
                *(float2*)(o1 + dcol) = make_float2(
                    (dacc[mi][ni][2] + i1.x) * RSQRT2, (dacc[mi][ni][3] + i1.y) * RSQRT2);
            }
        }
    }
}

// ---------------- attention: fp16 mma, static bound, 4-stage cp.async,
// ---------------- V natural layout + ldmatrix.trans PV B-frags ----------------
#define ASTR 40

__global__ __launch_bounds__(256) void attn_f16_kernel()
{
    __shared__ __half Ks[4][32 * ASTR];
    __shared__ __half Vs[4][32 * ASTR];

    int tid = threadIdx.x;
    int wid = tid >> 5, lane = tid & 31;
    int g = lane >> 2, t = lane & 3;
    int qhalf = blockIdx.x & 1, bh = blockIdx.x >> 1;
    int b = bh >> 3, h = bh & 7;
    int qbase = qhalf * 256 + wid * 32;

    int brow_lm = (lane & 7) + (lane >> 4) * 8;      // K (non-trans)
    int bcol_lm = ((lane >> 3) & 1) * 8;
    int trow_lm = lane & 15;                         // V (trans): k row
    int tcol_lm = (lane >> 4) * 8;                   // +8 n col

    // Q fragments resident
    const __half* Qg = g_Q + ((size_t)bh * S_ + qbase) * HD;
    unsigned qf[2][2][4];
#pragma unroll
    for (int mi = 0; mi < 2; mi++) {
        int r = mi * 16 + g;
#pragma unroll
        for (int ks = 0; ks < 2; ks++) {
            qf[mi][ks][0] = ldu32(&Qg[r * HD + ks * 16 + 2 * t]);
            qf[mi][ks][1] = ldu32(&Qg[(r + 8) * HD + ks * 16 + 2 * t]);
            qf[mi][ks][2] = ldu32(&Qg[r * HD + ks * 16 + 2 * t + 8]);
            qf[mi][ks][3] = ldu32(&Qg[(r + 8) * HD + ks * 16 + 2 * t + 8]);
        }
    }

    // static row-max bound
    float mrow[4];
    {
        const unsigned* mku = g_maxkd + bh * HD;
        float m0[2] = {0.f, 0.f}, m1[2] = {0.f, 0.f};
#pragma unroll
        for (int ks = 0; ks < 2; ks++) {
            float mkA0 = funkey(mku[ks * 16 + 2 * t]);
            float mkA1 = funkey(mku[ks * 16 + 2 * t + 1]);
            float mkB0 = funkey(mku[ks * 16 + 2 * t + 8]);
            float mkB1 = funkey(mku[ks * 16 + 2 * t + 9]);
#pragma unroll
            for (int mi = 0; mi < 2; mi++) {
                float2 qa = __half22float2(*(__half2*)&qf[mi][ks][0]);
                float2 qb = __half22float2(*(__half2*)&qf[mi][ks][2]);
                float2 qc = __half22float2(*(__half2*)&qf[mi][ks][1]);
                float2 qd = __half22float2(*(__half2*)&qf[mi][ks][3]);
                m0[mi] += qa.x * mkA0 + qa.y * mkA1 + qb.x * mkB0 + qb.y * mkB1;
                m1[mi] += qc.x * mkA0 + qc.y * mkA1 + qd.x * mkB0 + qd.y * mkB1;
            }
        }
#pragma unroll
        for (int o = 1; o <= 2; o <<= 1) {
#pragma unroll
            for (int mi = 0; mi < 2; mi++) {
                m0[mi] += __shfl_xor_sync(0xffffffffu, m0[mi], o);
                m1[mi] += __shfl_xor_sync(0xffffffffu, m1[mi], o);
            }
        }
        mrow[0] = m0[0]; mrow[1] = m1[0]; mrow[2] = m0[1]; mrow[3] = m1[1];
    }

    float oacc[2][4][4];
#pragma unroll
    for (int mi = 0; mi < 2; mi++)
#pragma unroll
        for (int nd = 0; nd < 4; nd++)
#pragma unroll
            for (int c = 0; c < 4; c++) oacc[mi][nd][c] = 0.f;
    float lacc[2][4];
#pragma unroll
    for (int mi = 0; mi < 2; mi++)
#pragma unroll
        for (int c = 0; c < 4; c++) lacc[mi][c] = 0.f;

    const unsigned ONES2[2] = {0x3C003C00u, 0x3C003C00u};

    // loaders: K and V identical [s][d] layout
    int mat = tid >> 7;           // 0 = K, 1 = V
    int lrw = (tid >> 2) & 31;
    int c4  = tid & 3;
    const __half* Kg = g_K + (size_t)bh * S_ * HD;
    const __half* Vg = g_V + (size_t)bh * S_ * HD;
    const __half* src = (mat == 0) ? Kg : Vg;
    uint32_t ksb = (uint32_t)__cvta_generic_to_shared(&Ks[0][0]);
    uint32_t vsb = (uint32_t)__cvta_generic_to_shared(&Vs[0][0]);
    uint32_t dstb = (mat == 0) ? ksb : vsb;

#define ASTAGE(kt_) do { \
    uint32_t _soff = (uint32_t)((kt_) & 3) * (32 * ASTR * 2) + (uint32_t)lrw * (ASTR * 2) + (uint32_t)c4 * 16; \
    cp16s(dstb + _soff, src + (size_t)((kt_) * 32 + lrw) * HD + c4 * 8); \
} while (0)

    ASTAGE(0); CP_COMMIT();
    ASTAGE(1); CP_COMMIT();
    ASTAGE(2); CP_COMMIT();

#pragma unroll 4
    for (int kt = 0; kt < 16; kt++) {
        CP_WAIT2();
        __syncthreads();
        if (kt + 3 < 16) ASTAGE(kt + 3);
        CP_COMMIT();

        uint32_t kbuf = ksb + (uint32_t)(kt & 3) * (32 * ASTR * 2);
        uint32_t vbuf = vsb + (uint32_t)(kt & 3) * (32 * ASTR * 2);

        // ---- QK^T with -m folded into accumulator init ----
        float sacc[2][4][4];
#pragma unroll
        for (int mi = 0; mi < 2; mi++)
#pragma unroll
            for (int ni = 0; ni < 4; ni++) {
                sacc[mi][ni][0] = -mrow[2 * mi];
                sacc[mi][ni][1] = -mrow[2 * mi];
                sacc[mi][ni][2] = -mrow[2 * mi + 1];
                sacc[mi][ni][3] = -mrow[2 * mi + 1];
            }

#pragma unroll
        for (int ks = 0; ks < 2; ks++) {
            unsigned kb[4][2];
#pragma unroll
            for (int nig = 0; nig < 2; nig++) {
                unsigned r[4];
                ldsm4(r, kbuf + (uint32_t)((nig * 16 + brow_lm) * ASTR + ks * 16 + bcol_lm) * 2);
                kb[nig * 2][0] = r[0]; kb[nig * 2][1] = r[1];
                kb[nig * 2 + 1][0] = r[2]; kb[nig * 2 + 1][1] = r[3];
            }
#pragma unroll
            for (int mi = 0; mi < 2; mi++)
#pragma unroll
                for (int ni = 0; ni < 4; ni++)
                    mma_f16(sacc[mi][ni], qf[mi][ks], kb[ni]);
        }

        // ---- exp (f16x2); result IS the PV A-frag ----
        unsigned p01[2][4], p23[2][4];
#pragma unroll
        for (int mi = 0; mi < 2; mi++)
#pragma unroll
            for (int ni = 0; ni < 4; ni++) {
                p01[mi][ni] = ex2h2(packh2(sacc[mi][ni][0], sacc[mi][ni][1]));
                p23[mi][ni] = ex2h2(packh2(sacc[mi][ni][2], sacc[mi][ni][3]));
            }

        // ---- PV (ldmatrix.trans B-frags from [s][d] V tile) + l-ones-mma ----
#pragma unroll
        for (int ks = 0; ks < 2; ks++) {
            unsigned vb[4][2];
#pragma unroll
            for (int ng = 0; ng < 2; ng++) {
                unsigned r[4];
                ldsm4t(r, vbuf + (uint32_t)((ks * 16 + trow_lm) * ASTR + ng * 16 + tcol_lm) * 2);
                vb[ng * 2][0] = r[0]; vb[ng * 2][1] = r[1];
                vb[ng * 2 + 1][0] = r[2]; vb[ng * 2 + 1][1] = r[3];
            }
#pragma unroll
            for (int mi = 0; mi < 2; mi++) {
                unsigned pa_[4];
                pa_[0] = p01[mi][2 * ks];
                pa_[1] = p23[mi][2 * ks];
                pa_[2] = p01[mi][2 * ks + 1];
                pa_[3] = p23[mi][2 * ks + 1];
#pragma unroll
                for (int nd = 0; nd < 4; nd++)
                    mma_f16(oacc[mi][nd], pa_, vb[nd]);
                mma_f16(lacc[mi], pa_, ONES2);
            }
        }
    }
#undef ASTAGE

    // finalize
#pragma unroll
    for (int r = 0; r < 4; r++) {
        int mi = r >> 1, cb = (r & 1) * 2;
        float inv = 1.f / lacc[mi][cb];
        int row = qbase + (r >> 1) * 16 + (r & 1) * 8 + g;
        __half* op = g_attn + ((size_t)b * S_ + row) * H_ + h * HD;
#pragma unroll
        for (int nd = 0; nd < 4; nd++) {
            *(__half2*)(op + nd * 8 + 2 * t) = __floats2half2_rn(
                oacc[mi][nd][cb] * inv, oacc[mi][nd][cb + 1] * inv);
        }
    }
}

// ---------------- launch ----------------
extern "C" void kernel_launch(void* const* d_in, const int* in_sizes, int n_in,
                              void* d_out, int out_size)
{
    const float* inputs = (const float*)d_in[0];
    const float* rmask  = (const float*)d_in[1];
    const float* w_in   = (const float*)d_in[2];
    const float* w_out  = (const float*)d_in[3];
    const float* gamma  = (const float*)d_in[4];
    const float* beta   = (const float*)d_in[5];
    float* out = (float*)d_out;

    const int gemm_smem = 4 * TILEH * (int)sizeof(__half);   // 73728 B
    cudaFuncSetAttribute(gemm_f16<1>, cudaFuncAttributeMaxDynamicSharedMemorySize, gemm_smem);
    cudaFuncSetAttribute(gemm_f16<2>, cudaFuncAttributeMaxDynamicSharedMemorySize, gemm_smem);

    ln_conv_kernel<<<M_ / 8, 256>>>(inputs, gamma, beta, rmask, w_in, w_out);
    gemm_f16<1><<<dim3(6, M_ / 128), 256, gemm_smem>>>(nullptr, nullptr);
    attn_f16_kernel<<<512, 256>>>();
    gemm_f16<2><<<dim3(2, M_ / 128), 256, gemm_smem>>>(inputs, out);
}

// round 11
// speedup vs baseline: 7.7811x; 1.0735x over previous
#include <cuda_runtime.h>
#include <cuda_fp16.h>
#include <math.h>
#include <stdint.h>

// Problem dims (fixed)
#define B_   32
#define S_   512
#define H_   256
#define NH   8
#define HD   32
#define M_   (B_ * S_)     // 16384
#define TOT  (M_ * H_)

#define QK_SCALE_L2E 0.25505654440f     // (1/sqrt(32)) * log2(e)
#define RSQRT2       0.70710678118654752f
#define LN_EPS       1e-5f

// ---------------- scratch ----------------
__device__ __half g_normed[TOT];
__device__ __half g_wih[768 * 256];
__device__ __half g_woh[256 * 256];
__device__ __half g_Q[TOT];     // [b,h,s,d], (q*q+1e-6)*scale*log2e  (>= 0)
__device__ __half g_K[TOT];     // [b,h,s,d], + log(radial_mask)
__device__ __half g_V[TOT];     // [b,h,s,d]
__device__ __half g_attn[TOT];  // [b,s,H]
__device__ float    g_lr[M_];
__device__ unsigned g_maxkd[B_ * NH * HD];   // order-preserving float keys

// ---------------- helpers ----------------
__device__ __forceinline__ void mma_f16(float* d, const unsigned* a, const unsigned* b) {
    asm("mma.sync.aligned.m16n8k16.row.col.f32.f16.f16.f32 "
        "{%0,%1,%2,%3},{%4,%5,%6,%7},{%8,%9},{%0,%1,%2,%3};"
        : "+f"(d[0]), "+f"(d[1]), "+f"(d[2]), "+f"(d[3])
        : "r"(a[0]), "r"(a[1]), "r"(a[2]), "r"(a[3]), "r"(b[0]), "r"(b[1]));
}
__device__ __forceinline__ void ldsm4(unsigned* r, uint32_t addr) {
    asm volatile("ldmatrix.sync.aligned.m8n8.x4.shared.b16 {%0,%1,%2,%3}, [%4];"
        : "=r"(r[0]), "=r"(r[1]), "=r"(r[2]), "=r"(r[3]) : "r"(addr));
}
__device__ __forceinline__ void ldsm4t(unsigned* r, uint32_t addr) {
    asm volatile("ldmatrix.sync.aligned.m8n8.x4.trans.shared.b16 {%0,%1,%2,%3}, [%4];"
        : "=r"(r[0]), "=r"(r[1]), "=r"(r[2]), "=r"(r[3]) : "r"(addr));
}
__device__ __forceinline__ unsigned packh2(float lo, float hi) {
    __half2 h = __floats2half2_rn(lo, hi);
    return *(unsigned*)&h;
}
__device__ __forceinline__ unsigned ex2h2(unsigned x) {
    unsigned y;
    asm("ex2.approx.f16x2 %0, %1;" : "=r"(y) : "r"(x));
    return y;
}
__device__ __forceinline__ unsigned ldu32(const __half* p) {
    return *(const unsigned*)p;
}
__device__ __forceinline__ void cp16s(uint32_t saddr, const void* gptr) {
    asm volatile("cp.async.cg.shared.global [%0], [%1], 16;" :: "r"(saddr), "l"(gptr));
}
#define CP_COMMIT() asm volatile("cp.async.commit_group;")
#define CP_WAIT1()  asm volatile("cp.async.wait_group 1;")
#define CP_WAIT2()  asm volatile("cp.async.wait_group 2;")

// order-preserving float<->uint key
__device__ __forceinline__ unsigned fkey(float f) {
    unsigned b = __float_as_uint(f);
    return (b & 0x80000000u) ? ~b : (b | 0x80000000u);
}
__device__ __forceinline__ float funkey(unsigned k) {
    unsigned b = (k & 0x80000000u) ? (k & 0x7fffffffu) : ~k;
    return __uint_as_float(b);
}

// ---------------- LayerNorm + fused weight conversion + maxk init ----------------
__global__ __launch_bounds__(256) void ln_conv_kernel(
    const float* __restrict__ x, const float* __restrict__ gamma,
    const float* __restrict__ beta, const float* __restrict__ rmask,
    const float* __restrict__ wi, const float* __restrict__ wo)
{
    int warp = threadIdx.x >> 5, lane = threadIdx.x & 31;
    int row  = blockIdx.x * 8 + warp;

    int gi = blockIdx.x * 256 + threadIdx.x;
    const int N1 = 768 * 256 / 2;
    const int N2 = 256 * 256 / 2;
    if (gi < B_ * NH * HD) g_maxkd[gi] = 0u;
    if (gi < N1) {
        float2 v = ((const float2*)wi)[gi];
        ((__half2*)g_wih)[gi] = __floats2half2_rn(v.x, v.y);
    } else if (gi < N1 + N2) {
        int j = gi - N1;
        float2 v = ((const float2*)wo)[j];
        ((__half2*)g_woh)[j] = __floats2half2_rn(v.x, v.y);
    }

    const float2* xr = (const float2*)(x + row * H_);
    const float2* g2 = (const float2*)gamma;
    const float2* b2 = (const float2*)beta;

    float2 v[4];
    float sum = 0.f, sq = 0.f;
#pragma unroll
    for (int k = 0; k < 4; k++) {
        float2 t = xr[lane + 32 * k];
        v[k] = t;
        sum += t.x + t.y;
        sq  += t.x * t.x + t.y * t.y;
    }
#pragma unroll
    for (int o = 16; o > 0; o >>= 1) {
        sum += __shfl_xor_sync(0xffffffffu, sum, o);
        sq  += __shfl_xor_sync(0xffffffffu, sq,  o);
    }
    float mu = sum * (1.f / H_);
    float var = sq * (1.f / H_) - mu * mu;
    float rstd = rsqrtf(var + LN_EPS);

    __half2* nr = (__half2*)(g_normed + row * H_);
#pragma unroll
    for (int k = 0; k < 4; k++) {
        int idx = lane + 32 * k;
        float2 gv = g2[idx], bv = b2[idx];
        nr[idx] = __floats2half2_rn(
            (v[k].x - mu) * rstd * gv.x + bv.x,
            (v[k].y - mu) * rstd * gv.y + bv.y);
    }
    if (lane == 0) g_lr[row] = logf(rmask[row]);
}

// ---------------- fp16 MMA GEMM (NT), cp.async 2-stage, ldmatrix frags, 2 CTAs/SM ----------------
#define SSTRH 72
#define TILEH (128 * SSTRH)

template <int MODE>
__global__ __launch_bounds__(256, 2) void gemm_f16(
    const float* __restrict__ extra, float* __restrict__ C)
{
    extern __shared__ __half smh[];
    __half* As = smh;
    __half* Bs = smh + 2 * TILEH;

    const __half* A    = (MODE == 1) ? g_normed : g_attn;
    const __half* Bmat = (MODE == 1) ? g_wih : g_woh;
    const int K = 256;

    int tid = threadIdx.x;
    int wid = tid >> 5, lane = tid & 31;
    int g = lane >> 2, t = lane & 3;
    int wm = wid >> 2, wn = wid & 3;
    int brow = blockIdx.y, bcol = blockIdx.x;

    int c8  = tid & 7;
    int rwg = tid >> 3;

    int arow_lm = (lane & 7) + ((lane >> 3) & 1) * 8;
    int acol_lm = (lane >> 4) * 8;
    int brow_lm = (lane & 7) + (lane >> 4) * 8;
    int bcol_lm = ((lane >> 3) & 1) * 8;

    const __half* Agb = A    + (size_t)(brow * 128) * K;
    const __half* Bgb = Bmat + (size_t)(bcol * 128) * K;
    uint32_t asBase = (uint32_t)__cvta_generic_to_shared(As);
    uint32_t bsBase = (uint32_t)__cvta_generic_to_shared(Bs);

    float dacc[4][4][4];
#pragma unroll
    for (int i = 0; i < 4; i++)
#pragma unroll
        for (int j = 0; j < 4; j++)
#pragma unroll
            for (int c = 0; c < 4; c++) dacc[i][j][c] = 0.f;

#define STAGE(kt_) do { \
    int _kb = (kt_) * 64; \
    uint32_t _ab = asBase + ((kt_) & 1) * (TILEH * 2); \
    uint32_t _bb = bsBase + ((kt_) & 1) * (TILEH * 2); \
    _Pragma("unroll") \
    for (int _i = 0; _i < 4; _i++) { \
        int _row = rwg + _i * 32; \
        uint32_t _off = (uint32_t)_row * (SSTRH * 2) + (uint32_t)c8 * 16; \
        cp16s(_ab + _off, Agb + (size_t)_row * K + _kb + c8 * 8); \
        cp16s(_bb + _off, Bgb + (size_t)_row * K + _kb + c8 * 8); \
    } \
} while (0)

    STAGE(0); CP_COMMIT();
    STAGE(1); CP_COMMIT();

#pragma unroll
    for (int kt = 0; kt < 4; kt++) {
        CP_WAIT1();
        __syncthreads();

        uint32_t abuf = asBase + (kt & 1) * (TILEH * 2);
        uint32_t bbuf = bsBase + (kt & 1) * (TILEH * 2);
#pragma unroll
        for (int ks = 0; ks < 4; ks++) {
            unsigned af[4][4], bf[4][2];
#pragma unroll
            for (int mi = 0; mi < 4; mi++)
                ldsm4(af[mi], abuf + (uint32_t)((wm * 64 + mi * 16 + arow_lm) * SSTRH
                                               + ks * 16 + acol_lm) * 2);
#pragma unroll
            for (int nig = 0; nig < 2; nig++) {
                unsigned r[4];
                ldsm4(r, bbuf + (uint32_t)((wn * 32 + nig * 16 + brow_lm) * SSTRH
                                           + ks * 16 + bcol_lm) * 2);
                bf[nig * 2][0] = r[0]; bf[nig * 2][1] = r[1];
                bf[nig * 2 + 1][0] = r[2]; bf[nig * 2 + 1][1] = r[3];
            }
#pragma unroll
            for (int mi = 0; mi < 4; mi++)
#pragma unroll
                for (int ni = 0; ni < 4; ni++)
                    mma_f16(dacc[mi][ni], af[mi], bf[ni]);
        }
        __syncthreads();

        if (kt + 2 < 4) STAGE(kt + 2);
        CP_COMMIT();
    }
#undef STAGE

    if (MODE == 1) {
        int region = (bcol * 128) >> 8;   // 0=q 1=k 2=v (uniform per CTA)
        int hh = ((bcol & 1) << 2) + wn;
        float cmax[4][2];
#pragma unroll
        for (int ni = 0; ni < 4; ni++) { cmax[ni][0] = -1e30f; cmax[ni][1] = -1e30f; }

#pragma unroll
        for (int mi = 0; mi < 4; mi++) {
            int r0 = brow * 128 + wm * 64 + mi * 16 + g;
            int r1 = r0 + 8;
            int b = r0 >> 9, s0 = r0 & 511, s1 = r1 & 511;
            __half* dst = (region == 0) ? g_Q : (region == 1) ? g_K : g_V;
            float lr0 = (region == 1) ? g_lr[r0] : 0.f;
            float lr1 = (region == 1) ? g_lr[r1] : 0.f;
            __half* p0 = dst + ((size_t)(b * 8 + hh) * S_ + s0) * HD;
            __half* p1 = dst + ((size_t)(b * 8 + hh) * S_ + s1) * HD;
#pragma unroll
            for (int ni = 0; ni < 4; ni++) {
                int dcol = ni * 8 + 2 * t;
                float v0 = dacc[mi][ni][0], v1 = dacc[mi][ni][1];
                float v2 = dacc[mi][ni][2], v3 = dacc[mi][ni][3];
                if (region == 0) {
                    v0 = (v0 * v0 + 1e-6f) * QK_SCALE_L2E;
                    v1 = (v1 * v1 + 1e-6f) * QK_SCALE_L2E;
                    v2 = (v2 * v2 + 1e-6f) * QK_SCALE_L2E;
                    v3 = (v3 * v3 + 1e-6f) * QK_SCALE_L2E;
                } else if (region == 1) {
                    v0 += lr0; v1 += lr0; v2 += lr1; v3 += lr1;
                    cmax[ni][0] = fmaxf(cmax[ni][0], fmaxf(v0, v2));
                    cmax[ni][1] = fmaxf(cmax[ni][1], fmaxf(v1, v3));
                }
                *(__half2*)(p0 + dcol) = __floats2half2_rn(v0, v1);
                *(__half2*)(p1 + dcol) = __floats2half2_rn(v2, v3);
            }
        }

        if (region == 1) {
#pragma unroll
            for (int ni = 0; ni < 4; ni++) {
#pragma unroll
                for (int o = 4; o <= 16; o <<= 1) {
                    cmax[ni][0] = fmaxf(cmax[ni][0], __shfl_xor_sync(0xffffffffu, cmax[ni][0], o));
                    cmax[ni][1] = fmaxf(cmax[ni][1], __shfl_xor_sync(0xffffffffu, cmax[ni][1], o));
                }
            }
            if (g == 0) {
                int b = brow >> 2;
                unsigned* mk = g_maxkd + (size_t)(b * 8 + hh) * HD;
#pragma unroll
                for (int ni = 0; ni < 4; ni++) {
                    atomicMax(&mk[ni * 8 + 2 * t],     fkey(cmax[ni][0]));
                    atomicMax(&mk[ni * 8 + 2 * t + 1], fkey(cmax[ni][1]));
                }
            }
        }
    } else {
#pragma unroll
        for (int mi = 0; mi < 4; mi++) {
            int r0 = brow * 128 + wm * 64 + mi * 16 + g;
            int r1 = r0 + 8;
            int cbase = bcol * 128 + wn * 32;
            const float* in0 = extra + (size_t)r0 * H_ + cbase;
            const float* in1 = extra + (size_t)r1 * H_ + cbase;
            float* o0 = C + (size_t)r0 * H_ + cbase;
            float* o1 = C + (size_t)r1 * H_ + cbase;
#pragma unroll
            for (int ni = 0; ni < 4; ni++) {
                int dcol = ni * 8 + 2 * t;
                float2 i0 = *(const float2*)(in0 + dcol);
                float2 i1 = *(const float2*)(in1 + dcol);
                *(float2*)(o0 + dcol) = make_float2(
                    (dacc[mi][ni][0] + i0.x) * RSQRT2, (dacc[mi][ni][1] + i0.y) * RSQRT2);
                *(float2*)(o1 + dcol) = make_float2(
                    (dacc[mi][ni][2] + i1.x) * RSQRT2, (dacc[mi][ni][3] + i1.y) * RSQRT2);
            }
        }
    }
}

// ---------------- attention: fp16 mma, static bound, 4-stage cp.async,
// ---------------- V natural layout + ldmatrix.trans PV B-frags ----------------
#define ASTR 40

__global__ __launch_bounds__(256) void attn_f16_kernel()
{
    __shared__ __half Ks[4][32 * ASTR];
    __shared__ __half Vs[4][32 * ASTR];

    int tid = threadIdx.x;
    int wid = tid >> 5, lane = tid & 31;
    int g = lane >> 2, t = lane & 3;
    int qhalf = blockIdx.x & 1, bh = blockIdx.x >> 1;
    int b = bh >> 3, h = bh & 7;
    int qbase = qhalf * 256 + wid * 32;

    int brow_lm = (lane & 7) + (lane >> 4) * 8;      // K (non-trans)
    int bcol_lm = ((lane >> 3) & 1) * 8;
    int trow_lm = lane & 15;                         // V (trans): k row
    int tcol_lm = (lane >> 4) * 8;                   // +8 n col

    // Q fragments resident
    const __half* Qg = g_Q + ((size_t)bh * S_ + qbase) * HD;
    unsigned qf[2][2][4];
#pragma unroll
    for (int mi = 0; mi < 2; mi++) {
        int r = mi * 16 + g;
#pragma unroll
        for (int ks = 0; ks < 2; ks++) {
            qf[mi][ks][0] = ldu32(&Qg[r * HD + ks * 16 + 2 * t]);
            qf[mi][ks][1] = ldu32(&Qg[(r + 8) * HD + ks * 16 + 2 * t]);
            qf[mi][ks][2] = ldu32(&Qg[r * HD + ks * 16 + 2 * t + 8]);
            qf[mi][ks][3] = ldu32(&Qg[(r + 8) * HD + ks * 16 + 2 * t + 8]);
        }
    }

    // static row-max bound
    float mrow[4];
    {
        const unsigned* mku = g_maxkd + bh * HD;
        float m0[2] = {0.f, 0.f}, m1[2] = {0.f, 0.f};
#pragma unroll
        for (int ks = 0; ks < 2; ks++) {
            float mkA0 = funkey(mku[ks * 16 + 2 * t]);
            float mkA1 = funkey(mku[ks * 16 + 2 * t + 1]);
            float mkB0 = funkey(mku[ks * 16 + 2 * t + 8]);
            float mkB1 = funkey(mku[ks * 16 + 2 * t + 9]);
#pragma unroll
            for (int mi = 0; mi < 2; mi++) {
                float2 qa = __half22float2(*(__half2*)&qf[mi][ks][0]);
                float2 qb = __half22float2(*(__half2*)&qf[mi][ks][2]);
                float2 qc = __half22float2(*(__half2*)&qf[mi][ks][1]);
                float2 qd = __half22float2(*(__half2*)&qf[mi][ks][3]);
                m0[mi] += qa.x * mkA0 + qa.y * mkA1 + qb.x * mkB0 + qb.y * mkB1;
                m1[mi] += qc.x * mkA0 + qc.y * mkA1 + qd.x * mkB0 + qd.y * mkB1;
            }
        }
#pragma unroll
        for (int o = 1; o <= 2; o <<= 1) {
#pragma unroll
            for (int mi = 0; mi < 2; mi++) {
                m0[mi] += __shfl_xor_sync(0xffffffffu, m0[mi], o);
                m1[mi] += __shfl_xor_sync(0xffffffffu, m1[mi], o);
            }
        }
        mrow[0] = m0[0]; mrow[1] = m1[0]; mrow[2] = m0[1]; mrow[3] = m1[1];
    }

    float oacc[2][4][4];
#pragma unroll
    for (int mi = 0; mi < 2; mi++)
#pragma unroll
        for (int nd = 0; nd < 4; nd++)
#pragma unroll
            for (int c = 0; c < 4; c++) oacc[mi][nd][c] = 0.f;
    float lacc[2][4];
#pragma unroll
    for (int mi = 0; mi < 2; mi++)
#pragma unroll
        for (int c = 0; c < 4; c++) lacc[mi][c] = 0.f;

    const unsigned ONES2[2] = {0x3C003C00u, 0x3C003C00u};

    int mat = tid >> 7;           // 0 = K, 1 = V
    int lrw = (tid >> 2) & 31;
    int c4  = tid & 3;
    const __half* Kg = g_K + (size_t)bh * S_ * HD;
    const __half* Vg = g_V + (size_t)bh * S_ * HD;
    const __half* src = (mat == 0) ? Kg : Vg;
    uint32_t ksb = (uint32_t)__cvta_generic_to_shared(&Ks[0][0]);
    uint32_t vsb = (uint32_t)__cvta_generic_to_shared(&Vs[0][0]);
    uint32_t dstb = (mat == 0) ? ksb : vsb;

#define ASTAGE(kt_) do { \
    uint32_t _soff = (uint32_t)((kt_) & 3) * (32 * ASTR * 2) + (uint32_t)lrw * (ASTR * 2) + (uint32_t)c4 * 16; \
    cp16s(dstb + _soff, src + (size_t)((kt_) * 32 + lrw) * HD + c4 * 8); \
} while (0)

    ASTAGE(0); CP_COMMIT();
    ASTAGE(1); CP_COMMIT();
    ASTAGE(2); CP_COMMIT();

#pragma unroll 4
    for (int kt = 0; kt < 16; kt++) {
        CP_WAIT2();
        __syncthreads();
        if (kt + 3 < 16) ASTAGE(kt + 3);
        CP_COMMIT();

        uint32_t kbuf = ksb + (uint32_t)(kt & 3) * (32 * ASTR * 2);
        uint32_t vbuf = vsb + (uint32_t)(kt & 3) * (32 * ASTR * 2);

        // ---- QK^T with -m folded into accumulator init ----
        float sacc[2][4][4];
#pragma unroll
        for (int mi = 0; mi < 2; mi++)
#pragma unroll
            for (int ni = 0; ni < 4; ni++) {
                sacc[mi][ni][0] = -mrow[2 * mi];
                sacc[mi][ni][1] = -mrow[2 * mi];
                sacc[mi][ni][2] = -mrow[2 * mi + 1];
                sacc[mi][ni][3] = -mrow[2 * mi + 1];
            }

#pragma unroll
        for (int ks = 0; ks < 2; ks++) {
            unsigned kb[4][2];
#pragma unroll
            for (int nig = 0; nig < 2; nig++) {
                unsigned r[4];
                ldsm4(r, kbuf + (uint32_t)((nig * 16 + brow_lm) * ASTR + ks * 16 + bcol_lm) * 2);
                kb[nig * 2][0] = r[0]; kb[nig * 2][1] = r[1];
                kb[nig * 2 + 1][0] = r[2]; kb[nig * 2 + 1][1] = r[3];
            }
#pragma unroll
            for (int mi = 0; mi < 2; mi++)
#pragma unroll
                for (int ni = 0; ni < 4; ni++)
                    mma_f16(sacc[mi][ni], qf[mi][ks], kb[ni]);
        }

        // ---- exp (f16x2); result IS the PV A-frag ----
        unsigned p01[2][4], p23[2][4];
#pragma unroll
        for (int mi = 0; mi < 2; mi++)
#pragma unroll
            for (int ni = 0; ni < 4; ni++) {
                p01[mi][ni] = ex2h2(packh2(sacc[mi][ni][0], sacc[mi][ni][1]));
                p23[mi][ni] = ex2h2(packh2(sacc[mi][ni][2], sacc[mi][ni][3]));
            }

        // ---- PV (ldmatrix.trans B-frags from [s][d] V tile) + l-ones-mma ----
#pragma unroll
        for (int ks = 0; ks < 2; ks++) {
            unsigned vb[4][2];
#pragma unroll
            for (int ng = 0; ng < 2; ng++) {
                unsigned r[4];
                ldsm4t(r, vbuf + (uint32_t)((ks * 16 + trow_lm) * ASTR + ng * 16 + tcol_lm) * 2);
                vb[ng * 2][0] = r[0]; vb[ng * 2][1] = r[1];
                vb[ng * 2 + 1][0] = r[2]; vb[ng * 2 + 1][1] = r[3];
            }
#pragma unroll
            for (int mi = 0; mi < 2; mi++) {
                unsigned pa_[4];
                pa_[0] = p01[mi][2 * ks];
                pa_[1] = p23[mi][2 * ks];
                pa_[2] = p01[mi][2 * ks + 1];
                pa_[3] = p23[mi][2 * ks + 1];
#pragma unroll
                for (int nd = 0; nd < 4; nd++)
                    mma_f16(oacc[mi][nd], pa_, vb[nd]);
                mma_f16(lacc[mi], pa_, ONES2);
            }
        }
    }
#undef ASTAGE

    // finalize
#pragma unroll
    for (int r = 0; r < 4; r++) {
        int mi = r >> 1, cb = (r & 1) * 2;
        float inv = 1.f / lacc[mi][cb];
        int row = qbase + (r >> 1) * 16 + (r & 1) * 8 + g;
        __half* op = g_attn + ((size_t)b * S_ + row) * H_ + h * HD;
#pragma unroll
        for (int nd = 0; nd < 4; nd++) {
            *(__half2*)(op + nd * 8 + 2 * t) = __floats2half2_rn(
                oacc[mi][nd][cb] * inv, oacc[mi][nd][cb + 1] * inv);
        }
    }
}

// ---------------- launch ----------------
extern "C" void kernel_launch(void* const* d_in, const int* in_sizes, int n_in,
                              void* d_out, int out_size)
{
    const float* inputs = (const float*)d_in[0];
    const float* rmask  = (const float*)d_in[1];
    const float* w_in   = (const float*)d_in[2];
    const float* w_out  = (const float*)d_in[3];
    const float* gamma  = (const float*)d_in[4];
    const float* beta   = (const float*)d_in[5];
    float* out = (float*)d_out;

    const int gemm_smem = 4 * TILEH * (int)sizeof(__half);   // 73728 B
    cudaFuncSetAttribute(gemm_f16<1>, cudaFuncAttributeMaxDynamicSharedMemorySize, gemm_smem);
    cudaFuncSetAttribute(gemm_f16<2>, cudaFuncAttributeMaxDynamicSharedMemorySize, gemm_smem);

    ln_conv_kernel<<<M_ / 8, 256>>>(inputs, gamma, beta, rmask, w_in, w_out);
    gemm_f16<1><<<dim3(6, M_ / 128), 256, gemm_smem>>>(nullptr, nullptr);
    attn_f16_kernel<<<512, 256>>>();
    gemm_f16<2><<<dim3(2, M_ / 128), 256, gemm_smem>>>(inputs, out);
}

// round 12
// speedup vs baseline: 7.8414x; 1.0078x over previous
#include <cuda_runtime.h>
#include <cuda_fp16.h>
#include <math.h>
#include <stdint.h>

// Problem dims (fixed)
#define B_   32
#define S_   512
#define H_   256
#define NH   8
#define HD   32
#define M_   (B_ * S_)     // 16384
#define TOT  (M_ * H_)

#define QK_SCALE_L2E 0.25505654440f     // (1/sqrt(32)) * log2(e)
#define RSQRT2       0.70710678118654752f
#define LN_EPS       1e-5f

// ---------------- scratch ----------------
__device__ __half g_normed[TOT];
__device__ __half g_wih[768 * 256];
__device__ __half g_woh[256 * 256];
__device__ __half g_Q[TOT];     // [b,h,s,d], (q*q+1e-6)*scale*log2e  (>= 0)
__device__ __half g_K[TOT];     // [b,h,s,d], + log(radial_mask)
__device__ __half g_V[TOT];     // [b,h,s,d]
__device__ __half g_attn[TOT];  // [b,s,H]
__device__ float    g_lr[M_];
__device__ unsigned g_maxkd[B_ * NH * HD];   // order-preserving float keys

// ---------------- helpers ----------------
__device__ __forceinline__ void mma_f16(float* d, const unsigned* a, const unsigned* b) {
    asm("mma.sync.aligned.m16n8k16.row.col.f32.f16.f16.f32 "
        "{%0,%1,%2,%3},{%4,%5,%6,%7},{%8,%9},{%0,%1,%2,%3};"
        : "+f"(d[0]), "+f"(d[1]), "+f"(d[2]), "+f"(d[3])
        : "r"(a[0]), "r"(a[1]), "r"(a[2]), "r"(a[3]), "r"(b[0]), "r"(b[1]));
}
__device__ __forceinline__ void ldsm4(unsigned* r, uint32_t addr) {
    asm volatile("ldmatrix.sync.aligned.m8n8.x4.shared.b16 {%0,%1,%2,%3}, [%4];"
        : "=r"(r[0]), "=r"(r[1]), "=r"(r[2]), "=r"(r[3]) : "r"(addr));
}
__device__ __forceinline__ void ldsm4t(unsigned* r, uint32_t addr) {
    asm volatile("ldmatrix.sync.aligned.m8n8.x4.trans.shared.b16 {%0,%1,%2,%3}, [%4];"
        : "=r"(r[0]), "=r"(r[1]), "=r"(r[2]), "=r"(r[3]) : "r"(addr));
}
__device__ __forceinline__ unsigned packh2(float lo, float hi) {
    __half2 h = __floats2half2_rn(lo, hi);
    return *(unsigned*)&h;
}
__device__ __forceinline__ unsigned ex2h2(unsigned x) {
    unsigned y;
    asm("ex2.approx.f16x2 %0, %1;" : "=r"(y) : "r"(x));
    return y;
}
__device__ __forceinline__ unsigned ldu32(const __half* p) {
    return *(const unsigned*)p;
}
__device__ __forceinline__ void cp16s(uint32_t saddr, const void* gptr) {
    asm volatile("cp.async.cg.shared.global [%0], [%1], 16;" :: "r"(saddr), "l"(gptr));
}
#define CP_COMMIT() asm volatile("cp.async.commit_group;")
#define CP_WAIT1()  asm volatile("cp.async.wait_group 1;")
#define CP_WAIT2()  asm volatile("cp.async.wait_group 2;")

// order-preserving float<->uint key
__device__ __forceinline__ unsigned fkey(float f) {
    unsigned b = __float_as_uint(f);
    return (b & 0x80000000u) ? ~b : (b | 0x80000000u);
}
__device__ __forceinline__ float funkey(unsigned k) {
    unsigned b = (k & 0x80000000u) ? (k & 0x7fffffffu) : ~k;
    return __uint_as_float(b);
}

// ---------------- LayerNorm + fused weight conversion + maxk init ----------------
__global__ __launch_bounds__(256) void ln_conv_kernel(
    const float* __restrict__ x, const float* __restrict__ gamma,
    const float* __restrict__ beta, const float* __restrict__ rmask,
    const float* __restrict__ wi, const float* __restrict__ wo)
{
    int warp = threadIdx.x >> 5, lane = threadIdx.x & 31;
    int row  = blockIdx.x * 8 + warp;

    int gi = blockIdx.x * 256 + threadIdx.x;
    const int N1 = 768 * 256 / 2;
    const int N2 = 256 * 256 / 2;
    if (gi < B_ * NH * HD) g_maxkd[gi] = 0u;
    if (gi < N1) {
        float2 v = ((const float2*)wi)[gi];
        ((__half2*)g_wih)[gi] = __floats2half2_rn(v.x, v.y);
    } else if (gi < N1 + N2) {
        int j = gi - N1;
        float2 v = ((const float2*)wo)[j];
        ((__half2*)g_woh)[j] = __floats2half2_rn(v.x, v.y);
    }

    const float2* xr = (const float2*)(x + row * H_);
    const float2* g2 = (const float2*)gamma;
    const float2* b2 = (const float2*)beta;

    float2 v[4];
    float sum = 0.f, sq = 0.f;
#pragma unroll
    for (int k = 0; k < 4; k++) {
        float2 t = xr[lane + 32 * k];
        v[k] = t;
        sum += t.x + t.y;
        sq  += t.x * t.x + t.y * t.y;
    }
#pragma unroll
    for (int o = 16; o > 0; o >>= 1) {
        sum += __shfl_xor_sync(0xffffffffu, sum, o);
        sq  += __shfl_xor_sync(0xffffffffu, sq,  o);
    }
    float mu = sum * (1.f / H_);
    float var = sq * (1.f / H_) - mu * mu;
    float rstd = rsqrtf(var + LN_EPS);

    __half2* nr = (__half2*)(g_normed + row * H_);
#pragma unroll
    for (int k = 0; k < 4; k++) {
        int idx = lane + 32 * k;
        float2 gv = g2[idx], bv = b2[idx];
        nr[idx] = __floats2half2_rn(
            (v[k].x - mu) * rstd * gv.x + bv.x,
            (v[k].y - mu) * rstd * gv.y + bv.y);
    }
    if (lane == 0) g_lr[row] = logf(rmask[row]);
}

// ---------------- fp16 MMA GEMM (NT): 3-stage cp.async, single barrier/tile,
// ---------------- prefetch-first, ldmatrix frags, 2 CTAs/SM ----------------
#define SSTRH 72
#define TILEH (128 * SSTRH)

template <int MODE>
__global__ __launch_bounds__(256, 2) void gemm_f16(
    const float* __restrict__ extra, float* __restrict__ C)
{
    extern __shared__ __half smh[];
    __half* As = smh;                 // [3][TILEH]
    __half* Bs = smh + 3 * TILEH;     // [3][TILEH]

    const __half* A    = (MODE == 1) ? g_normed : g_attn;
    const __half* Bmat = (MODE == 1) ? g_wih : g_woh;
    const int K = 256;

    int tid = threadIdx.x;
    int wid = tid >> 5, lane = tid & 31;
    int g = lane >> 2, t = lane & 3;
    int wm = wid >> 2, wn = wid & 3;
    int brow = blockIdx.y, bcol = blockIdx.x;

    int c8  = tid & 7;
    int rwg = tid >> 3;

    int arow_lm = (lane & 7) + ((lane >> 3) & 1) * 8;
    int acol_lm = (lane >> 4) * 8;
    int brow_lm = (lane & 7) + (lane >> 4) * 8;
    int bcol_lm = ((lane >> 3) & 1) * 8;

    const __half* Agb = A    + (size_t)(brow * 128) * K;
    const __half* Bgb = Bmat + (size_t)(bcol * 128) * K;
    uint32_t asBase = (uint32_t)__cvta_generic_to_shared(As);
    uint32_t bsBase = (uint32_t)__cvta_generic_to_shared(Bs);

    float dacc[4][4][4];
#pragma unroll
    for (int i = 0; i < 4; i++)
#pragma unroll
        for (int j = 0; j < 4; j++)
#pragma unroll
            for (int c = 0; c < 4; c++) dacc[i][j][c] = 0.f;

#define STAGE(kt_, buf_) do { \
    int _kb = (kt_) * 64; \
    uint32_t _ab = asBase + (uint32_t)(buf_) * (TILEH * 2); \
    uint32_t _bb = bsBase + (uint32_t)(buf_) * (TILEH * 2); \
    _Pragma("unroll") \
    for (int _i = 0; _i < 4; _i++) { \
        int _row = rwg + _i * 32; \
        uint32_t _off = (uint32_t)_row * (SSTRH * 2) + (uint32_t)c8 * 16; \
        cp16s(_ab + _off, Agb + (size_t)_row * K + _kb + c8 * 8); \
        cp16s(_bb + _off, Bgb + (size_t)_row * K + _kb + c8 * 8); \
    } \
} while (0)

    STAGE(0, 0); CP_COMMIT();
    STAGE(1, 1); CP_COMMIT();

#pragma unroll
    for (int kt = 0; kt < 4; kt++) {
        CP_WAIT1();
        __syncthreads();
        // prefetch kt+2 into buffer (kt+2)%3 — last read at kt-1, safe after this barrier
        if (kt + 2 < 4) STAGE(kt + 2, (kt + 2) % 3);
        CP_COMMIT();

        uint32_t abuf = asBase + (uint32_t)(kt % 3) * (TILEH * 2);
        uint32_t bbuf = bsBase + (uint32_t)(kt % 3) * (TILEH * 2);
#pragma unroll
        for (int ks = 0; ks < 4; ks++) {
            unsigned af[4][4], bf[4][2];
#pragma unroll
            for (int mi = 0; mi < 4; mi++)
                ldsm4(af[mi], abuf + (uint32_t)((wm * 64 + mi * 16 + arow_lm) * SSTRH
                                               + ks * 16 + acol_lm) * 2);
#pragma unroll
            for (int nig = 0; nig < 2; nig++) {
                unsigned r[4];
                ldsm4(r, bbuf + (uint32_t)((wn * 32 + nig * 16 + brow_lm) * SSTRH
                                           + ks * 16 + bcol_lm) * 2);
                bf[nig * 2][0] = r[0]; bf[nig * 2][1] = r[1];
                bf[nig * 2 + 1][0] = r[2]; bf[nig * 2 + 1][1] = r[3];
            }
#pragma unroll
            for (int mi = 0; mi < 4; mi++)
#pragma unroll
                for (int ni = 0; ni < 4; ni++)
                    mma_f16(dacc[mi][ni], af[mi], bf[ni]);
        }
    }
#undef STAGE

    if (MODE == 1) {
        int region = (bcol * 128) >> 8;   // 0=q 1=k 2=v (uniform per CTA)
        int hh = ((bcol & 1) << 2) + wn;
        float cmax[4][2];
#pragma unroll
        for (int ni = 0; ni < 4; ni++) { cmax[ni][0] = -1e30f; cmax[ni][1] = -1e30f; }

#pragma unroll
        for (int mi = 0; mi < 4; mi++) {
            int r0 = brow * 128 + wm * 64 + mi * 16 + g;
            int r1 = r0 + 8;
            int b = r0 >> 9, s0 = r0 & 511, s1 = r1 & 511;
            __half* dst = (region == 0) ? g_Q : (region == 1) ? g_K : g_V;
            float lr0 = (region == 1) ? g_lr[r0] : 0.f;
            float lr1 = (region == 1) ? g_lr[r1] : 0.f;
            __half* p0 = dst + ((size_t)(b * 8 + hh) * S_ + s0) * HD;
            __half* p1 = dst + ((size_t)(b * 8 + hh) * S_ + s1) * HD;
#pragma unroll
            for (int ni = 0; ni < 4; ni++) {
                int dcol = ni * 8 + 2 * t;
                float v0 = dacc[mi][ni][0], v1 = dacc[mi][ni][1];
                float v2 = dacc[mi][ni][2], v3 = dacc[mi][ni][3];
                if (region == 0) {
                    v0 = (v0 * v0 + 1e-6f) * QK_SCALE_L2E;
                    v1 = (v1 * v1 + 1e-6f) * QK_SCALE_L2E;
                    v2 = (v2 * v2 + 1e-6f) * QK_SCALE_L2E;
                    v3 = (v3 * v3 + 1e-6f) * QK_SCALE_L2E;
                } else if (region == 1) {
                    v0 += lr0; v1 += lr0; v2 += lr1; v3 += lr1;
                    cmax[ni][0] = fmaxf(cmax[ni][0], fmaxf(v0, v2));
                    cmax[ni][1] = fmaxf(cmax[ni][1], fmaxf(v1, v3));
                }
                *(__half2*)(p0 + dcol) = __floats2half2_rn(v0, v1);
                *(__half2*)(p1 + dcol) = __floats2half2_rn(v2, v3);
            }
        }

        if (region == 1) {
#pragma unroll
            for (int ni = 0; ni < 4; ni++) {
#pragma unroll
                for (int o = 4; o <= 16; o <<= 1) {
                    cmax[ni][0] = fmaxf(cmax[ni][0], __shfl_xor_sync(0xffffffffu, cmax[ni][0], o));
                    cmax[ni][1] = fmaxf(cmax[ni][1], __shfl_xor_sync(0xffffffffu, cmax[ni][1], o));
                }
            }
            if (g == 0) {
                int b = brow >> 2;
                unsigned* mk = g_maxkd + (size_t)(b * 8 + hh) * HD;
#pragma unroll
                for (int ni = 0; ni < 4; ni++) {
                    atomicMax(&mk[ni * 8 + 2 * t],     fkey(cmax[ni][0]));
                    atomicMax(&mk[ni * 8 + 2 * t + 1], fkey(cmax[ni][1]));
                }
            }
        }
    } else {
#pragma unroll
        for (int mi = 0; mi < 4; mi++) {
            int r0 = brow * 128 + wm * 64 + mi * 16 + g;
            int r1 = r0 + 8;
            int cbase = bcol * 128 + wn * 32;
            const float* in0 = extra + (size_t)r0 * H_ + cbase;
            const float* in1 = extra + (size_t)r1 * H_ + cbase;
            float* o0 = C + (size_t)r0 * H_ + cbase;
            float* o1 = C + (size_t)r1 * H_ + cbase;
#pragma unroll
            for (int ni = 0; ni < 4; ni++) {
                int dcol = ni * 8 + 2 * t;
                float2 i0 = *(const float2*)(in0 + dcol);
                float2 i1 = *(const float2*)(in1 + dcol);
                *(float2*)(o0 + dcol) = make_float2(
                    (dacc[mi][ni][0] + i0.x) * RSQRT2, (dacc[mi][ni][1] + i0.y) * RSQRT2);
                *(float2*)(o1 + dcol) = make_float2(
                    (dacc[mi][ni][2] + i1.x) * RSQRT2, (dacc[mi][ni][3] + i1.y) * RSQRT2);
            }
        }
    }
}

// ---------------- attention: fp16 mma, static bound, 4-stage cp.async,
// ---------------- V natural layout + ldmatrix.trans PV B-frags ----------------
#define ASTR 40

__global__ __launch_bounds__(256) void attn_f16_kernel()
{
    __shared__ __half Ks[4][32 * ASTR];
    __shared__ __half Vs[4][32 * ASTR];

    int tid = threadIdx.x;
    int wid = tid >> 5, lane = tid & 31;
    int g = lane >> 2, t = lane & 3;
    int qhalf = blockIdx.x & 1, bh = blockIdx.x >> 1;
    int b = bh >> 3, h = bh & 7;
    int qbase = qhalf * 256 + wid * 32;

    int brow_lm = (lane & 7) + (lane >> 4) * 8;      // K (non-trans)
    int bcol_lm = ((lane >> 3) & 1) * 8;
    int trow_lm = lane & 15;                         // V (trans): k row
    int tcol_lm = (lane >> 4) * 8;                   // +8 n col

    // Q fragments resident
    const __half* Qg = g_Q + ((size_t)bh * S_ + qbase) * HD;
    unsigned qf[2][2][4];
#pragma unroll
    for (int mi = 0; mi < 2; mi++) {
        int r = mi * 16 + g;
#pragma unroll
        for (int ks = 0; ks < 2; ks++) {
            qf[mi][ks][0] = ldu32(&Qg[r * HD + ks * 16 + 2 * t]);
            qf[mi][ks][1] = ldu32(&Qg[(r + 8) * HD + ks * 16 + 2 * t]);
            qf[mi][ks][2] = ldu32(&Qg[r * HD + ks * 16 + 2 * t + 8]);
            qf[mi][ks][3] = ldu32(&Qg[(r + 8) * HD + ks * 16 + 2 * t + 8]);
        }
    }

    // static row-max bound
    float mrow[4];
    {
        const unsigned* mku = g_maxkd + bh * HD;
        float m0[2] = {0.f, 0.f}, m1[2] = {0.f, 0.f};
#pragma unroll
        for (int ks = 0; ks < 2; ks++) {
            float mkA0 = funkey(mku[ks * 16 + 2 * t]);
            float mkA1 = funkey(mku[ks * 16 + 2 * t + 1]);
            float mkB0 = funkey(mku[ks * 16 + 2 * t + 8]);
            float mkB1 = funkey(mku[ks * 16 + 2 * t + 9]);
#pragma unroll
            for (int mi = 0; mi < 2; mi++) {
                float2 qa = __half22float2(*(__half2*)&qf[mi][ks][0]);
                float2 qb = __half22float2(*(__half2*)&qf[mi][ks][2]);
                float2 qc = __half22float2(*(__half2*)&qf[mi][ks][1]);
                float2 qd = __half22float2(*(__half2*)&qf[mi][ks][3]);
                m0[mi] += qa.x * mkA0 + qa.y * mkA1 + qb.x * mkB0 + qb.y * mkB1;
                m1[mi] += qc.x * mkA0 + qc.y * mkA1 + qd.x * mkB0 + qd.y * mkB1;
            }
        }
#pragma unroll
        for (int o = 1; o <= 2; o <<= 1) {
#pragma unroll
            for (int mi = 0; mi < 2; mi++) {
                m0[mi] += __shfl_xor_sync(0xffffffffu, m0[mi], o);
                m1[mi] += __shfl_xor_sync(0xffffffffu, m1[mi], o);
            }
        }
        mrow[0] = m0[0]; mrow[1] = m1[0]; mrow[2] = m0[1]; mrow[3] = m1[1];
    }

    float oacc[2][4][4];
#pragma unroll
    for (int mi = 0; mi < 2; mi++)
#pragma unroll
        for (int nd = 0; nd < 4; nd++)
#pragma unroll
            for (int c = 0; c < 4; c++) oacc[mi][nd][c] = 0.f;
    float lacc[2][4];
#pragma unroll
    for (int mi = 0; mi < 2; mi++)
#pragma unroll
        for (int c = 0; c < 4; c++) lacc[mi][c] = 0.f;

    const unsigned ONES2[2] = {0x3C003C00u, 0x3C003C00u};

    int mat = tid >> 7;           // 0 = K, 1 = V
    int lrw = (tid >> 2) & 31;
    int c4  = tid & 3;
    const __half* Kg = g_K + (size_t)bh * S_ * HD;
    const __half* Vg = g_V + (size_t)bh * S_ * HD;
    const __half* src = (mat == 0) ? Kg : Vg;
    uint32_t ksb = (uint32_t)__cvta_generic_to_shared(&Ks[0][0]);
    uint32_t vsb = (uint32_t)__cvta_generic_to_shared(&Vs[0][0]);
    uint32_t dstb = (mat == 0) ? ksb : vsb;

#define ASTAGE(kt_) do { \
    uint32_t _soff = (uint32_t)((kt_) & 3) * (32 * ASTR * 2) + (uint32_t)lrw * (ASTR * 2) + (uint32_t)c4 * 16; \
    cp16s(dstb + _soff, src + (size_t)((kt_) * 32 + lrw) * HD + c4 * 8); \
} while (0)

    ASTAGE(0); CP_COMMIT();
    ASTAGE(1); CP_COMMIT();
    ASTAGE(2); CP_COMMIT();

#pragma unroll 4
    for (int kt = 0; kt < 16; kt++) {
        CP_WAIT2();
        __syncthreads();
        if (kt + 3 < 16) ASTAGE(kt + 3);
        CP_COMMIT();

        uint32_t kbuf = ksb + (uint32_t)(kt & 3) * (32 * ASTR * 2);
        uint32_t vbuf = vsb + (uint32_t)(kt & 3) * (32 * ASTR * 2);

        // ---- QK^T with -m folded into accumulator init ----
        float sacc[2][4][4];
#pragma unroll
        for (int mi = 0; mi < 2; mi++)
#pragma unroll
            for (int ni = 0; ni < 4; ni++) {
                sacc[mi][ni][0] = -mrow[2 * mi];
                sacc[mi][ni][1] = -mrow[2 * mi];
                sacc[mi][ni][2] = -mrow[2 * mi + 1];
                sacc[mi][ni][3] = -mrow[2 * mi + 1];
            }

#pragma unroll
        for (int ks = 0; ks < 2; ks++) {
            unsigned kb[4][2];
#pragma unroll
            for (int nig = 0; nig < 2; nig++) {
                unsigned r[4];
                ldsm4(r, kbuf + (uint32_t)((nig * 16 + brow_lm) * ASTR + ks * 16 + bcol_lm) * 2);
                kb[nig * 2][0] = r[0]; kb[nig * 2][1] = r[1];
                kb[nig * 2 + 1][0] = r[2]; kb[nig * 2 + 1][1] = r[3];
            }
#pragma unroll
            for (int mi = 0; mi < 2; mi++)
#pragma unroll
                for (int ni = 0; ni < 4; ni++)
                    mma_f16(sacc[mi][ni], qf[mi][ks], kb[ni]);
        }

        // ---- exp (f16x2); result IS the PV A-frag ----
        unsigned p01[2][4], p23[2][4];
#pragma unroll
        for (int mi = 0; mi < 2; mi++)
#pragma unroll
            for (int ni = 0; ni < 4; ni++) {
                p01[mi][ni] = ex2h2(packh2(sacc[mi][ni][0], sacc[mi][ni][1]));
                p23[mi][ni] = ex2h2(packh2(sacc[mi][ni][2], sacc[mi][ni][3]));
            }

        // ---- PV (ldmatrix.trans B-frags from [s][d] V tile) + l-ones-mma ----
#pragma unroll
        for (int ks = 0; ks < 2; ks++) {
            unsigned vb[4][2];
#pragma unroll
            for (int ng = 0; ng < 2; ng++) {
                unsigned r[4];
                ldsm4t(r, vbuf + (uint32_t)((ks * 16 + trow_lm) * ASTR + ng * 16 + tcol_lm) * 2);
                vb[ng * 2][0] = r[0]; vb[ng * 2][1] = r[1];
                vb[ng * 2 + 1][0] = r[2]; vb[ng * 2 + 1][1] = r[3];
            }
#pragma unroll
            for (int mi = 0; mi < 2; mi++) {
                unsigned pa_[4];
                pa_[0] = p01[mi][2 * ks];
                pa_[1] = p23[mi][2 * ks];
                pa_[2] = p01[mi][2 * ks + 1];
                pa_[3] = p23[mi][2 * ks + 1];
#pragma unroll
                for (int nd = 0; nd < 4; nd++)
                    mma_f16(oacc[mi][nd], pa_, vb[nd]);
                mma_f16(lacc[mi], pa_, ONES2);
            }
        }
    }
#undef ASTAGE

    // finalize
#pragma unroll
    for (int r = 0; r < 4; r++) {
        int mi = r >> 1, cb = (r & 1) * 2;
        float inv = 1.f / lacc[mi][cb];
        int row = qbase + (r >> 1) * 16 + (r & 1) * 8 + g;
        __half* op = g_attn + ((size_t)b * S_ + row) * H_ + h * HD;
#pragma unroll
        for (int nd = 0; nd < 4; nd++) {
            *(__half2*)(op + nd * 8 + 2 * t) = __floats2half2_rn(
                oacc[mi][nd][cb] * inv, oacc[mi][nd][cb + 1] * inv);
        }
    }
}

// ---------------- launch ----------------
extern "C" void kernel_launch(void* const* d_in, const int* in_sizes, int n_in,
                              void* d_out, int out_size)
{
    const float* inputs = (const float*)d_in[0];
    const float* rmask  = (const float*)d_in[1];
    const float* w_in   = (const float*)d_in[2];
    const float* w_out  = (const float*)d_in[3];
    const float* gamma  = (const float*)d_in[4];
    const float* beta   = (const float*)d_in[5];
    float* out = (float*)d_out;

    const int gemm_smem = 6 * TILEH * (int)sizeof(__half);   // 110592 B (3-stage, 2 CTAs/SM)
    cudaFuncSetAttribute(gemm_f16<1>, cudaFuncAttributeMaxDynamicSharedMemorySize, gemm_smem);
    cudaFuncSetAttribute(gemm_f16<2>, cudaFuncAttributeMaxDynamicSharedMemorySize, gemm_smem);

    ln_conv_kernel<<<M_ / 8, 256>>>(inputs, gamma, beta, rmask, w_in, w_out);
    gemm_f16<1><<<dim3(6, M_ / 128), 256, gemm_smem>>>(nullptr, nullptr);
    attn_f16_kernel<<<512, 256>>>();
    gemm_f16<2><<<dim3(2, M_ / 128), 256, gemm_smem>>>(inputs, out);
}

// round 13
// speedup vs baseline: 7.8448x; 1.0004x over previous
#include <cuda_runtime.h>
#include <cuda_fp16.h>
#include <math.h>
#include <stdint.h>

// Problem dims (fixed)
#define B_   32
#define S_   512
#define H_   256
#define NH   8
#define HD   32
#define M_   (B_ * S_)     // 16384
#define TOT  (M_ * H_)

#define QK_SCALE_L2E 0.25505654440f     // (1/sqrt(32)) * log2(e)
#define RSQRT2       0.70710678118654752f
#define LN_EPS       1e-5f

// ---------------- scratch ----------------
__device__ __half g_normed[TOT];
__device__ __half g_wih[768 * 256];
__device__ __half g_woh[256 * 256];
__device__ __half g_Q[TOT];     // [b,h,s,d], (q*q+1e-6)*scale*log2e  (>= 0)
__device__ __half g_K[TOT];     // [b,h,s,d], + log(radial_mask)
__device__ __half g_V[TOT];     // [b,h,s,d]
__device__ __half g_attn[TOT];  // [b,s,H]
__device__ float    g_lr[M_];
__device__ unsigned g_maxkd[B_ * NH * HD];   // order-preserving float keys

// ---------------- helpers ----------------
__device__ __forceinline__ void mma_f16(float* d, const unsigned* a, const unsigned* b) {
    asm("mma.sync.aligned.m16n8k16.row.col.f32.f16.f16.f32 "
        "{%0,%1,%2,%3},{%4,%5,%6,%7},{%8,%9},{%0,%1,%2,%3};"
        : "+f"(d[0]), "+f"(d[1]), "+f"(d[2]), "+f"(d[3])
        : "r"(a[0]), "r"(a[1]), "r"(a[2]), "r"(a[3]), "r"(b[0]), "r"(b[1]));
}
__device__ __forceinline__ void ldsm4(unsigned* r, uint32_t addr) {
    asm volatile("ldmatrix.sync.aligned.m8n8.x4.shared.b16 {%0,%1,%2,%3}, [%4];"
        : "=r"(r[0]), "=r"(r[1]), "=r"(r[2]), "=r"(r[3]) : "r"(addr));
}
__device__ __forceinline__ void ldsm4t(unsigned* r, uint32_t addr) {
    asm volatile("ldmatrix.sync.aligned.m8n8.x4.trans.shared.b16 {%0,%1,%2,%3}, [%4];"
        : "=r"(r[0]), "=r"(r[1]), "=r"(r[2]), "=r"(r[3]) : "r"(addr));
}
__device__ __forceinline__ unsigned packh2(float lo, float hi) {
    __half2 h = __floats2half2_rn(lo, hi);
    return *(unsigned*)&h;
}
__device__ __forceinline__ unsigned ex2h2(unsigned x) {
    unsigned y;
    asm("ex2.approx.f16x2 %0, %1;" : "=r"(y) : "r"(x));
    return y;
}
__device__ __forceinline__ unsigned ldu32(const __half* p) {
    return *(const unsigned*)p;
}
__device__ __forceinline__ void cp16s(uint32_t saddr, const void* gptr) {
    asm volatile("cp.async.cg.shared.global [%0], [%1], 16;" :: "r"(saddr), "l"(gptr));
}
#define CP_COMMIT() asm volatile("cp.async.commit_group;")
#define CP_WAIT1()  asm volatile("cp.async.wait_group 1;")
#define CP_WAIT2()  asm volatile("cp.async.wait_group 2;")

// order-preserving float<->uint key
__device__ __forceinline__ unsigned fkey(float f) {
    unsigned b = __float_as_uint(f);
    return (b & 0x80000000u) ? ~b : (b | 0x80000000u);
}
__device__ __forceinline__ float funkey(unsigned k) {
    unsigned b = (k & 0x80000000u) ? (k & 0x7fffffffu) : ~k;
    return __uint_as_float(b);
}

// ---------------- LayerNorm + fused weight conversion + maxk init ----------------
__global__ __launch_bounds__(256) void ln_conv_kernel(
    const float* __restrict__ x, const float* __restrict__ gamma,
    const float* __restrict__ beta, const float* __restrict__ rmask,
    const float* __restrict__ wi, const float* __restrict__ wo)
{
    int warp = threadIdx.x >> 5, lane = threadIdx.x & 31;
    int row  = blockIdx.x * 8 + warp;

    int gi = blockIdx.x * 256 + threadIdx.x;
    const int N1 = 768 * 256 / 2;
    const int N2 = 256 * 256 / 2;
    if (gi < B_ * NH * HD) g_maxkd[gi] = 0u;
    if (gi < N1) {
        float2 v = ((const float2*)wi)[gi];
        ((__half2*)g_wih)[gi] = __floats2half2_rn(v.x, v.y);
    } else if (gi < N1 + N2) {
        int j = gi - N1;
        float2 v = ((const float2*)wo)[j];
        ((__half2*)g_woh)[j] = __floats2half2_rn(v.x, v.y);
    }

    const float2* xr = (const float2*)(x + row * H_);
    const float2* g2 = (const float2*)gamma;
    const float2* b2 = (const float2*)beta;

    float2 v[4];
    float sum = 0.f, sq = 0.f;
#pragma unroll
    for (int k = 0; k < 4; k++) {
        float2 t = xr[lane + 32 * k];
        v[k] = t;
        sum += t.x + t.y;
        sq  += t.x * t.x + t.y * t.y;
    }
#pragma unroll
    for (int o = 16; o > 0; o >>= 1) {
        sum += __shfl_xor_sync(0xffffffffu, sum, o);
        sq  += __shfl_xor_sync(0xffffffffu, sq,  o);
    }
    float mu = sum * (1.f / H_);
    float var = sq * (1.f / H_) - mu * mu;
    float rstd = rsqrtf(var + LN_EPS);

    __half2* nr = (__half2*)(g_normed + row * H_);
#pragma unroll
    for (int k = 0; k < 4; k++) {
        int idx = lane + 32 * k;
        float2 gv = g2[idx], bv = b2[idx];
        nr[idx] = __floats2half2_rn(
            (v[k].x - mu) * rstd * gv.x + bv.x,
            (v[k].y - mu) * rstd * gv.y + bv.y);
    }
    if (lane == 0) g_lr[row] = logf(rmask[row]);
}

// ---------------- fp16 MMA GEMM (NT): TRUE 3-deep cp.async pipeline ----------------
// Prologue stages 3 of 4 k-tiles; loop waits group kt with wait_group 2 and commits
// a group every iteration (empty when nothing left) to keep counts aligned.
#define SSTRH 72
#define TILEH (128 * SSTRH)

template <int MODE>
__global__ __launch_bounds__(256, 2) void gemm_f16(
    const float* __restrict__ extra, float* __restrict__ C)
{
    extern __shared__ __half smh[];
    __half* As = smh;                 // [3][TILEH]
    __half* Bs = smh + 3 * TILEH;     // [3][TILEH]

    const __half* A    = (MODE == 1) ? g_normed : g_attn;
    const __half* Bmat = (MODE == 1) ? g_wih : g_woh;
    const int K = 256;

    int tid = threadIdx.x;
    int wid = tid >> 5, lane = tid & 31;
    int g = lane >> 2, t = lane & 3;
    int wm = wid >> 2, wn = wid & 3;
    int brow = blockIdx.y, bcol = blockIdx.x;

    int c8  = tid & 7;
    int rwg = tid >> 3;

    int arow_lm = (lane & 7) + ((lane >> 3) & 1) * 8;
    int acol_lm = (lane >> 4) * 8;
    int brow_lm = (lane & 7) + (lane >> 4) * 8;
    int bcol_lm = ((lane >> 3) & 1) * 8;

    const __half* Agb = A    + (size_t)(brow * 128) * K;
    const __half* Bgb = Bmat + (size_t)(bcol * 128) * K;
    uint32_t asBase = (uint32_t)__cvta_generic_to_shared(As);
    uint32_t bsBase = (uint32_t)__cvta_generic_to_shared(Bs);

    float dacc[4][4][4];
#pragma unroll
    for (int i = 0; i < 4; i++)
#pragma unroll
        for (int j = 0; j < 4; j++)
#pragma unroll
            for (int c = 0; c < 4; c++) dacc[i][j][c] = 0.f;

#define STAGE(kt_, buf_) do { \
    int _kb = (kt_) * 64; \
    uint32_t _ab = asBase + (uint32_t)(buf_) * (TILEH * 2); \
    uint32_t _bb = bsBase + (uint32_t)(buf_) * (TILEH * 2); \
    _Pragma("unroll") \
    for (int _i = 0; _i < 4; _i++) { \
        int _row = rwg + _i * 32; \
        uint32_t _off = (uint32_t)_row * (SSTRH * 2) + (uint32_t)c8 * 16; \
        cp16s(_ab + _off, Agb + (size_t)_row * K + _kb + c8 * 8); \
        cp16s(_bb + _off, Bgb + (size_t)_row * K + _kb + c8 * 8); \
    } \
} while (0)

    STAGE(0, 0); CP_COMMIT();
    STAGE(1, 1); CP_COMMIT();
    STAGE(2, 2); CP_COMMIT();

#pragma unroll
    for (int kt = 0; kt < 4; kt++) {
        // 3 groups outstanding here -> wait_group 2 retires exactly group kt
        CP_WAIT2();
        __syncthreads();
        // buffer (kt+3)%3 == kt%3... careful: prefetch target is (kt+3)%3 which
        // equals kt%3 — the buffer we are ABOUT to read. So prefetch AFTER compute
        // would hazard; instead prefetch tile kt+3 into buffer (kt+3)%3 only after
        // reading: but reading happens now. Resolve: with 4 tiles and 3 buffers the
        // single in-loop prefetch (kt==0 -> tile 3 -> buffer 0) would clobber buf0
        // being read at kt=0. Use the spare: stage tile 3 at kt==1 into buffer 0
        // (buf0's reads finished at kt=0, behind this barrier).
        if (kt == 1) STAGE(3, 0);
        CP_COMMIT();   // every iteration (empty when no prefetch) keeps counts aligned

        uint32_t abuf = asBase + (uint32_t)(kt % 3) * (TILEH * 2);
        uint32_t bbuf = bsBase + (uint32_t)(kt % 3) * (TILEH * 2);
#pragma unroll
        for (int ks = 0; ks < 4; ks++) {
            unsigned af[4][4], bf[4][2];
#pragma unroll
            for (int mi = 0; mi < 4; mi++)
                ldsm4(af[mi], abuf + (uint32_t)((wm * 64 + mi * 16 + arow_lm) * SSTRH
                                               + ks * 16 + acol_lm) * 2);
#pragma unroll
            for (int nig = 0; nig < 2; nig++) {
                unsigned r[4];
                ldsm4(r, bbuf + (uint32_t)((wn * 32 + nig * 16 + brow_lm) * SSTRH
                                           + ks * 16 + bcol_lm) * 2);
                bf[nig * 2][0] = r[0]; bf[nig * 2][1] = r[1];
                bf[nig * 2 + 1][0] = r[2]; bf[nig * 2 + 1][1] = r[3];
            }
#pragma unroll
            for (int mi = 0; mi < 4; mi++)
#pragma unroll
                for (int ni = 0; ni < 4; ni++)
                    mma_f16(dacc[mi][ni], af[mi], bf[ni]);
        }
    }
#undef STAGE

    if (MODE == 1) {
        int region = (bcol * 128) >> 8;   // 0=q 1=k 2=v (uniform per CTA)
        int hh = ((bcol & 1) << 2) + wn;
        float cmax[4][2];
#pragma unroll
        for (int ni = 0; ni < 4; ni++) { cmax[ni][0] = -1e30f; cmax[ni][1] = -1e30f; }

#pragma unroll
        for (int mi = 0; mi < 4; mi++) {
            int r0 = brow * 128 + wm * 64 + mi * 16 + g;
            int r1 = r0 + 8;
            int b = r0 >> 9, s0 = r0 & 511, s1 = r1 & 511;
            __half* dst = (region == 0) ? g_Q : (region == 1) ? g_K : g_V;
            float lr0 = (region == 1) ? g_lr[r0] : 0.f;
            float lr1 = (region == 1) ? g_lr[r1] : 0.f;
            __half* p0 = dst + ((size_t)(b * 8 + hh) * S_ + s0) * HD;
            __half* p1 = dst + ((size_t)(b * 8 + hh) * S_ + s1) * HD;
#pragma unroll
            for (int ni = 0; ni < 4; ni++) {
                int dcol = ni * 8 + 2 * t;
                float v0 = dacc[mi][ni][0], v1 = dacc[mi][ni][1];
                float v2 = dacc[mi][ni][2], v3 = dacc[mi][ni][3];
                if (region == 0) {
                    v0 = (v0 * v0 + 1e-6f) * QK_SCALE_L2E;
                    v1 = (v1 * v1 + 1e-6f) * QK_SCALE_L2E;
                    v2 = (v2 * v2 + 1e-6f) * QK_SCALE_L2E;
                    v3 = (v3 * v3 + 1e-6f) * QK_SCALE_L2E;
                } else if (region == 1) {
                    v0 += lr0; v1 += lr0; v2 += lr1; v3 += lr1;
                    cmax[ni][0] = fmaxf(cmax[ni][0], fmaxf(v0, v2));
                    cmax[ni][1] = fmaxf(cmax[ni][1], fmaxf(v1, v3));
                }
                *(__half2*)(p0 + dcol) = __floats2half2_rn(v0, v1);
                *(__half2*)(p1 + dcol) = __floats2half2_rn(v2, v3);
            }
        }

        if (region == 1) {
#pragma unroll
            for (int ni = 0; ni < 4; ni++) {
#pragma unroll
                for (int o = 4; o <= 16; o <<= 1) {
                    cmax[ni][0] = fmaxf(cmax[ni][0], __shfl_xor_sync(0xffffffffu, cmax[ni][0], o));
                    cmax[ni][1] = fmaxf(cmax[ni][1], __shfl_xor_sync(0xffffffffu, cmax[ni][1], o));
                }
            }
            if (g == 0) {
                int b = brow >> 2;
                unsigned* mk = g_maxkd + (size_t)(b * 8 + hh) * HD;
#pragma unroll
                for (int ni = 0; ni < 4; ni++) {
                    atomicMax(&mk[ni * 8 + 2 * t],     fkey(cmax[ni][0]));
                    atomicMax(&mk[ni * 8 + 2 * t + 1], fkey(cmax[ni][1]));
                }
            }
        }
    } else {
#pragma unroll
        for (int mi = 0; mi < 4; mi++) {
            int r0 = brow * 128 + wm * 64 + mi * 16 + g;
            int r1 = r0 + 8;
            int cbase = bcol * 128 + wn * 32;
            const float* in0 = extra + (size_t)r0 * H_ + cbase;
            const float* in1 = extra + (size_t)r1 * H_ + cbase;
            float* o0 = C + (size_t)r0 * H_ + cbase;
            float* o1 = C + (size_t)r1 * H_ + cbase;
#pragma unroll
            for (int ni = 0; ni < 4; ni++) {
                int dcol = ni * 8 + 2 * t;
                float2 i0 = *(const float2*)(in0 + dcol);
                float2 i1 = *(const float2*)(in1 + dcol);
                *(float2*)(o0 + dcol) = make_float2(
                    (dacc[mi][ni][0] + i0.x) * RSQRT2, (dacc[mi][ni][1] + i0.y) * RSQRT2);
                *(float2*)(o1 + dcol) = make_float2(
                    (dacc[mi][ni][2] + i1.x) * RSQRT2, (dacc[mi][ni][3] + i1.y) * RSQRT2);
            }
        }
    }
}

// ---------------- attention: fp16 mma, static bound, 4-stage cp.async,
// ---------------- V natural layout + ldmatrix.trans PV B-frags ----------------
#define ASTR 40

__global__ __launch_bounds__(256) void attn_f16_kernel()
{
    __shared__ __half Ks[4][32 * ASTR];
    __shared__ __half Vs[4][32 * ASTR];

    int tid = threadIdx.x;
    int wid = tid >> 5, lane = tid & 31;
    int g = lane >> 2, t = lane & 3;
    int qhalf = blockIdx.x & 1, bh = blockIdx.x >> 1;
    int b = bh >> 3, h = bh & 7;
    int qbase = qhalf * 256 + wid * 32;

    int brow_lm = (lane & 7) + (lane >> 4) * 8;      // K (non-trans)
    int bcol_lm = ((lane >> 3) & 1) * 8;
    int trow_lm = lane & 15;                         // V (trans): k row
    int tcol_lm = (lane >> 4) * 8;                   // +8 n col

    // Q fragments resident
    const __half* Qg = g_Q + ((size_t)bh * S_ + qbase) * HD;
    unsigned qf[2][2][4];
#pragma unroll
    for (int mi = 0; mi < 2; mi++) {
        int r = mi * 16 + g;
#pragma unroll
        for (int ks = 0; ks < 2; ks++) {
            qf[mi][ks][0] = ldu32(&Qg[r * HD + ks * 16 + 2 * t]);
            qf[mi][ks][1] = ldu32(&Qg[(r + 8) * HD + ks * 16 + 2 * t]);
            qf[mi][ks][2] = ldu32(&Qg[r * HD + ks * 16 + 2 * t + 8]);
            qf[mi][ks][3] = ldu32(&Qg[(r + 8) * HD + ks * 16 + 2 * t + 8]);
        }
    }

    // static row-max bound
    float mrow[4];
    {
        const unsigned* mku = g_maxkd + bh * HD;
        float m0[2] = {0.f, 0.f}, m1[2] = {0.f, 0.f};
#pragma unroll
        for (int ks = 0; ks < 2; ks++) {
            float mkA0 = funkey(mku[ks * 16 + 2 * t]);
            float mkA1 = funkey(mku[ks * 16 + 2 * t + 1]);
            float mkB0 = funkey(mku[ks * 16 + 2 * t + 8]);
            float mkB1 = funkey(mku[ks * 16 + 2 * t + 9]);
#pragma unroll
            for (int mi = 0; mi < 2; mi++) {
                float2 qa = __half22float2(*(__half2*)&qf[mi][ks][0]);
                float2 qb = __half22float2(*(__half2*)&qf[mi][ks][2]);
                float2 qc = __half22float2(*(__half2*)&qf[mi][ks][1]);
                float2 qd = __half22float2(*(__half2*)&qf[mi][ks][3]);
                m0[mi] += qa.x * mkA0 + qa.y * mkA1 + qb.x * mkB0 + qb.y * mkB1;
                m1[mi] += qc.x * mkA0 + qc.y * mkA1 + qd.x * mkB0 + qd.y * mkB1;
            }
        }
#pragma unroll
        for (int o = 1; o <= 2; o <<= 1) {
#pragma unroll
            for (int mi = 0; mi < 2; mi++) {
                m0[mi] += __shfl_xor_sync(0xffffffffu, m0[mi], o);
                m1[mi] += __shfl_xor_sync(0xffffffffu, m1[mi], o);
            }
        }
        mrow[0] = m0[0]; mrow[1] = m1[0]; mrow[2] = m0[1]; mrow[3] = m1[1];
    }

    float oacc[2][4][4];
#pragma unroll
    for (int mi = 0; mi < 2; mi++)
#pragma unroll
        for (int nd = 0; nd < 4; nd++)
#pragma unroll
            for (int c = 0; c < 4; c++) oacc[mi][nd][c] = 0.f;
    float lacc[2][4];
#pragma unroll
    for (int mi = 0; mi < 2; mi++)
#pragma unroll
        for (int c = 0; c < 4; c++) lacc[mi][c] = 0.f;

    const unsigned ONES2[2] = {0x3C003C00u, 0x3C003C00u};

    int mat = tid >> 7;           // 0 = K, 1 = V
    int lrw = (tid >> 2) & 31;
    int c4  = tid & 3;
    const __half* Kg = g_K + (size_t)bh * S_ * HD;
    const __half* Vg = g_V + (size_t)bh * S_ * HD;
    const __half* src = (mat == 0) ? Kg : Vg;
    uint32_t ksb = (uint32_t)__cvta_generic_to_shared(&Ks[0][0]);
    uint32_t vsb = (uint32_t)__cvta_generic_to_shared(&Vs[0][0]);
    uint32_t dstb = (mat == 0) ? ksb : vsb;

#define ASTAGE(kt_) do { \
    uint32_t _soff = (uint32_t)((kt_) & 3) * (32 * ASTR * 2) + (uint32_t)lrw * (ASTR * 2) + (uint32_t)c4 * 16; \
    cp16s(dstb + _soff, src + (size_t)((kt_) * 32 + lrw) * HD + c4 * 8); \
} while (0)

    ASTAGE(0); CP_COMMIT();
    ASTAGE(1); CP_COMMIT();
    ASTAGE(2); CP_COMMIT();

#pragma unroll 4
    for (int kt = 0; kt < 16; kt++) {
        CP_WAIT2();
        __syncthreads();
        if (kt + 3 < 16) ASTAGE(kt + 3);
        CP_COMMIT();

        uint32_t kbuf = ksb + (uint32_t)(kt & 3) * (32 * ASTR * 2);
        uint32_t vbuf = vsb + (uint32_t)(kt & 3) * (32 * ASTR * 2);

        // ---- QK^T with -m folded into accumulator init ----
        float sacc[2][4][4];
#pragma unroll
        for (int mi = 0; mi < 2; mi++)
#pragma unroll
            for (int ni = 0; ni < 4; ni++) {
                sacc[mi][ni][0] = -mrow[2 * mi];
                sacc[mi][ni][1] = -mrow[2 * mi];
                sacc[mi][ni][2] = -mrow[2 * mi + 1];
                sacc[mi][ni][3] = -mrow[2 * mi + 1];
            }

#pragma unroll
        for (int ks = 0; ks < 2; ks++) {
            unsigned kb[4][2];
#pragma unroll
            for (int nig = 0; nig < 2; nig++) {
                unsigned r[4];
                ldsm4(r, kbuf + (uint32_t)((nig * 16 + brow_lm) * ASTR + ks * 16 + bcol_lm) * 2);
                kb[nig * 2][0] = r[0]; kb[nig * 2][1] = r[1];
                kb[nig * 2 + 1][0] = r[2]; kb[nig * 2 + 1][1] = r[3];
            }
#pragma unroll
            for (int mi = 0; mi < 2; mi++)
#pragma unroll
                for (int ni = 0; ni < 4; ni++)
                    mma_f16(sacc[mi][ni], qf[mi][ks], kb[ni]);
        }

        // ---- exp (f16x2); result IS the PV A-frag ----
        unsigned p01[2][4], p23[2][4];
#pragma unroll
        for (int mi = 0; mi < 2; mi++)
#pragma unroll
            for (int ni = 0; ni < 4; ni++) {
                p01[mi][ni] = ex2h2(packh2(sacc[mi][ni][0], sacc[mi][ni][1]));
                p23[mi][ni] = ex2h2(packh2(sacc[mi][ni][2], sacc[mi][ni][3]));
            }

        // ---- PV (ldmatrix.trans B-frags from [s][d] V tile) + l-ones-mma ----
#pragma unroll
        for (int ks = 0; ks < 2; ks++) {
            unsigned vb[4][2];
#pragma unroll
            for (int ng = 0; ng < 2; ng++) {
                unsigned r[4];
                ldsm4t(r, vbuf + (uint32_t)((ks * 16 + trow_lm) * ASTR + ng * 16 + tcol_lm) * 2);
                vb[ng * 2][0] = r[0]; vb[ng * 2][1] = r[1];
                vb[ng * 2 + 1][0] = r[2]; vb[ng * 2 + 1][1] = r[3];
            }
#pragma unroll
            for (int mi = 0; mi < 2; mi++) {
                unsigned pa_[4];
                pa_[0] = p01[mi][2 * ks];
                pa_[1] = p23[mi][2 * ks];
                pa_[2] = p01[mi][2 * ks + 1];
                pa_[3] = p23[mi][2 * ks + 1];
#pragma unroll
                for (int nd = 0; nd < 4; nd++)
                    mma_f16(oacc[mi][nd], pa_, vb[nd]);
                mma_f16(lacc[mi], pa_, ONES2);
            }
        }
    }
#undef ASTAGE

    // finalize
#pragma unroll
    for (int r = 0; r < 4; r++) {
        int mi = r >> 1, cb = (r & 1) * 2;
        float inv = 1.f / lacc[mi][cb];
        int row = qbase + (r >> 1) * 16 + (r & 1) * 8 + g;
        __half* op = g_attn + ((size_t)b * S_ + row) * H_ + h * HD;
#pragma unroll
        for (int nd = 0; nd < 4; nd++) {
            *(__half2*)(op + nd * 8 + 2 * t) = __floats2half2_rn(
                oacc[mi][nd][cb] * inv, oacc[mi][nd][cb + 1] * inv);
        }
    }
}

// ---------------- launch ----------------
extern "C" void kernel_launch(void* const* d_in, const int* in_sizes, int n_in,
                              void* d_out, int out_size)
{
    const float* inputs = (const float*)d_in[0];
    const float* rmask  = (const float*)d_in[1];
    const float* w_in   = (const float*)d_in[2];
    const float* w_out  = (const float*)d_in[3];
    const float* gamma  = (const float*)d_in[4];
    const float* beta   = (const float*)d_in[5];
    float* out = (float*)d_out;

    const int gemm_smem = 6 * TILEH * (int)sizeof(__half);   // 110592 B (3-stage, 2 CTAs/SM)
    cudaFuncSetAttribute(gemm_f16<1>, cudaFuncAttributeMaxDynamicSharedMemorySize, gemm_smem);
    cudaFuncSetAttribute(gemm_f16<2>, cudaFuncAttributeMaxDynamicSharedMemorySize, gemm_smem);

    ln_conv_kernel<<<M_ / 8, 256>>>(inputs, gamma, beta, rmask, w_in, w_out);
    gemm_f16<1><<<dim3(6, M_ / 128), 256, gemm_smem>>>(nullptr, nullptr);
    attn_f16_kernel<<<512, 256>>>();
    gemm_f16<2><<<dim3(2, M_ / 128), 256, gemm_smem>>>(inputs, out);
}